// round 1
// baseline (speedup 1.0000x reference)
#include <cuda_runtime.h>
#include <math.h>

#define B 4
#define S 2048
#define D 2048
#define H 16
#define G 4
#define HD 128

// ------------------------- scratch (device globals, no allocs) --------------
__device__ float g_q[(size_t)B * S * H * HD];     // 64 MB
__device__ float g_k[(size_t)B * S * G * HD];     // 16 MB
__device__ float g_v[(size_t)B * S * G * HD];     // 16 MB
__device__ float g_attn[(size_t)B * S * H * HD];  // 64 MB

// ============================ GEMM + bias ====================================
// C[M,N] = A[M,K] @ W[K,N] + bias[N], all row-major. M,N,K multiples of tile.
#define GBM 64
#define GBN 64
#define GBK 16

__global__ void gemm_bias_kernel(const float* __restrict__ A,
                                 const float* __restrict__ W,
                                 const float* __restrict__ bias,
                                 float* __restrict__ C,
                                 int M, int N, int K) {
    __shared__ float As[GBK][GBM + 4];   // transposed A tile
    __shared__ float Ws[GBK][GBN];

    const int tid = threadIdx.x;         // 256 threads
    const int tx = tid & 15;
    const int ty = tid >> 4;
    const int row0 = blockIdx.y * GBM;
    const int col0 = blockIdx.x * GBN;

    // A-load mapping: one float4 per thread covers 64 rows x 16 k
    const int a_r  = tid >> 2;           // 0..63
    const int a_c4 = (tid & 3) * 4;      // 0,4,8,12
    // W-load mapping: one float4 per thread covers 16 k x 64 n
    const int w_k  = tid >> 4;           // 0..15
    const int w_c4 = (tid & 15) * 4;     // 0..60

    float acc[4][4] = {};

    for (int k0 = 0; k0 < K; k0 += GBK) {
        float4 av = *(const float4*)&A[(size_t)(row0 + a_r) * K + k0 + a_c4];
        As[a_c4 + 0][a_r] = av.x;
        As[a_c4 + 1][a_r] = av.y;
        As[a_c4 + 2][a_r] = av.z;
        As[a_c4 + 3][a_r] = av.w;
        *(float4*)&Ws[w_k][w_c4] =
            *(const float4*)&W[(size_t)(k0 + w_k) * N + col0 + w_c4];
        __syncthreads();

        #pragma unroll
        for (int kk = 0; kk < GBK; kk++) {
            float4 a4 = *(const float4*)&As[kk][ty * 4];
            float4 b4 = *(const float4*)&Ws[kk][tx * 4];
            float a[4] = {a4.x, a4.y, a4.z, a4.w};
            float b[4] = {b4.x, b4.y, b4.z, b4.w};
            #pragma unroll
            for (int r = 0; r < 4; r++)
                #pragma unroll
                for (int c = 0; c < 4; c++)
                    acc[r][c] += a[r] * b[c];
        }
        __syncthreads();
    }

    float4 bb = *(const float4*)&bias[col0 + tx * 4];
    float bv[4] = {bb.x, bb.y, bb.z, bb.w};
    #pragma unroll
    for (int r = 0; r < 4; r++) {
        int row = row0 + ty * 4 + r;
        float4 o4 = make_float4(acc[r][0] + bv[0], acc[r][1] + bv[1],
                                acc[r][2] + bv[2], acc[r][3] + bv[3]);
        *(float4*)&C[(size_t)row * N + col0 + tx * 4] = o4;
    }
}

// ================================ RoPE =======================================
__global__ void rope_kernel() {
    int idx = blockIdx.x * blockDim.x + threadIdx.x;
    const int QTOT = B * S * H * (HD / 2);
    const int KTOT = B * S * G * (HD / 2);
    if (idx >= QTOT + KTOT) return;

    float* base;
    int i, s;
    if (idx < QTOT) {
        i = idx & 63;
        int h = (idx >> 6) % H;
        s = (idx / (64 * H)) % S;
        int b = idx / (64 * H * S);
        base = &g_q[(((size_t)(b * S + s)) * H + h) * HD];
    } else {
        int j = idx - QTOT;
        i = j & 63;
        int g = (j >> 6) % G;
        s = (j / (64 * G)) % S;
        int b = j / (64 * G * S);
        base = &g_k[(((size_t)(b * S + s)) * G + g) * HD];
    }
    float inv_freq = powf(10000.0f, -((float)(2 * i) / (float)HD));
    float ang = (float)s * inv_freq;
    float c = cosf(ang);
    float sn = sinf(ang);
    float t1 = base[i];
    float t2 = base[i + 64];
    base[i]      = t1 * c - t2 * sn;
    base[i + 64] = t2 * c + t1 * sn;
}

// ========================= Flash attention (causal, GQA) =====================
// Tile: 64 q-rows x 64 k-cols x HD=128. 256 threads (16x16).
// Per thread: S-tile 4x4, O-tile 4 rows x 8 cols.
#define FAM 64
#define FAN 64
#define QK_LD 68     // padded smem stride for transposed q/k tiles
#define V_LD 132     // padded smem stride for v tile
#define S_LD 65      // padded smem stride for score tile

__global__ void flash_kernel() {
    extern __shared__ float sm[];
    float* qts   = sm;                    // [HD][QK_LD]
    float* kts   = qts + HD * QK_LD;      // [HD][QK_LD]
    float* vsm   = kts + HD * QK_LD;      // [FAN][V_LD]
    float* ssm   = vsm + FAN * V_LD;      // [FAM][S_LD]
    float* row_m = ssm + FAM * S_LD;      // [64]
    float* row_l = row_m + 64;            // [64]
    float* row_s = row_l + 64;            // [64]

    const int tid = threadIdx.x;
    const int tx = tid & 15;
    const int ty = tid >> 4;
    const int qt = blockIdx.x;
    const int h  = blockIdx.y;
    const int b  = blockIdx.z;
    const int g  = h / (H / G);
    const int q0 = qt * FAM;
    const float scale = 0.08838834764831845f;  // 1/sqrt(128)

    // Load q tile transposed (scaled): 2048 float4s over 256 threads
    #pragma unroll
    for (int it = 0; it < 8; it++) {
        int i4 = tid + it * 256;
        int r  = i4 >> 5;             // 0..63
        int d4 = (i4 & 31) * 4;       // 0..124
        float4 qv = *(const float4*)&g_q[(((size_t)(b * S + q0 + r)) * H + h) * HD + d4];
        qts[(d4 + 0) * QK_LD + r] = qv.x * scale;
        qts[(d4 + 1) * QK_LD + r] = qv.y * scale;
        qts[(d4 + 2) * QK_LD + r] = qv.z * scale;
        qts[(d4 + 3) * QK_LD + r] = qv.w * scale;
    }
    if (tid < 64) {
        row_m[tid] = -1e30f;
        row_l[tid] = 0.0f;
    }

    float o[4][8];
    #pragma unroll
    for (int r = 0; r < 4; r++)
        #pragma unroll
        for (int c = 0; c < 8; c++) o[r][c] = 0.0f;

    for (int kt = 0; kt <= qt; kt++) {
        const int k0 = kt * FAN;
        __syncthreads();   // previous iteration done reading smem
        #pragma unroll
        for (int it = 0; it < 8; it++) {
            int i4 = tid + it * 256;
            int r  = i4 >> 5;
            int d4 = (i4 & 31) * 4;
            size_t gi = (((size_t)(b * S + k0 + r)) * G + g) * HD + d4;
            float4 kv = *(const float4*)&g_k[gi];
            kts[(d4 + 0) * QK_LD + r] = kv.x;
            kts[(d4 + 1) * QK_LD + r] = kv.y;
            kts[(d4 + 2) * QK_LD + r] = kv.z;
            kts[(d4 + 3) * QK_LD + r] = kv.w;
            float4 vv = *(const float4*)&g_v[gi];
            *(float4*)&vsm[r * V_LD + d4] = vv;
        }
        __syncthreads();

        // S = q @ k^T   (4x4 per thread)
        float sacc[4][4] = {};
        #pragma unroll 4
        for (int d = 0; d < HD; d++) {
            float4 a4 = *(const float4*)&qts[d * QK_LD + ty * 4];
            float4 k4 = *(const float4*)&kts[d * QK_LD + tx * 4];
            float a[4] = {a4.x, a4.y, a4.z, a4.w};
            float kvv[4] = {k4.x, k4.y, k4.z, k4.w};
            #pragma unroll
            for (int r = 0; r < 4; r++)
                #pragma unroll
                for (int c = 0; c < 4; c++)
                    sacc[r][c] += a[r] * kvv[c];
        }
        const bool diag = (kt == qt);
        #pragma unroll
        for (int r = 0; r < 4; r++) {
            int qi = q0 + ty * 4 + r;
            #pragma unroll
            for (int c = 0; c < 4; c++) {
                int ki = k0 + tx * 4 + c;
                float sv = sacc[r][c];
                if (diag && ki > qi) sv = -1e30f;
                ssm[(ty * 4 + r) * S_LD + tx * 4 + c] = sv;
            }
        }
        __syncthreads();

        // online softmax update (one thread per row)
        if (tid < 64) {
            int row = tid;
            float mo = row_m[row];
            float mx = mo;
            #pragma unroll 8
            for (int j = 0; j < FAN; j++) mx = fmaxf(mx, ssm[row * S_LD + j]);
            float sc = expf(mo - mx);
            float lsum = 0.0f;
            #pragma unroll 4
            for (int j = 0; j < FAN; j++) {
                float p = expf(ssm[row * S_LD + j] - mx);
                ssm[row * S_LD + j] = p;
                lsum += p;
            }
            row_m[row] = mx;
            row_l[row] = row_l[row] * sc + lsum;
            row_s[row] = sc;
        }
        __syncthreads();

        // O = O*rescale + P @ V
        float rsc[4];
        #pragma unroll
        for (int r = 0; r < 4; r++) rsc[r] = row_s[ty * 4 + r];
        #pragma unroll
        for (int r = 0; r < 4; r++)
            #pragma unroll
            for (int c = 0; c < 8; c++) o[r][c] *= rsc[r];

        #pragma unroll 2
        for (int j = 0; j < FAN; j++) {
            float p[4];
            #pragma unroll
            for (int r = 0; r < 4; r++) p[r] = ssm[(ty * 4 + r) * S_LD + j];
            float4 v0 = *(const float4*)&vsm[j * V_LD + tx * 8];
            float4 v1 = *(const float4*)&vsm[j * V_LD + tx * 8 + 4];
            float vv[8] = {v0.x, v0.y, v0.z, v0.w, v1.x, v1.y, v1.z, v1.w};
            #pragma unroll
            for (int r = 0; r < 4; r++)
                #pragma unroll
                for (int c = 0; c < 8; c++)
                    o[r][c] += p[r] * vv[c];
        }
    }

    float linv[4];
    #pragma unroll
    for (int r = 0; r < 4; r++) linv[r] = 1.0f / row_l[ty * 4 + r];
    #pragma unroll
    for (int r = 0; r < 4; r++) {
        size_t orow = (((size_t)(b * S + q0 + ty * 4 + r)) * H + h) * HD;
        #pragma unroll
        for (int c = 0; c < 8; c++)
            g_attn[orow + tx * 8 + c] = o[r][c] * linv[r];
    }
}

// =============================== launch ======================================
extern "C" void kernel_launch(void* const* d_in, const int* in_sizes, int n_in,
                              void* d_out, int out_size) {
    const float* x  = (const float*)d_in[0];
    const float* Wq = (const float*)d_in[1];
    const float* bq = (const float*)d_in[2];
    const float* Wk = (const float*)d_in[3];
    const float* bk = (const float*)d_in[4];
    const float* Wv = (const float*)d_in[5];
    const float* bv = (const float*)d_in[6];
    const float* Wo = (const float*)d_in[7];
    const float* bo = (const float*)d_in[8];
    float* out = (float*)d_out;

    float *qp, *kp, *vp, *ap;
    cudaGetSymbolAddress((void**)&qp, g_q);
    cudaGetSymbolAddress((void**)&kp, g_k);
    cudaGetSymbolAddress((void**)&vp, g_v);
    cudaGetSymbolAddress((void**)&ap, g_attn);

    const int M = B * S;  // 8192
    dim3 thr(256);

    // QKV projections
    gemm_bias_kernel<<<dim3((H * HD) / GBN, M / GBM), thr>>>(x, Wq, bq, qp, M, H * HD, D);
    gemm_bias_kernel<<<dim3((G * HD) / GBN, M / GBM), thr>>>(x, Wk, bk, kp, M, G * HD, D);
    gemm_bias_kernel<<<dim3((G * HD) / GBN, M / GBM), thr>>>(x, Wv, bv, vp, M, G * HD, D);

    // RoPE on q and k
    int rope_total = B * S * (H + G) * (HD / 2);
    rope_kernel<<<(rope_total + 255) / 256, 256>>>();

    // Flash attention
    size_t smem = (size_t)(HD * QK_LD * 2 + FAN * V_LD + FAM * S_LD + 192) * sizeof(float);
    cudaFuncSetAttribute(flash_kernel, cudaFuncAttributeMaxDynamicSharedMemorySize, (int)smem);
    flash_kernel<<<dim3(S / FAM, H, B), 256, smem>>>();

    // Output projection
    gemm_bias_kernel<<<dim3(D / GBN, M / GBM), thr>>>(ap, Wo, bo, out, M, D, H * HD);
}

// round 2
// speedup vs baseline: 1.5490x; 1.5490x over previous
#include <cuda_runtime.h>
#include <cuda_bf16.h>
#include <math.h>

#define B 4
#define S 2048
#define D 2048
#define H 16
#define G 4
#define HD 128

// ------------------------- scratch (device globals, no allocs) --------------
__device__ float g_q[(size_t)B * S * H * HD];     // 64 MB
__device__ float g_k[(size_t)B * S * G * HD];     // 16 MB
__device__ float g_v[(size_t)B * S * G * HD];     // 16 MB
__device__ float g_attn[(size_t)B * S * H * HD];  // 64 MB

// ===================== Tensor-core GEMM + bias (3xBF16) ======================
// C[M,N] = A[M,K] @ W[K,N] + bias[N]. Split each fp32 into bf16 hi+lo and do
// Ahi*Bhi + Ahi*Blo + Alo*Bhi with fp32 accumulation (error ~1e-5 rel).
// CTA tile 128x128x32, 256 threads = 8 warps (2x4), warp tile 64x32.
// mma.sync.m16n8k16 bf16. A-frags via ldmatrix.x4, B-frags via ldmatrix.x4.trans.

#define LDA 40    // bf16 stride of A smem rows (conflict-free ldmatrix)
#define LDB 136   // bf16 stride of B smem rows (conflict-free ldmatrix.trans)

#define LDSM4(R, addr)                                                        \
    asm volatile("ldmatrix.sync.aligned.m8n8.x4.shared.b16 {%0,%1,%2,%3}, [%4];" \
                 : "=r"(R[0]), "=r"(R[1]), "=r"(R[2]), "=r"(R[3]) : "r"(addr))
#define LDSM4T(R, addr)                                                       \
    asm volatile("ldmatrix.sync.aligned.m8n8.x4.trans.shared.b16 {%0,%1,%2,%3}, [%4];" \
                 : "=r"(R[0]), "=r"(R[1]), "=r"(R[2]), "=r"(R[3]) : "r"(addr))
#define MMA16816(d, a, b0v, b1v)                                              \
    asm volatile("mma.sync.aligned.m16n8k16.row.col.f32.bf16.bf16.f32 "       \
                 "{%0,%1,%2,%3},{%4,%5,%6,%7},{%8,%9},{%0,%1,%2,%3};"         \
                 : "+f"(d[0]), "+f"(d[1]), "+f"(d[2]), "+f"(d[3])             \
                 : "r"(a[0]), "r"(a[1]), "r"(a[2]), "r"(a[3]),                \
                   "r"(b0v), "r"(b1v))

__device__ __forceinline__ void split2(float x, float y,
                                       unsigned& hi, unsigned& lo) {
    __nv_bfloat16 hx = __float2bfloat16_rn(x);
    __nv_bfloat16 hy = __float2bfloat16_rn(y);
    float rx = x - __bfloat162float(hx);
    float ry = y - __bfloat162float(hy);
    __nv_bfloat16 lx = __float2bfloat16_rn(rx);
    __nv_bfloat16 ly = __float2bfloat16_rn(ry);
    __nv_bfloat162 h2 = __nv_bfloat162(hx, hy);
    __nv_bfloat162 l2 = __nv_bfloat162(lx, ly);
    hi = *(unsigned*)&h2;
    lo = *(unsigned*)&l2;
}

__global__ __launch_bounds__(256) void gemm_bias_tc(
    const float* __restrict__ A, const float* __restrict__ W,
    const float* __restrict__ bias, float* __restrict__ C,
    int M, int N, int K) {
    __shared__ __align__(16) __nv_bfloat16 Ah[128 * LDA];
    __shared__ __align__(16) __nv_bfloat16 Al[128 * LDA];
    __shared__ __align__(16) __nv_bfloat16 Bh[32 * LDB];
    __shared__ __align__(16) __nv_bfloat16 Bl[32 * LDB];

    const int tid = threadIdx.x;
    const int lane = tid & 31;
    const int warp = tid >> 5;
    const int wm = (warp >> 2) * 64;   // 0 / 64
    const int wn = (warp & 3) * 32;    // 0 / 32 / 64 / 96
    const int row0 = blockIdx.y * 128;
    const int col0 = blockIdx.x * 128;

    const unsigned aBaseH = (unsigned)__cvta_generic_to_shared(Ah);
    const unsigned aBaseL = (unsigned)__cvta_generic_to_shared(Al);
    const unsigned bBaseH = (unsigned)__cvta_generic_to_shared(Bh);
    const unsigned bBaseL = (unsigned)__cvta_generic_to_shared(Bl);

    float acc[4][4][4] = {};

    for (int k0 = 0; k0 < K; k0 += 32) {
        // ---- fill smem (convert fp32 -> bf16 hi/lo) ----
        #pragma unroll
        for (int i = 0; i < 4; i++) {
            int idx = tid + i * 256;
            {   // A tile: 128 rows x 32 k
                int r = idx >> 3, c4 = (idx & 7) * 4;
                float4 v = *(const float4*)&A[(size_t)(row0 + r) * K + k0 + c4];
                uint2 hp, lp;
                split2(v.x, v.y, hp.x, lp.x);
                split2(v.z, v.w, hp.y, lp.y);
                *(uint2*)&Ah[r * LDA + c4] = hp;
                *(uint2*)&Al[r * LDA + c4] = lp;
            }
            {   // B tile: 32 k x 128 n
                int r = idx >> 5, c4 = (idx & 31) * 4;
                float4 v = *(const float4*)&W[(size_t)(k0 + r) * N + col0 + c4];
                uint2 hp, lp;
                split2(v.x, v.y, hp.x, lp.x);
                split2(v.z, v.w, hp.y, lp.y);
                *(uint2*)&Bh[r * LDB + c4] = hp;
                *(uint2*)&Bl[r * LDB + c4] = lp;
            }
        }
        __syncthreads();

        #pragma unroll
        for (int ks = 0; ks < 2; ks++) {
            unsigned ah[4][4], al[4][4];
            #pragma unroll
            for (int im = 0; im < 4; im++) {
                unsigned off =
                    ((wm + im * 16 + (lane & 15)) * LDA + ks * 16 + (lane >> 4) * 8) * 2;
                LDSM4(ah[im], aBaseH + off);
                LDSM4(al[im], aBaseL + off);
            }
            int krow = ks * 16 + (lane & 7) + ((lane >> 3) & 1) * 8;
            #pragma unroll
            for (int pr = 0; pr < 2; pr++) {
                unsigned bh[4], bl[4];
                unsigned off = (krow * LDB + wn + pr * 16 + (lane >> 4) * 8) * 2;
                LDSM4T(bh, bBaseH + off);
                LDSM4T(bl, bBaseL + off);
                #pragma unroll
                for (int im = 0; im < 4; im++) {
                    MMA16816(acc[im][pr * 2 + 0], ah[im], bh[0], bh[1]);
                    MMA16816(acc[im][pr * 2 + 0], ah[im], bl[0], bl[1]);
                    MMA16816(acc[im][pr * 2 + 0], al[im], bh[0], bh[1]);
                    MMA16816(acc[im][pr * 2 + 1], ah[im], bh[2], bh[3]);
                    MMA16816(acc[im][pr * 2 + 1], ah[im], bl[2], bl[3]);
                    MMA16816(acc[im][pr * 2 + 1], al[im], bh[2], bh[3]);
                }
            }
        }
        __syncthreads();
    }

    // ---- epilogue: bias + store ----
    const int qr = lane >> 2, qc = lane & 3;
    #pragma unroll
    for (int im = 0; im < 4; im++) {
        #pragma unroll
        for (int jn = 0; jn < 4; jn++) {
            int row = row0 + wm + im * 16 + qr;
            int col = col0 + wn + jn * 8 + 2 * qc;
            float b0v = bias[col], b1v = bias[col + 1];
            float2 o0 = make_float2(acc[im][jn][0] + b0v, acc[im][jn][1] + b1v);
            float2 o1 = make_float2(acc[im][jn][2] + b0v, acc[im][jn][3] + b1v);
            *(float2*)&C[(size_t)row * N + col] = o0;
            *(float2*)&C[(size_t)(row + 8) * N + col] = o1;
        }
    }
}

// ================================ RoPE =======================================
__global__ void rope_kernel() {
    int idx = blockIdx.x * blockDim.x + threadIdx.x;
    const int QTOT = B * S * H * (HD / 2);
    const int KTOT = B * S * G * (HD / 2);
    if (idx >= QTOT + KTOT) return;

    float* base;
    int i, s;
    if (idx < QTOT) {
        i = idx & 63;
        int h = (idx >> 6) % H;
        s = (idx / (64 * H)) % S;
        int b = idx / (64 * H * S);
        base = &g_q[(((size_t)(b * S + s)) * H + h) * HD];
    } else {
        int j = idx - QTOT;
        i = j & 63;
        int g = (j >> 6) % G;
        s = (j / (64 * G)) % S;
        int b = j / (64 * G * S);
        base = &g_k[(((size_t)(b * S + s)) * G + g) * HD];
    }
    float inv_freq = powf(10000.0f, -((float)(2 * i) / (float)HD));
    float ang = (float)s * inv_freq;
    float c = cosf(ang);
    float sn = sinf(ang);
    float t1 = base[i];
    float t2 = base[i + 64];
    base[i]      = t1 * c - t2 * sn;
    base[i + 64] = t2 * c + t1 * sn;
}

// ========================= Flash attention (causal, GQA) =====================
#define FAM 64
#define FAN 64
#define QK_LD 68
#define V_LD 132
#define S_LD 65

__global__ void flash_kernel() {
    extern __shared__ float sm[];
    float* qts   = sm;
    float* kts   = qts + HD * QK_LD;
    float* vsm   = kts + HD * QK_LD;
    float* ssm   = vsm + FAN * V_LD;
    float* row_m = ssm + FAM * S_LD;
    float* row_l = row_m + 64;
    float* row_s = row_l + 64;

    const int tid = threadIdx.x;
    const int tx = tid & 15;
    const int ty = tid >> 4;
    const int qt = blockIdx.x;
    const int h  = blockIdx.y;
    const int b  = blockIdx.z;
    const int g  = h / (H / G);
    const int q0 = qt * FAM;
    const float scale = 0.08838834764831845f;

    #pragma unroll
    for (int it = 0; it < 8; it++) {
        int i4 = tid + it * 256;
        int r  = i4 >> 5;
        int d4 = (i4 & 31) * 4;
        float4 qv = *(const float4*)&g_q[(((size_t)(b * S + q0 + r)) * H + h) * HD + d4];
        qts[(d4 + 0) * QK_LD + r] = qv.x * scale;
        qts[(d4 + 1) * QK_LD + r] = qv.y * scale;
        qts[(d4 + 2) * QK_LD + r] = qv.z * scale;
        qts[(d4 + 3) * QK_LD + r] = qv.w * scale;
    }
    if (tid < 64) {
        row_m[tid] = -1e30f;
        row_l[tid] = 0.0f;
    }

    float o[4][8];
    #pragma unroll
    for (int r = 0; r < 4; r++)
        #pragma unroll
        for (int c = 0; c < 8; c++) o[r][c] = 0.0f;

    for (int kt = 0; kt <= qt; kt++) {
        const int k0 = kt * FAN;
        __syncthreads();
        #pragma unroll
        for (int it = 0; it < 8; it++) {
            int i4 = tid + it * 256;
            int r  = i4 >> 5;
            int d4 = (i4 & 31) * 4;
            size_t gi = (((size_t)(b * S + k0 + r)) * G + g) * HD + d4;
            float4 kv = *(const float4*)&g_k[gi];
            kts[(d4 + 0) * QK_LD + r] = kv.x;
            kts[(d4 + 1) * QK_LD + r] = kv.y;
            kts[(d4 + 2) * QK_LD + r] = kv.z;
            kts[(d4 + 3) * QK_LD + r] = kv.w;
            float4 vv = *(const float4*)&g_v[gi];
            *(float4*)&vsm[r * V_LD + d4] = vv;
        }
        __syncthreads();

        float sacc[4][4] = {};
        #pragma unroll 4
        for (int d = 0; d < HD; d++) {
            float4 a4 = *(const float4*)&qts[d * QK_LD + ty * 4];
            float4 k4 = *(const float4*)&kts[d * QK_LD + tx * 4];
            float a[4] = {a4.x, a4.y, a4.z, a4.w};
            float kvv[4] = {k4.x, k4.y, k4.z, k4.w};
            #pragma unroll
            for (int r = 0; r < 4; r++)
                #pragma unroll
                for (int c = 0; c < 4; c++)
                    sacc[r][c] += a[r] * kvv[c];
        }
        const bool diag = (kt == qt);
        #pragma unroll
        for (int r = 0; r < 4; r++) {
            int qi = q0 + ty * 4 + r;
            #pragma unroll
            for (int c = 0; c < 4; c++) {
                int ki = k0 + tx * 4 + c;
                float sv = sacc[r][c];
                if (diag && ki > qi) sv = -1e30f;
                ssm[(ty * 4 + r) * S_LD + tx * 4 + c] = sv;
            }
        }
        __syncthreads();

        if (tid < 64) {
            int row = tid;
            float mo = row_m[row];
            float mx = mo;
            #pragma unroll 8
            for (int j = 0; j < FAN; j++) mx = fmaxf(mx, ssm[row * S_LD + j]);
            float sc = expf(mo - mx);
            float lsum = 0.0f;
            #pragma unroll 4
            for (int j = 0; j < FAN; j++) {
                float p = expf(ssm[row * S_LD + j] - mx);
                ssm[row * S_LD + j] = p;
                lsum += p;
            }
            row_m[row] = mx;
            row_l[row] = row_l[row] * sc + lsum;
            row_s[row] = sc;
        }
        __syncthreads();

        float rsc[4];
        #pragma unroll
        for (int r = 0; r < 4; r++) rsc[r] = row_s[ty * 4 + r];
        #pragma unroll
        for (int r = 0; r < 4; r++)
            #pragma unroll
            for (int c = 0; c < 8; c++) o[r][c] *= rsc[r];

        #pragma unroll 2
        for (int j = 0; j < FAN; j++) {
            float p[4];
            #pragma unroll
            for (int r = 0; r < 4; r++) p[r] = ssm[(ty * 4 + r) * S_LD + j];
            float4 v0 = *(const float4*)&vsm[j * V_LD + tx * 8];
            float4 v1 = *(const float4*)&vsm[j * V_LD + tx * 8 + 4];
            float vv[8] = {v0.x, v0.y, v0.z, v0.w, v1.x, v1.y, v1.z, v1.w};
            #pragma unroll
            for (int r = 0; r < 4; r++)
                #pragma unroll
                for (int c = 0; c < 8; c++)
                    o[r][c] += p[r] * vv[c];
        }
    }

    float linv[4];
    #pragma unroll
    for (int r = 0; r < 4; r++) linv[r] = 1.0f / row_l[ty * 4 + r];
    #pragma unroll
    for (int r = 0; r < 4; r++) {
        size_t orow = (((size_t)(b * S + q0 + ty * 4 + r)) * H + h) * HD;
        #pragma unroll
        for (int c = 0; c < 8; c++)
            g_attn[orow + tx * 8 + c] = o[r][c] * linv[r];
    }
}

// =============================== launch ======================================
extern "C" void kernel_launch(void* const* d_in, const int* in_sizes, int n_in,
                              void* d_out, int out_size) {
    const float* x  = (const float*)d_in[0];
    const float* Wq = (const float*)d_in[1];
    const float* bq = (const float*)d_in[2];
    const float* Wk = (const float*)d_in[3];
    const float* bk = (const float*)d_in[4];
    const float* Wv = (const float*)d_in[5];
    const float* bv = (const float*)d_in[6];
    const float* Wo = (const float*)d_in[7];
    const float* bo = (const float*)d_in[8];
    float* out = (float*)d_out;

    float *qp, *kp, *vp, *ap;
    cudaGetSymbolAddress((void**)&qp, g_q);
    cudaGetSymbolAddress((void**)&kp, g_k);
    cudaGetSymbolAddress((void**)&vp, g_v);
    cudaGetSymbolAddress((void**)&ap, g_attn);

    const int M = B * S;  // 8192
    dim3 thr(256);

    // QKV projections (tensor core, 3xBF16)
    gemm_bias_tc<<<dim3((H * HD) / 128, M / 128), thr>>>(x, Wq, bq, qp, M, H * HD, D);
    gemm_bias_tc<<<dim3((G * HD) / 128, M / 128), thr>>>(x, Wk, bk, kp, M, G * HD, D);
    gemm_bias_tc<<<dim3((G * HD) / 128, M / 128), thr>>>(x, Wv, bv, vp, M, G * HD, D);

    // RoPE on q and k
    int rope_total = B * S * (H + G) * (HD / 2);
    rope_kernel<<<(rope_total + 255) / 256, 256>>>();

    // Flash attention (SIMT fp32)
    size_t smem = (size_t)(HD * QK_LD * 2 + FAN * V_LD + FAM * S_LD + 192) * sizeof(float);
    cudaFuncSetAttribute(flash_kernel, cudaFuncAttributeMaxDynamicSharedMemorySize, (int)smem);
    flash_kernel<<<dim3(S / FAM, H, B), 256, smem>>>();

    // Output projection (tensor core, 3xBF16)
    gemm_bias_tc<<<dim3(D / 128, M / 128), thr>>>(ap, Wo, bo, out, M, D, H * HD);
}

// round 3
// speedup vs baseline: 3.2775x; 2.1158x over previous
#include <cuda_runtime.h>
#include <cuda_bf16.h>
#include <math.h>

#define B 4
#define S 2048
#define D 2048
#define H 16
#define G 4
#define HD 128

// ------------------------- scratch (device globals, no allocs) --------------
__device__ float g_q[(size_t)B * S * H * HD];     // 64 MB
__device__ float g_k[(size_t)B * S * G * HD];     // 16 MB
__device__ float g_v[(size_t)B * S * G * HD];     // 16 MB
__device__ float g_attn[(size_t)B * S * H * HD];  // 64 MB

// ============================ shared PTX helpers =============================
#define LDSM4(R, addr)                                                        \
    asm volatile("ldmatrix.sync.aligned.m8n8.x4.shared.b16 {%0,%1,%2,%3}, [%4];" \
                 : "=r"(R[0]), "=r"(R[1]), "=r"(R[2]), "=r"(R[3]) : "r"(addr))
#define LDSM4T(R, addr)                                                       \
    asm volatile("ldmatrix.sync.aligned.m8n8.x4.trans.shared.b16 {%0,%1,%2,%3}, [%4];" \
                 : "=r"(R[0]), "=r"(R[1]), "=r"(R[2]), "=r"(R[3]) : "r"(addr))
#define MMA16816(d, a, b0v, b1v)                                              \
    asm volatile("mma.sync.aligned.m16n8k16.row.col.f32.bf16.bf16.f32 "       \
                 "{%0,%1,%2,%3},{%4,%5,%6,%7},{%8,%9},{%0,%1,%2,%3};"         \
                 : "+f"(d[0]), "+f"(d[1]), "+f"(d[2]), "+f"(d[3])             \
                 : "r"(a[0]), "r"(a[1]), "r"(a[2]), "r"(a[3]),                \
                   "r"(b0v), "r"(b1v))

__device__ __forceinline__ void split2(float x, float y,
                                       unsigned& hi, unsigned& lo) {
    __nv_bfloat16 hx = __float2bfloat16_rn(x);
    __nv_bfloat16 hy = __float2bfloat16_rn(y);
    float rx = x - __bfloat162float(hx);
    float ry = y - __bfloat162float(hy);
    __nv_bfloat16 lx = __float2bfloat16_rn(rx);
    __nv_bfloat16 ly = __float2bfloat16_rn(ry);
    __nv_bfloat162 h2 = __nv_bfloat162(hx, hy);
    __nv_bfloat162 l2 = __nv_bfloat162(lx, ly);
    hi = *(unsigned*)&h2;
    lo = *(unsigned*)&l2;
}

// ===================== Tensor-core GEMM + bias (3xBF16) ======================
#define LDA 40
#define LDB 136

__global__ __launch_bounds__(256) void gemm_bias_tc(
    const float* __restrict__ A, const float* __restrict__ W,
    const float* __restrict__ bias, float* __restrict__ C,
    int M, int N, int K) {
    __shared__ __align__(16) __nv_bfloat16 Ah[128 * LDA];
    __shared__ __align__(16) __nv_bfloat16 Al[128 * LDA];
    __shared__ __align__(16) __nv_bfloat16 Bh[32 * LDB];
    __shared__ __align__(16) __nv_bfloat16 Bl[32 * LDB];

    const int tid = threadIdx.x;
    const int lane = tid & 31;
    const int warp = tid >> 5;
    const int wm = (warp >> 2) * 64;
    const int wn = (warp & 3) * 32;
    const int row0 = blockIdx.y * 128;
    const int col0 = blockIdx.x * 128;

    const unsigned aBaseH = (unsigned)__cvta_generic_to_shared(Ah);
    const unsigned aBaseL = (unsigned)__cvta_generic_to_shared(Al);
    const unsigned bBaseH = (unsigned)__cvta_generic_to_shared(Bh);
    const unsigned bBaseL = (unsigned)__cvta_generic_to_shared(Bl);

    float acc[4][4][4] = {};

    for (int k0 = 0; k0 < K; k0 += 32) {
        #pragma unroll
        for (int i = 0; i < 4; i++) {
            int idx = tid + i * 256;
            {
                int r = idx >> 3, c4 = (idx & 7) * 4;
                float4 v = *(const float4*)&A[(size_t)(row0 + r) * K + k0 + c4];
                uint2 hp, lp;
                split2(v.x, v.y, hp.x, lp.x);
                split2(v.z, v.w, hp.y, lp.y);
                *(uint2*)&Ah[r * LDA + c4] = hp;
                *(uint2*)&Al[r * LDA + c4] = lp;
            }
            {
                int r = idx >> 5, c4 = (idx & 31) * 4;
                float4 v = *(const float4*)&W[(size_t)(k0 + r) * N + col0 + c4];
                uint2 hp, lp;
                split2(v.x, v.y, hp.x, lp.x);
                split2(v.z, v.w, hp.y, lp.y);
                *(uint2*)&Bh[r * LDB + c4] = hp;
                *(uint2*)&Bl[r * LDB + c4] = lp;
            }
        }
        __syncthreads();

        #pragma unroll
        for (int ks = 0; ks < 2; ks++) {
            unsigned ah[4][4], al[4][4];
            #pragma unroll
            for (int im = 0; im < 4; im++) {
                unsigned off =
                    ((wm + im * 16 + (lane & 15)) * LDA + ks * 16 + (lane >> 4) * 8) * 2;
                LDSM4(ah[im], aBaseH + off);
                LDSM4(al[im], aBaseL + off);
            }
            int krow = ks * 16 + (lane & 7) + ((lane >> 3) & 1) * 8;
            #pragma unroll
            for (int pr = 0; pr < 2; pr++) {
                unsigned bh[4], bl[4];
                unsigned off = (krow * LDB + wn + pr * 16 + (lane >> 4) * 8) * 2;
                LDSM4T(bh, bBaseH + off);
                LDSM4T(bl, bBaseL + off);
                #pragma unroll
                for (int im = 0; im < 4; im++) {
                    MMA16816(acc[im][pr * 2 + 0], ah[im], bh[0], bh[1]);
                    MMA16816(acc[im][pr * 2 + 0], ah[im], bl[0], bl[1]);
                    MMA16816(acc[im][pr * 2 + 0], al[im], bh[0], bh[1]);
                    MMA16816(acc[im][pr * 2 + 1], ah[im], bh[2], bh[3]);
                    MMA16816(acc[im][pr * 2 + 1], ah[im], bl[2], bl[3]);
                    MMA16816(acc[im][pr * 2 + 1], al[im], bh[2], bh[3]);
                }
            }
        }
        __syncthreads();
    }

    const int qr = lane >> 2, qc = lane & 3;
    #pragma unroll
    for (int im = 0; im < 4; im++) {
        #pragma unroll
        for (int jn = 0; jn < 4; jn++) {
            int row = row0 + wm + im * 16 + qr;
            int col = col0 + wn + jn * 8 + 2 * qc;
            float b0v = bias[col], b1v = bias[col + 1];
            float2 o0 = make_float2(acc[im][jn][0] + b0v, acc[im][jn][1] + b1v);
            float2 o1 = make_float2(acc[im][jn][2] + b0v, acc[im][jn][3] + b1v);
            *(float2*)&C[(size_t)row * N + col] = o0;
            *(float2*)&C[(size_t)(row + 8) * N + col] = o1;
        }
    }
}

// ================================ RoPE =======================================
__global__ void rope_kernel() {
    int idx = blockIdx.x * blockDim.x + threadIdx.x;
    const int QTOT = B * S * H * (HD / 2);
    const int KTOT = B * S * G * (HD / 2);
    if (idx >= QTOT + KTOT) return;

    float* base;
    int i, s;
    if (idx < QTOT) {
        i = idx & 63;
        int h = (idx >> 6) % H;
        s = (idx / (64 * H)) % S;
        int b = idx / (64 * H * S);
        base = &g_q[(((size_t)(b * S + s)) * H + h) * HD];
    } else {
        int j = idx - QTOT;
        i = j & 63;
        int g = (j >> 6) % G;
        s = (j / (64 * G)) % S;
        int b = j / (64 * G * S);
        base = &g_k[(((size_t)(b * S + s)) * G + g) * HD];
    }
    float inv_freq = powf(10000.0f, -((float)(2 * i) / (float)HD));
    float ang = (float)s * inv_freq;
    float c = cosf(ang);
    float sn = sinf(ang);
    float t1 = base[i];
    float t2 = base[i + 64];
    base[i]      = t1 * c - t2 * sn;
    base[i + 64] = t2 * c + t1 * sn;
}

// ================ Flash attention: tensor cores, 3xBF16 split ================
// 64 q-rows x 64 k-cols tiles, 4 warps (16 rows each), softmax in registers.
#define LQ 136   // bf16 smem stride (128+8): conflict-free ldmatrix

__global__ __launch_bounds__(128) void flash_tc() {
    extern __shared__ __nv_bfloat16 smb[];
    __nv_bfloat16* Qh = smb;
    __nv_bfloat16* Ql = Qh + 64 * LQ;
    __nv_bfloat16* Kh = Ql + 64 * LQ;
    __nv_bfloat16* Kl = Kh + 64 * LQ;
    __nv_bfloat16* Vh = Kl + 64 * LQ;
    __nv_bfloat16* Vl = Vh + 64 * LQ;

    const int tid  = threadIdx.x;
    const int lane = tid & 31;
    const int warp = tid >> 5;
    const int qt = blockIdx.x;
    const int h  = blockIdx.y;
    const int b  = blockIdx.z;
    const int g  = h / (H / G);
    const int q0 = qt * 64;
    const int wm = warp * 16;
    const float scale = 0.08838834764831845f;  // 1/sqrt(128)

    const unsigned qBH = (unsigned)__cvta_generic_to_shared(Qh);
    const unsigned qBL = (unsigned)__cvta_generic_to_shared(Ql);
    const unsigned kBH = (unsigned)__cvta_generic_to_shared(Kh);
    const unsigned kBL = (unsigned)__cvta_generic_to_shared(Kl);
    const unsigned vBH = (unsigned)__cvta_generic_to_shared(Vh);
    const unsigned vBL = (unsigned)__cvta_generic_to_shared(Vl);

    // ---- load Q tile (scaled, split hi/lo) ----
    #pragma unroll
    for (int it = 0; it < 16; it++) {
        int i4 = tid + it * 128;
        int r  = i4 >> 5;
        int c4 = (i4 & 31) * 4;
        float4 qv = *(const float4*)&g_q[(((size_t)(b * S + q0 + r)) * H + h) * HD + c4];
        uint2 hp, lp;
        split2(qv.x * scale, qv.y * scale, hp.x, lp.x);
        split2(qv.z * scale, qv.w * scale, hp.y, lp.y);
        *(uint2*)&Qh[r * LQ + c4] = hp;
        *(uint2*)&Ql[r * LQ + c4] = lp;
    }

    const int gid = lane >> 2, tig = lane & 3;
    const int row0g = q0 + wm + gid;     // global q row for acc elems 0,1
    const int row1g = row0g + 8;         // for elems 2,3

    float rm0 = -1e30f, rm1 = -1e30f, rl0 = 0.0f, rl1 = 0.0f;
    float oacc[16][4] = {};

    for (int kt = 0; kt <= qt; kt++) {
        const int k0 = kt * 64;
        __syncthreads();
        // ---- load K,V tiles (split hi/lo) ----
        #pragma unroll
        for (int it = 0; it < 16; it++) {
            int i4 = tid + it * 128;
            int r  = i4 >> 5;
            int c4 = (i4 & 31) * 4;
            size_t gi = (((size_t)(b * S + k0 + r)) * G + g) * HD + c4;
            float4 kv = *(const float4*)&g_k[gi];
            uint2 hp, lp;
            split2(kv.x, kv.y, hp.x, lp.x);
            split2(kv.z, kv.w, hp.y, lp.y);
            *(uint2*)&Kh[r * LQ + c4] = hp;
            *(uint2*)&Kl[r * LQ + c4] = lp;
            float4 vv = *(const float4*)&g_v[gi];
            split2(vv.x, vv.y, hp.x, lp.x);
            split2(vv.z, vv.w, hp.y, lp.y);
            *(uint2*)&Vh[r * LQ + c4] = hp;
            *(uint2*)&Vl[r * LQ + c4] = lp;
        }
        __syncthreads();

        // ---- S = Q @ K^T (3-term bf16 split) ----
        float sacc[8][4] = {};
        #pragma unroll
        for (int ks = 0; ks < 8; ks++) {
            unsigned ah[4], al[4];
            unsigned offa = ((wm + (lane & 15)) * LQ + ks * 16 + (lane >> 4) * 8) * 2;
            LDSM4(ah, qBH + offa);
            LDSM4(al, qBL + offa);
            #pragma unroll
            for (int nb = 0; nb < 4; nb++) {
                unsigned kh[4], kl[4];
                unsigned offb = ((nb * 16 + (lane >> 4) * 8 + (lane & 7)) * LQ +
                                 ks * 16 + ((lane >> 3) & 1) * 8) * 2;
                LDSM4(kh, kBH + offb);
                LDSM4(kl, kBL + offb);
                MMA16816(sacc[2 * nb + 0], ah, kh[0], kh[1]);
                MMA16816(sacc[2 * nb + 0], ah, kl[0], kl[1]);
                MMA16816(sacc[2 * nb + 0], al, kh[0], kh[1]);
                MMA16816(sacc[2 * nb + 1], ah, kh[2], kh[3]);
                MMA16816(sacc[2 * nb + 1], ah, kl[2], kl[3]);
                MMA16816(sacc[2 * nb + 1], al, kh[2], kh[3]);
            }
        }

        // ---- causal mask (diag tile only) ----
        if (kt == qt) {
            #pragma unroll
            for (int nt = 0; nt < 8; nt++) {
                int colg = k0 + nt * 8 + 2 * tig;
                if (colg > row0g)     sacc[nt][0] = -1e30f;
                if (colg + 1 > row0g) sacc[nt][1] = -1e30f;
                if (colg > row1g)     sacc[nt][2] = -1e30f;
                if (colg + 1 > row1g) sacc[nt][3] = -1e30f;
            }
        }

        // ---- online softmax (registers + quad shuffles) ----
        float mx0 = rm0, mx1 = rm1;
        #pragma unroll
        for (int nt = 0; nt < 8; nt++) {
            mx0 = fmaxf(mx0, fmaxf(sacc[nt][0], sacc[nt][1]));
            mx1 = fmaxf(mx1, fmaxf(sacc[nt][2], sacc[nt][3]));
        }
        mx0 = fmaxf(mx0, __shfl_xor_sync(0xffffffff, mx0, 1));
        mx0 = fmaxf(mx0, __shfl_xor_sync(0xffffffff, mx0, 2));
        mx1 = fmaxf(mx1, __shfl_xor_sync(0xffffffff, mx1, 1));
        mx1 = fmaxf(mx1, __shfl_xor_sync(0xffffffff, mx1, 2));
        float sc0 = __expf(rm0 - mx0);
        float sc1 = __expf(rm1 - mx1);
        rm0 = mx0; rm1 = mx1;
        float sum0 = 0.0f, sum1 = 0.0f;
        #pragma unroll
        for (int nt = 0; nt < 8; nt++) {
            sacc[nt][0] = __expf(sacc[nt][0] - mx0);
            sacc[nt][1] = __expf(sacc[nt][1] - mx0);
            sacc[nt][2] = __expf(sacc[nt][2] - mx1);
            sacc[nt][3] = __expf(sacc[nt][3] - mx1);
            sum0 += sacc[nt][0] + sacc[nt][1];
            sum1 += sacc[nt][2] + sacc[nt][3];
        }
        sum0 += __shfl_xor_sync(0xffffffff, sum0, 1);
        sum0 += __shfl_xor_sync(0xffffffff, sum0, 2);
        sum1 += __shfl_xor_sync(0xffffffff, sum1, 1);
        sum1 += __shfl_xor_sync(0xffffffff, sum1, 2);
        rl0 = rl0 * sc0 + sum0;
        rl1 = rl1 * sc1 + sum1;
        #pragma unroll
        for (int nt = 0; nt < 16; nt++) {
            oacc[nt][0] *= sc0; oacc[nt][1] *= sc0;
            oacc[nt][2] *= sc1; oacc[nt][3] *= sc1;
        }

        // ---- O += P @ V (P repacked from sacc, 3-term split) ----
        #pragma unroll
        for (int j = 0; j < 4; j++) {
            unsigned ph[4], pl[4];
            split2(sacc[2 * j][0],     sacc[2 * j][1],     ph[0], pl[0]);
            split2(sacc[2 * j][2],     sacc[2 * j][3],     ph[1], pl[1]);
            split2(sacc[2 * j + 1][0], sacc[2 * j + 1][1], ph[2], pl[2]);
            split2(sacc[2 * j + 1][2], sacc[2 * j + 1][3], ph[3], pl[3]);
            #pragma unroll
            for (int nb = 0; nb < 8; nb++) {
                unsigned vh4[4], vl4[4];
                unsigned offv = ((j * 16 + (lane & 7) + ((lane >> 3) & 1) * 8) * LQ +
                                 nb * 16 + (lane >> 4) * 8) * 2;
                LDSM4T(vh4, vBH + offv);
                LDSM4T(vl4, vBL + offv);
                MMA16816(oacc[2 * nb + 0], ph, vh4[0], vh4[1]);
                MMA16816(oacc[2 * nb + 0], ph, vl4[0], vl4[1]);
                MMA16816(oacc[2 * nb + 0], pl, vh4[0], vh4[1]);
                MMA16816(oacc[2 * nb + 1], ph, vh4[2], vh4[3]);
                MMA16816(oacc[2 * nb + 1], ph, vl4[2], vl4[3]);
                MMA16816(oacc[2 * nb + 1], pl, vh4[2], vh4[3]);
            }
        }
    }

    // ---- finalize: divide by l, store ----
    float li0 = 1.0f / rl0, li1 = 1.0f / rl1;
    size_t or0 = (((size_t)(b * S + row0g)) * H + h) * HD;
    size_t or1 = (((size_t)(b * S + row1g)) * H + h) * HD;
    #pragma unroll
    for (int nt = 0; nt < 16; nt++) {
        int col = nt * 8 + 2 * tig;
        *(float2*)&g_attn[or0 + col] = make_float2(oacc[nt][0] * li0, oacc[nt][1] * li0);
        *(float2*)&g_attn[or1 + col] = make_float2(oacc[nt][2] * li1, oacc[nt][3] * li1);
    }
}

// =============================== launch ======================================
extern "C" void kernel_launch(void* const* d_in, const int* in_sizes, int n_in,
                              void* d_out, int out_size) {
    const float* x  = (const float*)d_in[0];
    const float* Wq = (const float*)d_in[1];
    const float* bq = (const float*)d_in[2];
    const float* Wk = (const float*)d_in[3];
    const float* bk = (const float*)d_in[4];
    const float* Wv = (const float*)d_in[5];
    const float* bv = (const float*)d_in[6];
    const float* Wo = (const float*)d_in[7];
    const float* bo = (const float*)d_in[8];
    float* out = (float*)d_out;

    float *qp, *kp, *vp, *ap;
    cudaGetSymbolAddress((void**)&qp, g_q);
    cudaGetSymbolAddress((void**)&kp, g_k);
    cudaGetSymbolAddress((void**)&vp, g_v);
    cudaGetSymbolAddress((void**)&ap, g_attn);

    const int M = B * S;  // 8192
    dim3 thr(256);

    gemm_bias_tc<<<dim3((H * HD) / 128, M / 128), thr>>>(x, Wq, bq, qp, M, H * HD, D);
    gemm_bias_tc<<<dim3((G * HD) / 128, M / 128), thr>>>(x, Wk, bk, kp, M, G * HD, D);
    gemm_bias_tc<<<dim3((G * HD) / 128, M / 128), thr>>>(x, Wv, bv, vp, M, G * HD, D);

    int rope_total = B * S * (H + G) * (HD / 2);
    rope_kernel<<<(rope_total + 255) / 256, 256>>>();

    size_t smem = (size_t)6 * 64 * LQ * sizeof(__nv_bfloat16);  // 104448 B
    cudaFuncSetAttribute(flash_tc, cudaFuncAttributeMaxDynamicSharedMemorySize, (int)smem);
    flash_tc<<<dim3(S / 64, H, B), 128, smem>>>();

    gemm_bias_tc<<<dim3(D / 128, M / 128), thr>>>(ap, Wo, bo, out, M, D, H * HD);
}

// round 4
// speedup vs baseline: 3.6538x; 1.1148x over previous
#include <cuda_runtime.h>
#include <cuda_bf16.h>
#include <math.h>

#define B 4
#define S 2048
#define D 2048
#define H 16
#define G 4
#define HD 128
#define NQKV 3072   // packed q(2048) | k(512) | v(512)

// ------------------------- scratch (device globals, no allocs) --------------
__device__ float         g_qkv[(size_t)B * S * NQKV];      // 96 MB packed q|k|v
__device__ __nv_bfloat16 g_xh[(size_t)B * S * D];          // x hi
__device__ __nv_bfloat16 g_xl[(size_t)B * S * D];          // x lo
__device__ __nv_bfloat16 g_wqh[(size_t)D * NQKV];          // packed Wqkv hi
__device__ __nv_bfloat16 g_wql[(size_t)D * NQKV];          // packed Wqkv lo
__device__ __nv_bfloat16 g_woh[(size_t)H * HD * D];
__device__ __nv_bfloat16 g_wol[(size_t)H * HD * D];
__device__ __nv_bfloat16 g_ah[(size_t)B * S * H * HD];     // attn out hi
__device__ __nv_bfloat16 g_al[(size_t)B * S * H * HD];     // attn out lo
__device__ float         g_bqkv[NQKV];

// ============================ shared PTX helpers =============================
#define LDSM4(R, addr)                                                        \
    asm volatile("ldmatrix.sync.aligned.m8n8.x4.shared.b16 {%0,%1,%2,%3}, [%4];" \
                 : "=r"(R[0]), "=r"(R[1]), "=r"(R[2]), "=r"(R[3]) : "r"(addr))
#define LDSM4T(R, addr)                                                       \
    asm volatile("ldmatrix.sync.aligned.m8n8.x4.trans.shared.b16 {%0,%1,%2,%3}, [%4];" \
                 : "=r"(R[0]), "=r"(R[1]), "=r"(R[2]), "=r"(R[3]) : "r"(addr))
#define MMA16816(d, a, b0v, b1v)                                              \
    asm volatile("mma.sync.aligned.m16n8k16.row.col.f32.bf16.bf16.f32 "       \
                 "{%0,%1,%2,%3},{%4,%5,%6,%7},{%8,%9},{%0,%1,%2,%3};"         \
                 : "+f"(d[0]), "+f"(d[1]), "+f"(d[2]), "+f"(d[3])             \
                 : "r"(a[0]), "r"(a[1]), "r"(a[2]), "r"(a[3]),                \
                   "r"(b0v), "r"(b1v))
#define CP16(smaddr, gptr)                                                    \
    asm volatile("cp.async.cg.shared.global [%0], [%1], 16;" :: "r"(smaddr), "l"(gptr))
#define CP_COMMIT asm volatile("cp.async.commit_group;")

__device__ __forceinline__ void split2(float x, float y,
                                       unsigned& hi, unsigned& lo) {
    __nv_bfloat16 hx = __float2bfloat16_rn(x);
    __nv_bfloat16 hy = __float2bfloat16_rn(y);
    float rx = x - __bfloat162float(hx);
    float ry = y - __bfloat162float(hy);
    __nv_bfloat16 lx = __float2bfloat16_rn(rx);
    __nv_bfloat16 ly = __float2bfloat16_rn(ry);
    __nv_bfloat162 h2 = __nv_bfloat162(hx, hy);
    __nv_bfloat162 l2 = __nv_bfloat162(lx, ly);
    hi = *(unsigned*)&h2;
    lo = *(unsigned*)&l2;
}

// ========================= conversion / packing kernels ======================
__global__ void convert_split(const float* __restrict__ src,
                              __nv_bfloat16* __restrict__ hi,
                              __nv_bfloat16* __restrict__ lo, int n4) {
    int i = blockIdx.x * blockDim.x + threadIdx.x;
    if (i >= n4) return;
    float4 v = ((const float4*)src)[i];
    uint2 h, l;
    split2(v.x, v.y, h.x, l.x);
    split2(v.z, v.w, h.y, l.y);
    ((uint2*)hi)[i] = h;
    ((uint2*)lo)[i] = l;
}

__global__ void convert_pack(const float* __restrict__ src,
                             __nv_bfloat16* __restrict__ hi,
                             __nv_bfloat16* __restrict__ lo,
                             int srcN, int dstOff, int n4) {
    int i = blockIdx.x * blockDim.x + threadIdx.x;
    if (i >= n4) return;
    int rw = srcN >> 2;
    int r = i / rw, c = (i % rw) * 4;
    float4 v = *(const float4*)&src[(size_t)r * srcN + c];
    uint2 h, l;
    split2(v.x, v.y, h.x, l.x);
    split2(v.z, v.w, h.y, l.y);
    size_t d = (size_t)r * NQKV + dstOff + c;
    *(uint2*)&hi[d] = h;
    *(uint2*)&lo[d] = l;
}

__global__ void pack_bias(const float* __restrict__ bq, const float* __restrict__ bk,
                          const float* __restrict__ bv, float* __restrict__ dst) {
    int i = blockIdx.x * blockDim.x + threadIdx.x;
    if (i >= NQKV) return;
    dst[i] = (i < 2048) ? bq[i] : (i < 2560) ? bk[i - 2048] : bv[i - 2560];
}

// =========== Tensor-core GEMM + bias (pre-split bf16, cp.async x2) ===========
#define LDA 40
#define LDB 136
#define ST_EL 18944   // per-stage smem elements: 2*128*40 + 2*32*136

__global__ __launch_bounds__(256) void gemm_bias_bf16(
    const __nv_bfloat16* __restrict__ Ahg, const __nv_bfloat16* __restrict__ Alg,
    const __nv_bfloat16* __restrict__ Bhg, const __nv_bfloat16* __restrict__ Blg,
    const float* __restrict__ bias, float* __restrict__ C,
    int M, int N, int K) {
    extern __shared__ __nv_bfloat16 smem[];
    const unsigned smBase = (unsigned)__cvta_generic_to_shared(smem);

    const int tid = threadIdx.x;
    const int lane = tid & 31;
    const int warp = tid >> 5;
    const int wm = (warp >> 2) * 64;
    const int wn = (warp & 3) * 32;
    const int row0 = blockIdx.y * 128;
    const int col0 = blockIdx.x * 128;
    const int NT = K / 32;

    float acc[4][4][4] = {};

    // ---- async-load one k-stage into buffer st ----
    auto issue = [&](int st, int k0) {
        unsigned sb = smBase + st * (ST_EL * 2);
        #pragma unroll
        for (int j = 0; j < 2; j++) {           // A hi/lo: 512 chunks each
            int c = tid + j * 256;
            int r = c >> 2, c8 = (c & 3) * 8;
            unsigned so = (unsigned)(r * LDA + c8) * 2;
            CP16(sb + so, &Ahg[(size_t)(row0 + r) * K + k0 + c8]);
            CP16(sb + 10240 + so, &Alg[(size_t)(row0 + r) * K + k0 + c8]);
        }
        #pragma unroll
        for (int j = 0; j < 2; j++) {           // B hi/lo
            int c = tid + j * 256;
            int r = c >> 4, c8 = (c & 15) * 8;
            unsigned so = (unsigned)(r * LDB + c8) * 2;
            CP16(sb + 20480 + so, &Bhg[(size_t)(k0 + r) * N + col0 + c8]);
            CP16(sb + 29184 + so, &Blg[(size_t)(k0 + r) * N + col0 + c8]);
        }
    };

    issue(0, 0);
    CP_COMMIT;

    for (int it = 0; it < NT; it++) {
        if (it + 1 < NT) {
            issue((it + 1) & 1, (it + 1) * 32);
            CP_COMMIT;
            asm volatile("cp.async.wait_group 1;");
        } else {
            asm volatile("cp.async.wait_group 0;");
        }
        __syncthreads();

        unsigned sb = smBase + (it & 1) * (ST_EL * 2);
        const unsigned aBaseH = sb, aBaseL = sb + 10240;
        const unsigned bBaseH = sb + 20480, bBaseL = sb + 29184;

        #pragma unroll
        for (int ks = 0; ks < 2; ks++) {
            unsigned ah[4][4], al[4][4];
            #pragma unroll
            for (int im = 0; im < 4; im++) {
                unsigned off =
                    ((wm + im * 16 + (lane & 15)) * LDA + ks * 16 + (lane >> 4) * 8) * 2;
                LDSM4(ah[im], aBaseH + off);
                LDSM4(al[im], aBaseL + off);
            }
            int krow = ks * 16 + (lane & 7) + ((lane >> 3) & 1) * 8;
            #pragma unroll
            for (int pr = 0; pr < 2; pr++) {
                unsigned bh[4], bl[4];
                unsigned off = (krow * LDB + wn + pr * 16 + (lane >> 4) * 8) * 2;
                LDSM4T(bh, bBaseH + off);
                LDSM4T(bl, bBaseL + off);
                #pragma unroll
                for (int im = 0; im < 4; im++) {
                    MMA16816(acc[im][pr * 2 + 0], ah[im], bh[0], bh[1]);
                    MMA16816(acc[im][pr * 2 + 0], ah[im], bl[0], bl[1]);
                    MMA16816(acc[im][pr * 2 + 0], al[im], bh[0], bh[1]);
                    MMA16816(acc[im][pr * 2 + 1], ah[im], bh[2], bh[3]);
                    MMA16816(acc[im][pr * 2 + 1], ah[im], bl[2], bl[3]);
                    MMA16816(acc[im][pr * 2 + 1], al[im], bh[2], bh[3]);
                }
            }
        }
        __syncthreads();
    }

    const int qr = lane >> 2, qc = lane & 3;
    #pragma unroll
    for (int im = 0; im < 4; im++) {
        #pragma unroll
        for (int jn = 0; jn < 4; jn++) {
            int row = row0 + wm + im * 16 + qr;
            int col = col0 + wn + jn * 8 + 2 * qc;
            float b0v = bias[col], b1v = bias[col + 1];
            float2 o0 = make_float2(acc[im][jn][0] + b0v, acc[im][jn][1] + b1v);
            float2 o1 = make_float2(acc[im][jn][2] + b0v, acc[im][jn][3] + b1v);
            *(float2*)&C[(size_t)row * N + col] = o0;
            *(float2*)&C[(size_t)(row + 8) * N + col] = o1;
        }
    }
}

// ================================ RoPE (packed) ==============================
__global__ void rope_kernel() {
    int idx = blockIdx.x * blockDim.x + threadIdx.x;
    const int QTOT = B * S * H * (HD / 2);
    const int KTOT = B * S * G * (HD / 2);
    if (idx >= QTOT + KTOT) return;

    float* base;
    int i, s;
    if (idx < QTOT) {
        i = idx & 63;
        int h = (idx >> 6) % H;
        s = (idx / (64 * H)) % S;
        int b = idx / (64 * H * S);
        base = &g_qkv[(size_t)(b * S + s) * NQKV + h * HD];
    } else {
        int j = idx - QTOT;
        i = j & 63;
        int g = (j >> 6) % G;
        s = (j / (64 * G)) % S;
        int b = j / (64 * G * S);
        base = &g_qkv[(size_t)(b * S + s) * NQKV + 2048 + g * HD];
    }
    float inv_freq = powf(10000.0f, -((float)(2 * i) / (float)HD));
    float ang = (float)s * inv_freq;
    float c = cosf(ang);
    float sn = sinf(ang);
    float t1 = base[i];
    float t2 = base[i + 64];
    base[i]      = t1 * c - t2 * sn;
    base[i + 64] = t2 * c + t1 * sn;
}

// ================ Flash attention: tensor cores, 3xBF16 split ================
#define LQ 136

__global__ __launch_bounds__(128) void flash_tc() {
    extern __shared__ __nv_bfloat16 smb[];
    __nv_bfloat16* Qh = smb;
    __nv_bfloat16* Ql = Qh + 64 * LQ;
    __nv_bfloat16* Kh = Ql + 64 * LQ;
    __nv_bfloat16* Kl = Kh + 64 * LQ;
    __nv_bfloat16* Vh = Kl + 64 * LQ;
    __nv_bfloat16* Vl = Vh + 64 * LQ;

    const int tid  = threadIdx.x;
    const int lane = tid & 31;
    const int warp = tid >> 5;
    const int qt = blockIdx.x;
    const int h  = blockIdx.y;
    const int b  = blockIdx.z;
    const int g  = h / (H / G);
    const int q0 = qt * 64;
    const int wm = warp * 16;
    const float scale = 0.08838834764831845f;

    const unsigned qBH = (unsigned)__cvta_generic_to_shared(Qh);
    const unsigned qBL = (unsigned)__cvta_generic_to_shared(Ql);
    const unsigned kBH = (unsigned)__cvta_generic_to_shared(Kh);
    const unsigned kBL = (unsigned)__cvta_generic_to_shared(Kl);
    const unsigned vBH = (unsigned)__cvta_generic_to_shared(Vh);
    const unsigned vBL = (unsigned)__cvta_generic_to_shared(Vl);

    #pragma unroll
    for (int it = 0; it < 16; it++) {
        int i4 = tid + it * 128;
        int r  = i4 >> 5;
        int c4 = (i4 & 31) * 4;
        float4 qv = *(const float4*)&g_qkv[(size_t)(b * S + q0 + r) * NQKV + h * HD + c4];
        uint2 hp, lp;
        split2(qv.x * scale, qv.y * scale, hp.x, lp.x);
        split2(qv.z * scale, qv.w * scale, hp.y, lp.y);
        *(uint2*)&Qh[r * LQ + c4] = hp;
        *(uint2*)&Ql[r * LQ + c4] = lp;
    }

    const int gid = lane >> 2, tig = lane & 3;
    const int row0g = q0 + wm + gid;
    const int row1g = row0g + 8;

    float rm0 = -1e30f, rm1 = -1e30f, rl0 = 0.0f, rl1 = 0.0f;
    float oacc[16][4] = {};

    for (int kt = 0; kt <= qt; kt++) {
        const int k0 = kt * 64;
        __syncthreads();
        #pragma unroll
        for (int it = 0; it < 16; it++) {
            int i4 = tid + it * 128;
            int r  = i4 >> 5;
            int c4 = (i4 & 31) * 4;
            size_t rb = (size_t)(b * S + k0 + r) * NQKV + 2048 + g * HD + c4;
            float4 kv = *(const float4*)&g_qkv[rb];
            uint2 hp, lp;
            split2(kv.x, kv.y, hp.x, lp.x);
            split2(kv.z, kv.w, hp.y, lp.y);
            *(uint2*)&Kh[r * LQ + c4] = hp;
            *(uint2*)&Kl[r * LQ + c4] = lp;
            float4 vv = *(const float4*)&g_qkv[rb + 512];
            split2(vv.x, vv.y, hp.x, lp.x);
            split2(vv.z, vv.w, hp.y, lp.y);
            *(uint2*)&Vh[r * LQ + c4] = hp;
            *(uint2*)&Vl[r * LQ + c4] = lp;
        }
        __syncthreads();

        float sacc[8][4] = {};
        #pragma unroll
        for (int ks = 0; ks < 8; ks++) {
            unsigned ah[4], al[4];
            unsigned offa = ((wm + (lane & 15)) * LQ + ks * 16 + (lane >> 4) * 8) * 2;
            LDSM4(ah, qBH + offa);
            LDSM4(al, qBL + offa);
            #pragma unroll
            for (int nb = 0; nb < 4; nb++) {
                unsigned kh[4], kl[4];
                unsigned offb = ((nb * 16 + (lane >> 4) * 8 + (lane & 7)) * LQ +
                                 ks * 16 + ((lane >> 3) & 1) * 8) * 2;
                LDSM4(kh, kBH + offb);
                LDSM4(kl, kBL + offb);
                MMA16816(sacc[2 * nb + 0], ah, kh[0], kh[1]);
                MMA16816(sacc[2 * nb + 0], ah, kl[0], kl[1]);
                MMA16816(sacc[2 * nb + 0], al, kh[0], kh[1]);
                MMA16816(sacc[2 * nb + 1], ah, kh[2], kh[3]);
                MMA16816(sacc[2 * nb + 1], ah, kl[2], kl[3]);
                MMA16816(sacc[2 * nb + 1], al, kh[2], kh[3]);
            }
        }

        if (kt == qt) {
            #pragma unroll
            for (int nt = 0; nt < 8; nt++) {
                int colg = k0 + nt * 8 + 2 * tig;
                if (colg > row0g)     sacc[nt][0] = -1e30f;
                if (colg + 1 > row0g) sacc[nt][1] = -1e30f;
                if (colg > row1g)     sacc[nt][2] = -1e30f;
                if (colg + 1 > row1g) sacc[nt][3] = -1e30f;
            }
        }

        float mx0 = rm0, mx1 = rm1;
        #pragma unroll
        for (int nt = 0; nt < 8; nt++) {
            mx0 = fmaxf(mx0, fmaxf(sacc[nt][0], sacc[nt][1]));
            mx1 = fmaxf(mx1, fmaxf(sacc[nt][2], sacc[nt][3]));
        }
        mx0 = fmaxf(mx0, __shfl_xor_sync(0xffffffff, mx0, 1));
        mx0 = fmaxf(mx0, __shfl_xor_sync(0xffffffff, mx0, 2));
        mx1 = fmaxf(mx1, __shfl_xor_sync(0xffffffff, mx1, 1));
        mx1 = fmaxf(mx1, __shfl_xor_sync(0xffffffff, mx1, 2));
        float sc0 = __expf(rm0 - mx0);
        float sc1 = __expf(rm1 - mx1);
        rm0 = mx0; rm1 = mx1;
        float sum0 = 0.0f, sum1 = 0.0f;
        #pragma unroll
        for (int nt = 0; nt < 8; nt++) {
            sacc[nt][0] = __expf(sacc[nt][0] - mx0);
            sacc[nt][1] = __expf(sacc[nt][1] - mx0);
            sacc[nt][2] = __expf(sacc[nt][2] - mx1);
            sacc[nt][3] = __expf(sacc[nt][3] - mx1);
            sum0 += sacc[nt][0] + sacc[nt][1];
            sum1 += sacc[nt][2] + sacc[nt][3];
        }
        sum0 += __shfl_xor_sync(0xffffffff, sum0, 1);
        sum0 += __shfl_xor_sync(0xffffffff, sum0, 2);
        sum1 += __shfl_xor_sync(0xffffffff, sum1, 1);
        sum1 += __shfl_xor_sync(0xffffffff, sum1, 2);
        rl0 = rl0 * sc0 + sum0;
        rl1 = rl1 * sc1 + sum1;
        #pragma unroll
        for (int nt = 0; nt < 16; nt++) {
            oacc[nt][0] *= sc0; oacc[nt][1] *= sc0;
            oacc[nt][2] *= sc1; oacc[nt][3] *= sc1;
        }

        #pragma unroll
        for (int j = 0; j < 4; j++) {
            unsigned ph[4], pl[4];
            split2(sacc[2 * j][0],     sacc[2 * j][1],     ph[0], pl[0]);
            split2(sacc[2 * j][2],     sacc[2 * j][3],     ph[1], pl[1]);
            split2(sacc[2 * j + 1][0], sacc[2 * j + 1][1], ph[2], pl[2]);
            split2(sacc[2 * j + 1][2], sacc[2 * j + 1][3], ph[3], pl[3]);
            #pragma unroll
            for (int nb = 0; nb < 8; nb++) {
                unsigned vh4[4], vl4[4];
                unsigned offv = ((j * 16 + (lane & 7) + ((lane >> 3) & 1) * 8) * LQ +
                                 nb * 16 + (lane >> 4) * 8) * 2;
                LDSM4T(vh4, vBH + offv);
                LDSM4T(vl4, vBL + offv);
                MMA16816(oacc[2 * nb + 0], ph, vh4[0], vh4[1]);
                MMA16816(oacc[2 * nb + 0], ph, vl4[0], vl4[1]);
                MMA16816(oacc[2 * nb + 0], pl, vh4[0], vh4[1]);
                MMA16816(oacc[2 * nb + 1], ph, vh4[2], vh4[3]);
                MMA16816(oacc[2 * nb + 1], ph, vl4[2], vl4[3]);
                MMA16816(oacc[2 * nb + 1], pl, vh4[2], vh4[3]);
            }
        }
    }

    // ---- finalize: divide by l, split to bf16 hi/lo, store ----
    float li0 = 1.0f / rl0, li1 = 1.0f / rl1;
    size_t or0 = (size_t)(b * S + row0g) * (H * HD) + h * HD;
    size_t or1 = (size_t)(b * S + row1g) * (H * HD) + h * HD;
    #pragma unroll
    for (int nt = 0; nt < 16; nt++) {
        int col = nt * 8 + 2 * tig;
        unsigned hh, ll;
        split2(oacc[nt][0] * li0, oacc[nt][1] * li0, hh, ll);
        *(unsigned*)&g_ah[or0 + col] = hh;
        *(unsigned*)&g_al[or0 + col] = ll;
        split2(oacc[nt][2] * li1, oacc[nt][3] * li1, hh, ll);
        *(unsigned*)&g_ah[or1 + col] = hh;
        *(unsigned*)&g_al[or1 + col] = ll;
    }
}

// =============================== launch ======================================
extern "C" void kernel_launch(void* const* d_in, const int* in_sizes, int n_in,
                              void* d_out, int out_size) {
    const float* x  = (const float*)d_in[0];
    const float* Wq = (const float*)d_in[1];
    const float* bq = (const float*)d_in[2];
    const float* Wk = (const float*)d_in[3];
    const float* bk = (const float*)d_in[4];
    const float* Wv = (const float*)d_in[5];
    const float* bv = (const float*)d_in[6];
    const float* Wo = (const float*)d_in[7];
    const float* bo = (const float*)d_in[8];
    float* out = (float*)d_out;

    __nv_bfloat16 *xh, *xl, *wqh, *wql, *woh, *wol, *ah, *al;
    float *qkv, *bqkv;
    cudaGetSymbolAddress((void**)&xh, g_xh);
    cudaGetSymbolAddress((void**)&xl, g_xl);
    cudaGetSymbolAddress((void**)&wqh, g_wqh);
    cudaGetSymbolAddress((void**)&wql, g_wql);
    cudaGetSymbolAddress((void**)&woh, g_woh);
    cudaGetSymbolAddress((void**)&wol, g_wol);
    cudaGetSymbolAddress((void**)&ah, g_ah);
    cudaGetSymbolAddress((void**)&al, g_al);
    cudaGetSymbolAddress((void**)&qkv, g_qkv);
    cudaGetSymbolAddress((void**)&bqkv, g_bqkv);

    const int M = B * S;  // 8192

    // ---- pre-split conversions ----
    {
        int n4 = M * D / 4;
        convert_split<<<(n4 + 255) / 256, 256>>>(x, xh, xl, n4);
    }
    {
        int n4 = D * 2048 / 4;
        convert_pack<<<(n4 + 255) / 256, 256>>>(Wq, wqh, wql, 2048, 0, n4);
        n4 = D * 512 / 4;
        convert_pack<<<(n4 + 255) / 256, 256>>>(Wk, wqh, wql, 512, 2048, n4);
        convert_pack<<<(n4 + 255) / 256, 256>>>(Wv, wqh, wql, 512, 2560, n4);
        n4 = D * D / 4;
        convert_split<<<(n4 + 255) / 256, 256>>>(Wo, woh, wol, n4);
    }
    pack_bias<<<(NQKV + 255) / 256, 256>>>(bq, bk, bv, bqkv);

    size_t gsm = (size_t)2 * ST_EL * sizeof(__nv_bfloat16);  // 75776 B
    cudaFuncSetAttribute(gemm_bias_bf16, cudaFuncAttributeMaxDynamicSharedMemorySize, (int)gsm);

    // ---- fused QKV projection ----
    gemm_bias_bf16<<<dim3(NQKV / 128, M / 128), 256, gsm>>>(
        xh, xl, wqh, wql, bqkv, qkv, M, NQKV, D);

    // ---- RoPE ----
    int rope_total = B * S * (H + G) * (HD / 2);
    rope_kernel<<<(rope_total + 255) / 256, 256>>>();

    // ---- flash attention ----
    size_t smem = (size_t)6 * 64 * LQ * sizeof(__nv_bfloat16);  // 104448 B
    cudaFuncSetAttribute(flash_tc, cudaFuncAttributeMaxDynamicSharedMemorySize, (int)smem);
    flash_tc<<<dim3(S / 64, H, B), 128, smem>>>();

    // ---- output projection ----
    gemm_bias_bf16<<<dim3(D / 128, M / 128), 256, gsm>>>(
        ah, al, woh, wol, bo, out, M, D, H * HD);
}

// round 6
// speedup vs baseline: 3.7172x; 1.0174x over previous
#include <cuda_runtime.h>
#include <cuda_bf16.h>
#include <math.h>

#define B 4
#define S 2048
#define D 2048
#define H 16
#define G 4
#define HD 128
#define NQKV 3072   // packed q(2048) | k(512) | v(512)

// ------------------------- scratch (device globals, no allocs) --------------
__device__ float         g_qkv[(size_t)B * S * NQKV];      // 96 MB packed q|k|v
__device__ __nv_bfloat16 g_xh[(size_t)B * S * D];
__device__ __nv_bfloat16 g_xl[(size_t)B * S * D];
__device__ __nv_bfloat16 g_wqh[(size_t)D * NQKV];          // packed Wqkv hi [k][n]
__device__ __nv_bfloat16 g_wql[(size_t)D * NQKV];
__device__ __nv_bfloat16 g_woh[(size_t)H * HD * D];
__device__ __nv_bfloat16 g_wol[(size_t)H * HD * D];
__device__ __nv_bfloat16 g_ah[(size_t)B * S * H * HD];     // attn out hi
__device__ __nv_bfloat16 g_al[(size_t)B * S * H * HD];     // attn out lo
__device__ float         g_bqkv[NQKV];
// pre-split, roped operands for flash
__device__ __nv_bfloat16 g_qsh[(size_t)B * H * S * HD];    // q hi [b][h][s][hd]
__device__ __nv_bfloat16 g_qsl[(size_t)B * H * S * HD];
__device__ __nv_bfloat16 g_ksh[(size_t)B * G * S * HD];    // k hi [b][g][s][hd]
__device__ __nv_bfloat16 g_ksl[(size_t)B * G * S * HD];
__device__ __nv_bfloat16 g_vsh[(size_t)B * G * S * HD];
__device__ __nv_bfloat16 g_vsl[(size_t)B * G * S * HD];

// ============================ shared PTX helpers =============================
#define LDSM4(R, addr)                                                        \
    asm volatile("ldmatrix.sync.aligned.m8n8.x4.shared.b16 {%0,%1,%2,%3}, [%4];" \
                 : "=r"(R[0]), "=r"(R[1]), "=r"(R[2]), "=r"(R[3]) : "r"(addr))
#define LDSM4T(R, addr)                                                       \
    asm volatile("ldmatrix.sync.aligned.m8n8.x4.trans.shared.b16 {%0,%1,%2,%3}, [%4];" \
                 : "=r"(R[0]), "=r"(R[1]), "=r"(R[2]), "=r"(R[3]) : "r"(addr))
#define MMA16816(d, a, b0v, b1v)                                              \
    asm volatile("mma.sync.aligned.m16n8k16.row.col.f32.bf16.bf16.f32 "       \
                 "{%0,%1,%2,%3},{%4,%5,%6,%7},{%8,%9},{%0,%1,%2,%3};"         \
                 : "+f"(d[0]), "+f"(d[1]), "+f"(d[2]), "+f"(d[3])             \
                 : "r"(a[0]), "r"(a[1]), "r"(a[2]), "r"(a[3]),                \
                   "r"(b0v), "r"(b1v))
#define CP16(smaddr, gptr)                                                    \
    asm volatile("cp.async.cg.shared.global [%0], [%1], 16;" :: "r"(smaddr), "l"(gptr))
#define CP_COMMIT asm volatile("cp.async.commit_group;")

__device__ __forceinline__ void split2(float x, float y,
                                       unsigned& hi, unsigned& lo) {
    __nv_bfloat16 hx = __float2bfloat16_rn(x);
    __nv_bfloat16 hy = __float2bfloat16_rn(y);
    float rx = x - __bfloat162float(hx);
    float ry = y - __bfloat162float(hy);
    __nv_bfloat16 lx = __float2bfloat16_rn(rx);
    __nv_bfloat16 ly = __float2bfloat16_rn(ry);
    __nv_bfloat162 h2 = __nv_bfloat162(hx, hy);
    __nv_bfloat162 l2 = __nv_bfloat162(lx, ly);
    hi = *(unsigned*)&h2;
    lo = *(unsigned*)&l2;
}

// ========================= conversion / packing kernels ======================
__global__ void convert_split(const float* __restrict__ src,
                              __nv_bfloat16* __restrict__ hi,
                              __nv_bfloat16* __restrict__ lo, int n4) {
    int i = blockIdx.x * blockDim.x + threadIdx.x;
    if (i >= n4) return;
    float4 v = ((const float4*)src)[i];
    uint2 h, l;
    split2(v.x, v.y, h.x, l.x);
    split2(v.z, v.w, h.y, l.y);
    ((uint2*)hi)[i] = h;
    ((uint2*)lo)[i] = l;
}

__global__ void convert_pack(const float* __restrict__ src,
                             __nv_bfloat16* __restrict__ hi,
                             __nv_bfloat16* __restrict__ lo,
                             int srcN, int dstOff, int n4) {
    int i = blockIdx.x * blockDim.x + threadIdx.x;
    if (i >= n4) return;
    int rw = srcN >> 2;
    int r = i / rw, c = (i % rw) * 4;
    float4 v = *(const float4*)&src[(size_t)r * srcN + c];
    uint2 h, l;
    split2(v.x, v.y, h.x, l.x);
    split2(v.z, v.w, h.y, l.y);
    size_t d = (size_t)r * NQKV + dstOff + c;
    *(uint2*)&hi[d] = h;
    *(uint2*)&lo[d] = l;
}

__global__ void pack_bias(const float* __restrict__ bq, const float* __restrict__ bk,
                          const float* __restrict__ bv, float* __restrict__ dst) {
    int i = blockIdx.x * blockDim.x + threadIdx.x;
    if (i >= NQKV) return;
    dst[i] = (i < 2048) ? bq[i] : (i < 2560) ? bk[i - 2048] : bv[i - 2560];
}

// =========== Tensor-core GEMM + bias (pre-split bf16, cp.async x2) ===========
#define LDA 40
#define LDB 136
#define ST_EL 18944   // per-stage smem elements: 2*128*40 + 2*32*136

__global__ __launch_bounds__(256) void gemm_bias_bf16(
    const __nv_bfloat16* __restrict__ Ahg, const __nv_bfloat16* __restrict__ Alg,
    const __nv_bfloat16* __restrict__ Bhg, const __nv_bfloat16* __restrict__ Blg,
    const float* __restrict__ bias, float* __restrict__ C,
    int M, int N, int K) {
    extern __shared__ __nv_bfloat16 smem[];
    const unsigned smBase = (unsigned)__cvta_generic_to_shared(smem);

    const int tid = threadIdx.x;
    const int lane = tid & 31;
    const int warp = tid >> 5;
    const int wm = (warp >> 2) * 64;
    const int wn = (warp & 3) * 32;
    const int row0 = blockIdx.y * 128;
    const int col0 = blockIdx.x * 128;
    const int NT = K / 32;

    float acc[4][4][4] = {};

    auto issue = [&](int st, int k0) {
        unsigned sb = smBase + st * (ST_EL * 2);
        #pragma unroll
        for (int j = 0; j < 2; j++) {
            int c = tid + j * 256;
            int r = c >> 2, c8 = (c & 3) * 8;
            unsigned so = (unsigned)(r * LDA + c8) * 2;
            CP16(sb + so, &Ahg[(size_t)(row0 + r) * K + k0 + c8]);
            CP16(sb + 10240 + so, &Alg[(size_t)(row0 + r) * K + k0 + c8]);
        }
        #pragma unroll
        for (int j = 0; j < 2; j++) {
            int c = tid + j * 256;
            int r = c >> 4, c8 = (c & 15) * 8;
            unsigned so = (unsigned)(r * LDB + c8) * 2;
            CP16(sb + 20480 + so, &Bhg[(size_t)(k0 + r) * N + col0 + c8]);
            CP16(sb + 29184 + so, &Blg[(size_t)(k0 + r) * N + col0 + c8]);
        }
    };

    issue(0, 0);
    CP_COMMIT;

    for (int it = 0; it < NT; it++) {
        if (it + 1 < NT) {
            issue((it + 1) & 1, (it + 1) * 32);
            CP_COMMIT;
            asm volatile("cp.async.wait_group 1;");
        } else {
            asm volatile("cp.async.wait_group 0;");
        }
        __syncthreads();

        unsigned sb = smBase + (it & 1) * (ST_EL * 2);
        const unsigned aBaseH = sb, aBaseL = sb + 10240;
        const unsigned bBaseH = sb + 20480, bBaseL = sb + 29184;

        #pragma unroll
        for (int ks = 0; ks < 2; ks++) {
            unsigned ah[4][4], al[4][4];
            #pragma unroll
            for (int im = 0; im < 4; im++) {
                unsigned off =
                    ((wm + im * 16 + (lane & 15)) * LDA + ks * 16 + (lane >> 4) * 8) * 2;
                LDSM4(ah[im], aBaseH + off);
                LDSM4(al[im], aBaseL + off);
            }
            int krow = ks * 16 + (lane & 7) + ((lane >> 3) & 1) * 8;
            #pragma unroll
            for (int pr = 0; pr < 2; pr++) {
                unsigned bh[4], bl[4];
                unsigned off = (krow * LDB + wn + pr * 16 + (lane >> 4) * 8) * 2;
                LDSM4T(bh, bBaseH + off);
                LDSM4T(bl, bBaseL + off);
                #pragma unroll
                for (int im = 0; im < 4; im++) {
                    MMA16816(acc[im][pr * 2 + 0], ah[im], bh[0], bh[1]);
                    MMA16816(acc[im][pr * 2 + 0], ah[im], bl[0], bl[1]);
                    MMA16816(acc[im][pr * 2 + 0], al[im], bh[0], bh[1]);
                    MMA16816(acc[im][pr * 2 + 1], ah[im], bh[2], bh[3]);
                    MMA16816(acc[im][pr * 2 + 1], ah[im], bl[2], bl[3]);
                    MMA16816(acc[im][pr * 2 + 1], al[im], bh[2], bh[3]);
                }
            }
        }
        __syncthreads();
    }

    const int qr = lane >> 2, qc = lane & 3;
    #pragma unroll
    for (int im = 0; im < 4; im++) {
        #pragma unroll
        for (int jn = 0; jn < 4; jn++) {
            int row = row0 + wm + im * 16 + qr;
            int col = col0 + wn + jn * 8 + 2 * qc;
            float b0v = bias[col], b1v = bias[col + 1];
            float2 o0 = make_float2(acc[im][jn][0] + b0v, acc[im][jn][1] + b1v);
            float2 o1 = make_float2(acc[im][jn][2] + b0v, acc[im][jn][3] + b1v);
            *(float2*)&C[(size_t)row * N + col] = o0;
            *(float2*)&C[(size_t)(row + 8) * N + col] = o1;
        }
    }
}

// ================== fused RoPE + fp32->bf16 hi/lo split ======================
// Reads g_qkv (post-GEMM), writes pre-split roped q (scaled), k, and split v.
__global__ void rope_split() {
    int idx = blockIdx.x * blockDim.x + threadIdx.x;
    const int QN = B * S * H * 16;   // quads of rope pairs (4 pairs/thread)
    const int KN = B * S * G * 16;
    const int VN = B * S * G * 32;   // float4 quads of v
    const float scale = 0.08838834764831845f;

    if (idx < QN + KN) {
        bool isq = idx < QN;
        int j = isq ? idx : idx - QN;
        int nh = isq ? H : G;
        int i  = (j & 15) * 4;
        int hh = (j >> 4) % nh;
        int s  = (j / (16 * nh)) % S;
        int b  = j / (16 * nh * S);
        const float* src = &g_qkv[(size_t)(b * S + s) * NQKV + (isq ? 0 : 2048) + hh * HD];
        float4 a = *(const float4*)&src[i];
        float4 c = *(const float4*)&src[i + 64];
        float av[4] = {a.x, a.y, a.z, a.w};
        float cv[4] = {c.x, c.y, c.z, c.w};
        float o1[4], o2[4];
        #pragma unroll
        for (int t = 0; t < 4; t++) {
            float inv_freq = powf(10000.0f, -((float)(i + t) / 64.0f));
            float ang = (float)s * inv_freq;
            float cs = cosf(ang), sn = sinf(ang);
            o1[t] = av[t] * cs - cv[t] * sn;
            o2[t] = cv[t] * cs + av[t] * sn;
            if (isq) { o1[t] *= scale; o2[t] *= scale; }
        }
        uint2 h1, l1, h2, l2;
        split2(o1[0], o1[1], h1.x, l1.x);
        split2(o1[2], o1[3], h1.y, l1.y);
        split2(o2[0], o2[1], h2.x, l2.x);
        split2(o2[2], o2[3], h2.y, l2.y);
        size_t dst = ((size_t)(b * nh + hh) * S + s) * HD + i;
        __nv_bfloat16* dh = isq ? g_qsh : g_ksh;
        __nv_bfloat16* dl = isq ? g_qsl : g_ksl;
        *(uint2*)&dh[dst] = h1;
        *(uint2*)&dl[dst] = l1;
        *(uint2*)&dh[dst + 64] = h2;
        *(uint2*)&dl[dst + 64] = l2;
    } else if (idx < QN + KN + VN) {
        int j = idx - QN - KN;
        int i = (j & 31) * 4;
        int gg = (j >> 5) % G;
        int s  = (j / (32 * G)) % S;
        int b  = j / (32 * G * S);
        float4 v = *(const float4*)&g_qkv[(size_t)(b * S + s) * NQKV + 2560 + gg * HD + i];
        uint2 h, l;
        split2(v.x, v.y, h.x, l.x);
        split2(v.z, v.w, h.y, l.y);
        size_t dst = ((size_t)(b * G + gg) * S + s) * HD + i;
        *(uint2*)&g_vsh[dst] = h;
        *(uint2*)&g_vsl[dst] = l;
    }
}

// ================ Flash attention: HMMA tensor cores, 3xBF16 =================
// Consumes pre-split bf16 hi/lo q/k/v — no conversion math in the loop.
#define LQ 136

__global__ __launch_bounds__(128) void flash_tc() {
    extern __shared__ __nv_bfloat16 smb[];
    __nv_bfloat16* Qh = smb;
    __nv_bfloat16* Ql = Qh + 64 * LQ;
    __nv_bfloat16* Kh = Ql + 64 * LQ;
    __nv_bfloat16* Kl = Kh + 64 * LQ;
    __nv_bfloat16* Vh = Kl + 64 * LQ;
    __nv_bfloat16* Vl = Vh + 64 * LQ;

    const int tid  = threadIdx.x;
    const int lane = tid & 31;
    const int warp = tid >> 5;
    const int qt = gridDim.x - 1 - blockIdx.x;   // heavy tiles first
    const int h  = blockIdx.y;
    const int b  = blockIdx.z;
    const int g  = h / (H / G);
    const int q0 = qt * 64;
    const int wm = warp * 16;

    const unsigned qBH = (unsigned)__cvta_generic_to_shared(Qh);
    const unsigned qBL = (unsigned)__cvta_generic_to_shared(Ql);
    const unsigned kBH = (unsigned)__cvta_generic_to_shared(Kh);
    const unsigned kBL = (unsigned)__cvta_generic_to_shared(Kl);
    const unsigned vBH = (unsigned)__cvta_generic_to_shared(Vh);
    const unsigned vBL = (unsigned)__cvta_generic_to_shared(Vl);

    // ---- load Q tile (pre-split, pre-scaled) ----
    #pragma unroll
    for (int it = 0; it < 8; it++) {
        int i4 = tid + it * 128;
        int r  = i4 >> 4;
        int c8 = (i4 & 15) * 8;
        size_t gi = ((size_t)(b * H + h) * S + q0 + r) * HD + c8;
        *(uint4*)&Qh[r * LQ + c8] = *(const uint4*)&g_qsh[gi];
        *(uint4*)&Ql[r * LQ + c8] = *(const uint4*)&g_qsl[gi];
    }

    const int gid = lane >> 2, tig = lane & 3;
    const int row0g = q0 + wm + gid;
    const int row1g = row0g + 8;

    float rm0 = -1e30f, rm1 = -1e30f, rl0 = 0.0f, rl1 = 0.0f;
    float oacc[16][4] = {};

    for (int kt = 0; kt <= qt; kt++) {
        const int k0 = kt * 64;
        __syncthreads();
        // ---- load K,V tiles (straight copies) ----
        #pragma unroll
        for (int it = 0; it < 8; it++) {
            int i4 = tid + it * 128;
            int r  = i4 >> 4;
            int c8 = (i4 & 15) * 8;
            size_t gi = ((size_t)(b * G + g) * S + k0 + r) * HD + c8;
            unsigned so = r * LQ + c8;
            *(uint4*)&Kh[so] = *(const uint4*)&g_ksh[gi];
            *(uint4*)&Kl[so] = *(const uint4*)&g_ksl[gi];
            *(uint4*)&Vh[so] = *(const uint4*)&g_vsh[gi];
            *(uint4*)&Vl[so] = *(const uint4*)&g_vsl[gi];
        }
        __syncthreads();

        // ---- S = Q @ K^T (3-term bf16 split) ----
        float sacc[8][4] = {};
        #pragma unroll
        for (int ks = 0; ks < 8; ks++) {
            unsigned ah[4], al[4];
            unsigned offa = ((wm + (lane & 15)) * LQ + ks * 16 + (lane >> 4) * 8) * 2;
            LDSM4(ah, qBH + offa);
            LDSM4(al, qBL + offa);
            #pragma unroll
            for (int nb = 0; nb < 4; nb++) {
                unsigned kh[4], kl[4];
                unsigned offb = ((nb * 16 + (lane >> 4) * 8 + (lane & 7)) * LQ +
                                 ks * 16 + ((lane >> 3) & 1) * 8) * 2;
                LDSM4(kh, kBH + offb);
                LDSM4(kl, kBL + offb);
                MMA16816(sacc[2 * nb + 0], ah, kh[0], kh[1]);
                MMA16816(sacc[2 * nb + 0], ah, kl[0], kl[1]);
                MMA16816(sacc[2 * nb + 0], al, kh[0], kh[1]);
                MMA16816(sacc[2 * nb + 1], ah, kh[2], kh[3]);
                MMA16816(sacc[2 * nb + 1], ah, kl[2], kl[3]);
                MMA16816(sacc[2 * nb + 1], al, kh[2], kh[3]);
            }
        }

        if (kt == qt) {
            #pragma unroll
            for (int nt = 0; nt < 8; nt++) {
                int colg = k0 + nt * 8 + 2 * tig;
                if (colg > row0g)     sacc[nt][0] = -1e30f;
                if (colg + 1 > row0g) sacc[nt][1] = -1e30f;
                if (colg > row1g)     sacc[nt][2] = -1e30f;
                if (colg + 1 > row1g) sacc[nt][3] = -1e30f;
            }
        }

        // ---- online softmax (registers + quad shuffles) ----
        float mx0 = rm0, mx1 = rm1;
        #pragma unroll
        for (int nt = 0; nt < 8; nt++) {
            mx0 = fmaxf(mx0, fmaxf(sacc[nt][0], sacc[nt][1]));
            mx1 = fmaxf(mx1, fmaxf(sacc[nt][2], sacc[nt][3]));
        }
        mx0 = fmaxf(mx0, __shfl_xor_sync(0xffffffff, mx0, 1));
        mx0 = fmaxf(mx0, __shfl_xor_sync(0xffffffff, mx0, 2));
        mx1 = fmaxf(mx1, __shfl_xor_sync(0xffffffff, mx1, 1));
        mx1 = fmaxf(mx1, __shfl_xor_sync(0xffffffff, mx1, 2));
        float sc0 = __expf(rm0 - mx0);
        float sc1 = __expf(rm1 - mx1);
        rm0 = mx0; rm1 = mx1;
        float sum0 = 0.0f, sum1 = 0.0f;
        #pragma unroll
        for (int nt = 0; nt < 8; nt++) {
            sacc[nt][0] = __expf(sacc[nt][0] - mx0);
            sacc[nt][1] = __expf(sacc[nt][1] - mx0);
            sacc[nt][2] = __expf(sacc[nt][2] - mx1);
            sacc[nt][3] = __expf(sacc[nt][3] - mx1);
            sum0 += sacc[nt][0] + sacc[nt][1];
            sum1 += sacc[nt][2] + sacc[nt][3];
        }
        sum0 += __shfl_xor_sync(0xffffffff, sum0, 1);
        sum0 += __shfl_xor_sync(0xffffffff, sum0, 2);
        sum1 += __shfl_xor_sync(0xffffffff, sum1, 1);
        sum1 += __shfl_xor_sync(0xffffffff, sum1, 2);
        rl0 = rl0 * sc0 + sum0;
        rl1 = rl1 * sc1 + sum1;
        #pragma unroll
        for (int nt = 0; nt < 16; nt++) {
            oacc[nt][0] *= sc0; oacc[nt][1] *= sc0;
            oacc[nt][2] *= sc1; oacc[nt][3] *= sc1;
        }

        // ---- O += P @ V ----
        #pragma unroll
        for (int j = 0; j < 4; j++) {
            unsigned ph[4], pl[4];
            split2(sacc[2 * j][0],     sacc[2 * j][1],     ph[0], pl[0]);
            split2(sacc[2 * j][2],     sacc[2 * j][3],     ph[1], pl[1]);
            split2(sacc[2 * j + 1][0], sacc[2 * j + 1][1], ph[2], pl[2]);
            split2(sacc[2 * j + 1][2], sacc[2 * j + 1][3], ph[3], pl[3]);
            #pragma unroll
            for (int nb = 0; nb < 8; nb++) {
                unsigned vh4[4], vl4[4];
                unsigned offv = ((j * 16 + (lane & 7) + ((lane >> 3) & 1) * 8) * LQ +
                                 nb * 16 + (lane >> 4) * 8) * 2;
                LDSM4T(vh4, vBH + offv);
                LDSM4T(vl4, vBL + offv);
                MMA16816(oacc[2 * nb + 0], ph, vh4[0], vh4[1]);
                MMA16816(oacc[2 * nb + 0], ph, vl4[0], vl4[1]);
                MMA16816(oacc[2 * nb + 0], pl, vh4[0], vh4[1]);
                MMA16816(oacc[2 * nb + 1], ph, vh4[2], vh4[3]);
                MMA16816(oacc[2 * nb + 1], ph, vl4[2], vl4[3]);
                MMA16816(oacc[2 * nb + 1], pl, vh4[2], vh4[3]);
            }
        }
    }

    // ---- finalize: divide by l, split to bf16 hi/lo, store ----
    float li0 = 1.0f / rl0, li1 = 1.0f / rl1;
    size_t or0 = (size_t)(b * S + row0g) * (H * HD) + h * HD;
    size_t or1 = (size_t)(b * S + row1g) * (H * HD) + h * HD;
    #pragma unroll
    for (int nt = 0; nt < 16; nt++) {
        int col = nt * 8 + 2 * tig;
        unsigned hh, ll;
        split2(oacc[nt][0] * li0, oacc[nt][1] * li0, hh, ll);
        *(unsigned*)&g_ah[or0 + col] = hh;
        *(unsigned*)&g_al[or0 + col] = ll;
        split2(oacc[nt][2] * li1, oacc[nt][3] * li1, hh, ll);
        *(unsigned*)&g_ah[or1 + col] = hh;
        *(unsigned*)&g_al[or1 + col] = ll;
    }
}

// =============================== launch ======================================
extern "C" void kernel_launch(void* const* d_in, const int* in_sizes, int n_in,
                              void* d_out, int out_size) {
    const float* x  = (const float*)d_in[0];
    const float* Wq = (const float*)d_in[1];
    const float* bq = (const float*)d_in[2];
    const float* Wk = (const float*)d_in[3];
    const float* bk = (const float*)d_in[4];
    const float* Wv = (const float*)d_in[5];
    const float* bv = (const float*)d_in[6];
    const float* Wo = (const float*)d_in[7];
    const float* bo = (const float*)d_in[8];
    float* out = (float*)d_out;

    __nv_bfloat16 *xh, *xl, *wqh, *wql, *woh, *wol, *ah, *al;
    float *qkv, *bqkv;
    cudaGetSymbolAddress((void**)&xh, g_xh);
    cudaGetSymbolAddress((void**)&xl, g_xl);
    cudaGetSymbolAddress((void**)&wqh, g_wqh);
    cudaGetSymbolAddress((void**)&wql, g_wql);
    cudaGetSymbolAddress((void**)&woh, g_woh);
    cudaGetSymbolAddress((void**)&wol, g_wol);
    cudaGetSymbolAddress((void**)&ah, g_ah);
    cudaGetSymbolAddress((void**)&al, g_al);
    cudaGetSymbolAddress((void**)&qkv, g_qkv);
    cudaGetSymbolAddress((void**)&bqkv, g_bqkv);

    const int M = B * S;  // 8192

    // ---- pre-split conversions ----
    {
        int n4 = M * D / 4;
        convert_split<<<(n4 + 255) / 256, 256>>>(x, xh, xl, n4);
    }
    {
        int n4 = D * 2048 / 4;
        convert_pack<<<(n4 + 255) / 256, 256>>>(Wq, wqh, wql, 2048, 0, n4);
        n4 = D * 512 / 4;
        convert_pack<<<(n4 + 255) / 256, 256>>>(Wk, wqh, wql, 512, 2048, n4);
        convert_pack<<<(n4 + 255) / 256, 256>>>(Wv, wqh, wql, 512, 2560, n4);
        n4 = D * D / 4;
        convert_split<<<(n4 + 255) / 256, 256>>>(Wo, woh, wol, n4);
    }
    pack_bias<<<(NQKV + 255) / 256, 256>>>(bq, bk, bv, bqkv);

    size_t gsm = (size_t)2 * ST_EL * sizeof(__nv_bfloat16);  // 75776 B
    cudaFuncSetAttribute(gemm_bias_bf16, cudaFuncAttributeMaxDynamicSharedMemorySize, (int)gsm);

    // ---- fused QKV projection ----
    gemm_bias_bf16<<<dim3(NQKV / 128, M / 128), 256, gsm>>>(
        xh, xl, wqh, wql, bqkv, qkv, M, NQKV, D);

    // ---- fused RoPE + hi/lo split ----
    int rs_total = B * S * H * 16 + B * S * G * 16 + B * S * G * 32;
    rope_split<<<(rs_total + 255) / 256, 256>>>();

    // ---- flash attention ----
    size_t smem = (size_t)6 * 64 * LQ * sizeof(__nv_bfloat16);  // 104448 B
    cudaFuncSetAttribute(flash_tc, cudaFuncAttributeMaxDynamicSharedMemorySize, (int)smem);
    flash_tc<<<dim3(S / 64, H, B), 128, smem>>>();

    // ---- output projection ----
    gemm_bias_bf16<<<dim3(D / 128, M / 128), 256, gsm>>>(
        ah, al, woh, wol, bo, out, M, D, H * HD);
}

// round 7
// speedup vs baseline: 3.8205x; 1.0278x over previous
#include <cuda_runtime.h>
#include <cuda_bf16.h>
#include <math.h>

#define B 4
#define S 2048
#define D 2048
#define H 16
#define G 4
#define HD 128
#define NQKV 3072   // packed q(2048) | k(512) | v(512)

// ------------------------- scratch (device globals, no allocs) --------------
__device__ __nv_bfloat16 g_xh[(size_t)B * S * D];
__device__ __nv_bfloat16 g_xl[(size_t)B * S * D];
__device__ __nv_bfloat16 g_wqh[(size_t)D * NQKV];          // packed Wqkv hi [k][n]
__device__ __nv_bfloat16 g_wql[(size_t)D * NQKV];
__device__ __nv_bfloat16 g_woh[(size_t)H * HD * D];
__device__ __nv_bfloat16 g_wol[(size_t)H * HD * D];
__device__ __nv_bfloat16 g_ah[(size_t)B * S * H * HD];     // attn out hi
__device__ __nv_bfloat16 g_al[(size_t)B * S * H * HD];     // attn out lo
__device__ float         g_bqkv[NQKV];
// pre-split, roped operands for flash
__device__ __nv_bfloat16 g_qsh[(size_t)B * H * S * HD];    // q hi [b][h][s][hd]
__device__ __nv_bfloat16 g_qsl[(size_t)B * H * S * HD];
__device__ __nv_bfloat16 g_ksh[(size_t)B * G * S * HD];    // k hi [b][g][s][hd]
__device__ __nv_bfloat16 g_ksl[(size_t)B * G * S * HD];
__device__ __nv_bfloat16 g_vsh[(size_t)B * G * S * HD];
__device__ __nv_bfloat16 g_vsl[(size_t)B * G * S * HD];

// ============================ shared PTX helpers =============================
#define LDSM4(R, addr)                                                        \
    asm volatile("ldmatrix.sync.aligned.m8n8.x4.shared.b16 {%0,%1,%2,%3}, [%4];" \
                 : "=r"(R[0]), "=r"(R[1]), "=r"(R[2]), "=r"(R[3]) : "r"(addr))
#define LDSM4T(R, addr)                                                       \
    asm volatile("ldmatrix.sync.aligned.m8n8.x4.trans.shared.b16 {%0,%1,%2,%3}, [%4];" \
                 : "=r"(R[0]), "=r"(R[1]), "=r"(R[2]), "=r"(R[3]) : "r"(addr))
#define MMA16816(d, a, b0v, b1v)                                              \
    asm volatile("mma.sync.aligned.m16n8k16.row.col.f32.bf16.bf16.f32 "       \
                 "{%0,%1,%2,%3},{%4,%5,%6,%7},{%8,%9},{%0,%1,%2,%3};"         \
                 : "+f"(d[0]), "+f"(d[1]), "+f"(d[2]), "+f"(d[3])             \
                 : "r"(a[0]), "r"(a[1]), "r"(a[2]), "r"(a[3]),                \
                   "r"(b0v), "r"(b1v))
#define CP16(smaddr, gptr)                                                    \
    asm volatile("cp.async.cg.shared.global [%0], [%1], 16;" :: "r"(smaddr), "l"(gptr))
#define CP_COMMIT asm volatile("cp.async.commit_group;")

__device__ __forceinline__ void split2(float x, float y,
                                       unsigned& hi, unsigned& lo) {
    __nv_bfloat16 hx = __float2bfloat16_rn(x);
    __nv_bfloat16 hy = __float2bfloat16_rn(y);
    float rx = x - __bfloat162float(hx);
    float ry = y - __bfloat162float(hy);
    __nv_bfloat16 lx = __float2bfloat16_rn(rx);
    __nv_bfloat16 ly = __float2bfloat16_rn(ry);
    __nv_bfloat162 h2 = __nv_bfloat162(hx, hy);
    __nv_bfloat162 l2 = __nv_bfloat162(lx, ly);
    hi = *(unsigned*)&h2;
    lo = *(unsigned*)&l2;
}

// ========================= conversion / packing kernels ======================
__global__ void convert_split(const float* __restrict__ src,
                              __nv_bfloat16* __restrict__ hi,
                              __nv_bfloat16* __restrict__ lo, int n4) {
    int i = blockIdx.x * blockDim.x + threadIdx.x;
    if (i >= n4) return;
    float4 v = ((const float4*)src)[i];
    uint2 h, l;
    split2(v.x, v.y, h.x, l.x);
    split2(v.z, v.w, h.y, l.y);
    ((uint2*)hi)[i] = h;
    ((uint2*)lo)[i] = l;
}

__global__ void convert_pack(const float* __restrict__ src,
                             __nv_bfloat16* __restrict__ hi,
                             __nv_bfloat16* __restrict__ lo,
                             int srcN, int dstOff, int n4) {
    int i = blockIdx.x * blockDim.x + threadIdx.x;
    if (i >= n4) return;
    int rw = srcN >> 2;
    int r = i / rw, c = (i % rw) * 4;
    float4 v = *(const float4*)&src[(size_t)r * srcN + c];
    uint2 h, l;
    split2(v.x, v.y, h.x, l.x);
    split2(v.z, v.w, h.y, l.y);
    size_t d = (size_t)r * NQKV + dstOff + c;
    *(uint2*)&hi[d] = h;
    *(uint2*)&lo[d] = l;
}

__global__ void pack_bias(const float* __restrict__ bq, const float* __restrict__ bk,
                          const float* __restrict__ bv, float* __restrict__ dst) {
    int i = blockIdx.x * blockDim.x + threadIdx.x;
    if (i >= NQKV) return;
    dst[i] = (i < 2048) ? bq[i] : (i < 2560) ? bk[i - 2048] : bv[i - 2560];
}

// ======================== GEMM mainloop shared pieces ========================
#define LDA 40
#define LDB 136
#define ST_EL 18944   // per-stage smem elements: 2*128*40 + 2*32*136

// Mainloop macro body is shared by both GEMM kernels via a helper.
struct GemmAcc { float a[4][4][4]; };

__device__ __forceinline__ void gemm_mainloop(
    const __nv_bfloat16* __restrict__ Ahg, const __nv_bfloat16* __restrict__ Alg,
    const __nv_bfloat16* __restrict__ Bhg, const __nv_bfloat16* __restrict__ Blg,
    int K, int N, int row0, int col0, unsigned smBase, GemmAcc& acc) {
    const int tid = threadIdx.x;
    const int lane = tid & 31;
    const int warp = tid >> 5;
    const int wm = (warp >> 2) * 64;
    const int wn = (warp & 3) * 32;
    const int NT = K / 32;

    auto issue = [&](int st, int k0) {
        unsigned sb = smBase + st * (ST_EL * 2);
        #pragma unroll
        for (int j = 0; j < 2; j++) {
            int c = tid + j * 256;
            int r = c >> 2, c8 = (c & 3) * 8;
            unsigned so = (unsigned)(r * LDA + c8) * 2;
            CP16(sb + so, &Ahg[(size_t)(row0 + r) * K + k0 + c8]);
            CP16(sb + 10240 + so, &Alg[(size_t)(row0 + r) * K + k0 + c8]);
        }
        #pragma unroll
        for (int j = 0; j < 2; j++) {
            int c = tid + j * 256;
            int r = c >> 4, c8 = (c & 15) * 8;
            unsigned so = (unsigned)(r * LDB + c8) * 2;
            CP16(sb + 20480 + so, &Bhg[(size_t)(k0 + r) * N + col0 + c8]);
            CP16(sb + 29184 + so, &Blg[(size_t)(k0 + r) * N + col0 + c8]);
        }
    };

    issue(0, 0);
    CP_COMMIT;

    for (int it = 0; it < NT; it++) {
        if (it + 1 < NT) {
            issue((it + 1) & 1, (it + 1) * 32);
            CP_COMMIT;
            asm volatile("cp.async.wait_group 1;");
        } else {
            asm volatile("cp.async.wait_group 0;");
        }
        __syncthreads();

        unsigned sb = smBase + (it & 1) * (ST_EL * 2);
        const unsigned aBaseH = sb, aBaseL = sb + 10240;
        const unsigned bBaseH = sb + 20480, bBaseL = sb + 29184;

        #pragma unroll
        for (int ks = 0; ks < 2; ks++) {
            unsigned ah[4][4], al[4][4];
            #pragma unroll
            for (int im = 0; im < 4; im++) {
                unsigned off =
                    ((wm + im * 16 + (lane & 15)) * LDA + ks * 16 + (lane >> 4) * 8) * 2;
                LDSM4(ah[im], aBaseH + off);
                LDSM4(al[im], aBaseL + off);
            }
            int krow = ks * 16 + (lane & 7) + ((lane >> 3) & 1) * 8;
            #pragma unroll
            for (int pr = 0; pr < 2; pr++) {
                unsigned bh[4], bl[4];
                unsigned off = (krow * LDB + wn + pr * 16 + (lane >> 4) * 8) * 2;
                LDSM4T(bh, bBaseH + off);
                LDSM4T(bl, bBaseL + off);
                #pragma unroll
                for (int im = 0; im < 4; im++) {
                    MMA16816(acc.a[im][pr * 2 + 0], ah[im], bh[0], bh[1]);
                    MMA16816(acc.a[im][pr * 2 + 0], ah[im], bl[0], bl[1]);
                    MMA16816(acc.a[im][pr * 2 + 0], al[im], bh[0], bh[1]);
                    MMA16816(acc.a[im][pr * 2 + 1], ah[im], bh[2], bh[3]);
                    MMA16816(acc.a[im][pr * 2 + 1], ah[im], bl[2], bl[3]);
                    MMA16816(acc.a[im][pr * 2 + 1], al[im], bh[2], bh[3]);
                }
            }
        }
        __syncthreads();
    }
}

// ============= QKV GEMM with fused bias + RoPE + hi/lo split epilogue ========
#define STF 132   // fp32 smem stride for epilogue tile

__global__ __launch_bounds__(256) void gemm_qkv_fused(
    const __nv_bfloat16* __restrict__ Ahg, const __nv_bfloat16* __restrict__ Alg,
    const __nv_bfloat16* __restrict__ Bhg, const __nv_bfloat16* __restrict__ Blg,
    const float* __restrict__ bias) {
    extern __shared__ __nv_bfloat16 smem[];
    const unsigned smBase = (unsigned)__cvta_generic_to_shared(smem);

    const int tid = threadIdx.x;
    const int lane = tid & 31;
    const int warp = tid >> 5;
    const int wm = (warp >> 2) * 64;
    const int wn = (warp & 3) * 32;
    const int row0 = blockIdx.y * 128;
    const int col0 = blockIdx.x * 128;

    GemmAcc acc = {};
    gemm_mainloop(Ahg, Alg, Bhg, Blg, D, NQKV, row0, col0, smBase, acc);

    // ---- stage fp32 tile (with bias) in smem ----
    float* st = (float*)smem;
    const int qr = lane >> 2, qc = lane & 3;
    #pragma unroll
    for (int im = 0; im < 4; im++) {
        #pragma unroll
        for (int jn = 0; jn < 4; jn++) {
            int rr = wm + im * 16 + qr;
            int cc = wn + jn * 8 + 2 * qc;
            float b0v = bias[col0 + cc], b1v = bias[col0 + cc + 1];
            st[rr * STF + cc]           = acc.a[im][jn][0] + b0v;
            st[rr * STF + cc + 1]       = acc.a[im][jn][1] + b1v;
            st[(rr + 8) * STF + cc]     = acc.a[im][jn][2] + b0v;
            st[(rr + 8) * STF + cc + 1] = acc.a[im][jn][3] + b1v;
        }
    }
    __syncthreads();

    const int tile = col0 >> 7;      // head tile: 0-15 q, 16-19 k, 20-23 v
    const int bb = row0 >> 11;
    const float scale = 0.08838834764831845f;
    const float L2E = 0.20762050593046f;   // log2(10000)/64

    if (tile < 20) {   // q or k: rope + split
        bool isq = tile < 16;
        int hh = isq ? tile : tile - 16;
        int nh = isq ? H : G;
        __nv_bfloat16* dh = isq ? g_qsh : g_ksh;
        __nv_bfloat16* dl = isq ? g_qsl : g_ksl;
        float sc = isq ? scale : 1.0f;
        #pragma unroll 4
        for (int t = 0; t < 16; t++) {
            int idx = tid + t * 256;
            int r = idx >> 5;
            int i2 = (idx & 31) * 2;
            int s = (row0 + r) & (S - 1);
            float a0 = st[r * STF + i2],      a1 = st[r * STF + i2 + 1];
            float c0 = st[r * STF + i2 + 64], c1 = st[r * STF + i2 + 65];
            float f0 = exp2f(-(float)i2 * L2E);
            float f1 = exp2f(-(float)(i2 + 1) * L2E);
            float cs0 = cosf(s * f0), sn0 = sinf(s * f0);
            float cs1 = cosf(s * f1), sn1 = sinf(s * f1);
            float o10 = (a0 * cs0 - c0 * sn0) * sc;
            float o11 = (a1 * cs1 - c1 * sn1) * sc;
            float o20 = (c0 * cs0 + a0 * sn0) * sc;
            float o21 = (c1 * cs1 + a1 * sn1) * sc;
            unsigned h1, l1, h2, l2;
            split2(o10, o11, h1, l1);
            split2(o20, o21, h2, l2);
            size_t dst = ((size_t)(bb * nh + hh) * S + s) * HD + i2;
            *(unsigned*)&dh[dst] = h1;
            *(unsigned*)&dl[dst] = l1;
            *(unsigned*)&dh[dst + 64] = h2;
            *(unsigned*)&dl[dst + 64] = l2;
        }
    } else {           // v: split only
        int gg = tile - 20;
        #pragma unroll 4
        for (int t = 0; t < 32; t++) {
            int idx = tid + t * 256;
            int r = idx >> 6;
            int i2 = (idx & 63) * 2;
            int s = (row0 + r) & (S - 1);
            float v0 = st[r * STF + i2], v1 = st[r * STF + i2 + 1];
            unsigned h, l;
            split2(v0, v1, h, l);
            size_t dst = ((size_t)(bb * G + gg) * S + s) * HD + i2;
            *(unsigned*)&g_vsh[dst] = h;
            *(unsigned*)&g_vsl[dst] = l;
        }
    }
}

// ================ plain GEMM + bias (for output projection) ==================
__global__ __launch_bounds__(256) void gemm_bias_bf16(
    const __nv_bfloat16* __restrict__ Ahg, const __nv_bfloat16* __restrict__ Alg,
    const __nv_bfloat16* __restrict__ Bhg, const __nv_bfloat16* __restrict__ Blg,
    const float* __restrict__ bias, float* __restrict__ C,
    int M, int N, int K) {
    extern __shared__ __nv_bfloat16 smem[];
    const unsigned smBase = (unsigned)__cvta_generic_to_shared(smem);

    const int tid = threadIdx.x;
    const int lane = tid & 31;
    const int warp = tid >> 5;
    const int wm = (warp >> 2) * 64;
    const int wn = (warp & 3) * 32;
    const int row0 = blockIdx.y * 128;
    const int col0 = blockIdx.x * 128;

    GemmAcc acc = {};
    gemm_mainloop(Ahg, Alg, Bhg, Blg, K, N, row0, col0, smBase, acc);

    const int qr = lane >> 2, qc = lane & 3;
    #pragma unroll
    for (int im = 0; im < 4; im++) {
        #pragma unroll
        for (int jn = 0; jn < 4; jn++) {
            int row = row0 + wm + im * 16 + qr;
            int col = col0 + wn + jn * 8 + 2 * qc;
            float b0v = bias[col], b1v = bias[col + 1];
            float2 o0 = make_float2(acc.a[im][jn][0] + b0v, acc.a[im][jn][1] + b1v);
            float2 o1 = make_float2(acc.a[im][jn][2] + b0v, acc.a[im][jn][3] + b1v);
            *(float2*)&C[(size_t)row * N + col] = o0;
            *(float2*)&C[(size_t)(row + 8) * N + col] = o1;
        }
    }
}

// ====== Flash attention: 128-row q tiles, 8 warps, HMMA 3xBF16 split =========
#define LQ 136

__global__ __launch_bounds__(256) void flash_tc() {
    extern __shared__ __nv_bfloat16 smb[];
    __nv_bfloat16* Qh = smb;
    __nv_bfloat16* Ql = Qh + 128 * LQ;
    __nv_bfloat16* Kh = Ql + 128 * LQ;
    __nv_bfloat16* Kl = Kh + 64 * LQ;
    __nv_bfloat16* Vh = Kl + 64 * LQ;
    __nv_bfloat16* Vl = Vh + 64 * LQ;

    const int tid  = threadIdx.x;
    const int lane = tid & 31;
    const int warp = tid >> 5;              // 0..7
    const int qtile = gridDim.x - 1 - blockIdx.x;  // heavy tiles first
    const int h  = blockIdx.y;
    const int b  = blockIdx.z;
    const int g  = h / (H / G);
    const int q0 = qtile * 128;
    const int wm = warp * 16;

    const unsigned qBH = (unsigned)__cvta_generic_to_shared(Qh);
    const unsigned qBL = (unsigned)__cvta_generic_to_shared(Ql);
    const unsigned kBH = (unsigned)__cvta_generic_to_shared(Kh);
    const unsigned kBL = (unsigned)__cvta_generic_to_shared(Kl);
    const unsigned vBH = (unsigned)__cvta_generic_to_shared(Vh);
    const unsigned vBL = (unsigned)__cvta_generic_to_shared(Vl);

    // ---- load Q tile (pre-split, pre-scaled, roped) ----
    #pragma unroll
    for (int it = 0; it < 8; it++) {
        int i4 = tid + it * 256;           // 0..2047
        int r  = i4 >> 4;                  // 0..127
        int c8 = (i4 & 15) * 8;
        size_t gi = ((size_t)(b * H + h) * S + q0 + r) * HD + c8;
        *(uint4*)&Qh[r * LQ + c8] = *(const uint4*)&g_qsh[gi];
        *(uint4*)&Ql[r * LQ + c8] = *(const uint4*)&g_qsl[gi];
    }

    const int gid = lane >> 2, tig = lane & 3;
    const int row0g = q0 + wm + gid;
    const int row1g = row0g + 8;
    const int wmaxrow = q0 + wm + 15;

    float rm0 = -1e30f, rm1 = -1e30f, rl0 = 0.0f, rl1 = 0.0f;
    float oacc[16][4] = {};

    const int NKT = 2 * qtile + 2;
    for (int kt = 0; kt < NKT; kt++) {
        const int k0 = kt * 64;
        __syncthreads();
        // ---- load K,V tiles ----
        #pragma unroll
        for (int it = 0; it < 4; it++) {
            int i4 = tid + it * 256;       // 0..1023
            int r  = i4 >> 4;              // 0..63
            int c8 = (i4 & 15) * 8;
            size_t gi = ((size_t)(b * G + g) * S + k0 + r) * HD + c8;
            unsigned so = r * LQ + c8;
            *(uint4*)&Kh[so] = *(const uint4*)&g_ksh[gi];
            *(uint4*)&Kl[so] = *(const uint4*)&g_ksl[gi];
            *(uint4*)&Vh[so] = *(const uint4*)&g_vsh[gi];
            *(uint4*)&Vl[so] = *(const uint4*)&g_vsl[gi];
        }
        __syncthreads();

        if (k0 > wmaxrow) continue;        // whole warp above diagonal

        // ---- S = Q @ K^T ----
        float sacc[8][4] = {};
        #pragma unroll
        for (int ks = 0; ks < 8; ks++) {
            unsigned ah[4], al[4];
            unsigned offa = ((wm + (lane & 15)) * LQ + ks * 16 + (lane >> 4) * 8) * 2;
            LDSM4(ah, qBH + offa);
            LDSM4(al, qBL + offa);
            #pragma unroll
            for (int nb = 0; nb < 4; nb++) {
                unsigned kh[4], kl[4];
                unsigned offb = ((nb * 16 + (lane >> 4) * 8 + (lane & 7)) * LQ +
                                 ks * 16 + ((lane >> 3) & 1) * 8) * 2;
                LDSM4(kh, kBH + offb);
                LDSM4(kl, kBL + offb);
                MMA16816(sacc[2 * nb + 0], ah, kh[0], kh[1]);
                MMA16816(sacc[2 * nb + 0], ah, kl[0], kl[1]);
                MMA16816(sacc[2 * nb + 0], al, kh[0], kh[1]);
                MMA16816(sacc[2 * nb + 1], ah, kh[2], kh[3]);
                MMA16816(sacc[2 * nb + 1], ah, kl[2], kl[3]);
                MMA16816(sacc[2 * nb + 1], al, kh[2], kh[3]);
            }
        }

        if (k0 + 63 > row0g) {
            #pragma unroll
            for (int nt = 0; nt < 8; nt++) {
                int colg = k0 + nt * 8 + 2 * tig;
                if (colg > row0g)     sacc[nt][0] = -1e30f;
                if (colg + 1 > row0g) sacc[nt][1] = -1e30f;
                if (colg > row1g)     sacc[nt][2] = -1e30f;
                if (colg + 1 > row1g) sacc[nt][3] = -1e30f;
            }
        }

        // ---- online softmax ----
        float mx0 = rm0, mx1 = rm1;
        #pragma unroll
        for (int nt = 0; nt < 8; nt++) {
            mx0 = fmaxf(mx0, fmaxf(sacc[nt][0], sacc[nt][1]));
            mx1 = fmaxf(mx1, fmaxf(sacc[nt][2], sacc[nt][3]));
        }
        mx0 = fmaxf(mx0, __shfl_xor_sync(0xffffffff, mx0, 1));
        mx0 = fmaxf(mx0, __shfl_xor_sync(0xffffffff, mx0, 2));
        mx1 = fmaxf(mx1, __shfl_xor_sync(0xffffffff, mx1, 1));
        mx1 = fmaxf(mx1, __shfl_xor_sync(0xffffffff, mx1, 2));
        float sc0 = __expf(rm0 - mx0);
        float sc1 = __expf(rm1 - mx1);
        rm0 = mx0; rm1 = mx1;
        float sum0 = 0.0f, sum1 = 0.0f;
        #pragma unroll
        for (int nt = 0; nt < 8; nt++) {
            sacc[nt][0] = __expf(sacc[nt][0] - mx0);
            sacc[nt][1] = __expf(sacc[nt][1] - mx0);
            sacc[nt][2] = __expf(sacc[nt][2] - mx1);
            sacc[nt][3] = __expf(sacc[nt][3] - mx1);
            sum0 += sacc[nt][0] + sacc[nt][1];
            sum1 += sacc[nt][2] + sacc[nt][3];
        }
        sum0 += __shfl_xor_sync(0xffffffff, sum0, 1);
        sum0 += __shfl_xor_sync(0xffffffff, sum0, 2);
        sum1 += __shfl_xor_sync(0xffffffff, sum1, 1);
        sum1 += __shfl_xor_sync(0xffffffff, sum1, 2);
        rl0 = rl0 * sc0 + sum0;
        rl1 = rl1 * sc1 + sum1;
        #pragma unroll
        for (int nt = 0; nt < 16; nt++) {
            oacc[nt][0] *= sc0; oacc[nt][1] *= sc0;
            oacc[nt][2] *= sc1; oacc[nt][3] *= sc1;
        }

        // ---- O += P @ V ----
        #pragma unroll
        for (int j = 0; j < 4; j++) {
            unsigned ph[4], pl[4];
            split2(sacc[2 * j][0],     sacc[2 * j][1],     ph[0], pl[0]);
            split2(sacc[2 * j][2],     sacc[2 * j][3],     ph[1], pl[1]);
            split2(sacc[2 * j + 1][0], sacc[2 * j + 1][1], ph[2], pl[2]);
            split2(sacc[2 * j + 1][2], sacc[2 * j + 1][3], ph[3], pl[3]);
            #pragma unroll
            for (int nb = 0; nb < 8; nb++) {
                unsigned vh4[4], vl4[4];
                unsigned offv = ((j * 16 + (lane & 7) + ((lane >> 3) & 1) * 8) * LQ +
                                 nb * 16 + (lane >> 4) * 8) * 2;
                LDSM4T(vh4, vBH + offv);
                LDSM4T(vl4, vBL + offv);
                MMA16816(oacc[2 * nb + 0], ph, vh4[0], vh4[1]);
                MMA16816(oacc[2 * nb + 0], ph, vl4[0], vl4[1]);
                MMA16816(oacc[2 * nb + 0], pl, vh4[0], vh4[1]);
                MMA16816(oacc[2 * nb + 1], ph, vh4[2], vh4[3]);
                MMA16816(oacc[2 * nb + 1], ph, vl4[2], vl4[3]);
                MMA16816(oacc[2 * nb + 1], pl, vh4[2], vh4[3]);
            }
        }
    }

    // ---- finalize ----
    float li0 = 1.0f / rl0, li1 = 1.0f / rl1;
    size_t or0 = (size_t)(b * S + row0g) * (H * HD) + h * HD;
    size_t or1 = (size_t)(b * S + row1g) * (H * HD) + h * HD;
    #pragma unroll
    for (int nt = 0; nt < 16; nt++) {
        int col = nt * 8 + 2 * tig;
        unsigned hh, ll;
        split2(oacc[nt][0] * li0, oacc[nt][1] * li0, hh, ll);
        *(unsigned*)&g_ah[or0 + col] = hh;
        *(unsigned*)&g_al[or0 + col] = ll;
        split2(oacc[nt][2] * li1, oacc[nt][3] * li1, hh, ll);
        *(unsigned*)&g_ah[or1 + col] = hh;
        *(unsigned*)&g_al[or1 + col] = ll;
    }
}

// =============================== launch ======================================
extern "C" void kernel_launch(void* const* d_in, const int* in_sizes, int n_in,
                              void* d_out, int out_size) {
    const float* x  = (const float*)d_in[0];
    const float* Wq = (const float*)d_in[1];
    const float* bq = (const float*)d_in[2];
    const float* Wk = (const float*)d_in[3];
    const float* bk = (const float*)d_in[4];
    const float* Wv = (const float*)d_in[5];
    const float* bv = (const float*)d_in[6];
    const float* Wo = (const float*)d_in[7];
    const float* bo = (const float*)d_in[8];
    float* out = (float*)d_out;

    __nv_bfloat16 *xh, *xl, *wqh, *wql, *woh, *wol, *ah, *al;
    float *bqkv;
    cudaGetSymbolAddress((void**)&xh, g_xh);
    cudaGetSymbolAddress((void**)&xl, g_xl);
    cudaGetSymbolAddress((void**)&wqh, g_wqh);
    cudaGetSymbolAddress((void**)&wql, g_wql);
    cudaGetSymbolAddress((void**)&woh, g_woh);
    cudaGetSymbolAddress((void**)&wol, g_wol);
    cudaGetSymbolAddress((void**)&ah, g_ah);
    cudaGetSymbolAddress((void**)&al, g_al);
    cudaGetSymbolAddress((void**)&bqkv, g_bqkv);

    const int M = B * S;  // 8192

    // ---- pre-split conversions ----
    {
        int n4 = M * D / 4;
        convert_split<<<(n4 + 255) / 256, 256>>>(x, xh, xl, n4);
    }
    {
        int n4 = D * 2048 / 4;
        convert_pack<<<(n4 + 255) / 256, 256>>>(Wq, wqh, wql, 2048, 0, n4);
        n4 = D * 512 / 4;
        convert_pack<<<(n4 + 255) / 256, 256>>>(Wk, wqh, wql, 512, 2048, n4);
        convert_pack<<<(n4 + 255) / 256, 256>>>(Wv, wqh, wql, 512, 2560, n4);
        n4 = D * D / 4;
        convert_split<<<(n4 + 255) / 256, 256>>>(Wo, woh, wol, n4);
    }
    pack_bias<<<(NQKV + 255) / 256, 256>>>(bq, bk, bv, bqkv);

    size_t gsm = (size_t)2 * ST_EL * sizeof(__nv_bfloat16);  // 75776 B
    cudaFuncSetAttribute(gemm_qkv_fused, cudaFuncAttributeMaxDynamicSharedMemorySize, (int)gsm);
    cudaFuncSetAttribute(gemm_bias_bf16, cudaFuncAttributeMaxDynamicSharedMemorySize, (int)gsm);

    // ---- fused QKV projection + bias + RoPE + split ----
    gemm_qkv_fused<<<dim3(NQKV / 128, M / 128), 256, gsm>>>(xh, xl, wqh, wql, bqkv);

    // ---- flash attention (128-row q tiles) ----
    size_t smem = (size_t)(2 * 128 + 4 * 64) * LQ * sizeof(__nv_bfloat16);  // 139264 B
    cudaFuncSetAttribute(flash_tc, cudaFuncAttributeMaxDynamicSharedMemorySize, (int)smem);
    flash_tc<<<dim3(S / 128, H, B), 256, smem>>>();

    // ---- output projection ----
    gemm_bias_bf16<<<dim3(D / 128, M / 128), 256, gsm>>>(
        ah, al, woh, wol, bo, out, M, D, H * HD);
}

// round 8
// speedup vs baseline: 3.8647x; 1.0116x over previous
#include <cuda_runtime.h>
#include <cuda_bf16.h>
#include <math.h>

#define B 4
#define S 2048
#define D 2048
#define H 16
#define G 4
#define HD 128
#define NQKV 3072   // packed q(2048) | k(512) | v(512)

// ------------------------- scratch (device globals, no allocs) --------------
__device__ __nv_bfloat16 g_xh[(size_t)B * S * D];
__device__ __nv_bfloat16 g_xl[(size_t)B * S * D];
__device__ __nv_bfloat16 g_wqh[(size_t)D * NQKV];          // packed Wqkv hi [k][n]
__device__ __nv_bfloat16 g_wql[(size_t)D * NQKV];
__device__ __nv_bfloat16 g_woh[(size_t)H * HD * D];
__device__ __nv_bfloat16 g_wol[(size_t)H * HD * D];
__device__ __nv_bfloat16 g_ah[(size_t)B * S * H * HD];     // attn out hi
__device__ __nv_bfloat16 g_al[(size_t)B * S * H * HD];     // attn out lo
__device__ float         g_bqkv[NQKV];
// pre-split, roped operands for flash
__device__ __nv_bfloat16 g_qsh[(size_t)B * H * S * HD];    // q hi [b][h][s][hd]
__device__ __nv_bfloat16 g_qsl[(size_t)B * H * S * HD];
__device__ __nv_bfloat16 g_ksh[(size_t)B * G * S * HD];    // k hi [b][g][s][hd]
__device__ __nv_bfloat16 g_ksl[(size_t)B * G * S * HD];
__device__ __nv_bfloat16 g_vsh[(size_t)B * G * S * HD];
__device__ __nv_bfloat16 g_vsl[(size_t)B * G * S * HD];

// ============================ shared PTX helpers =============================
#define LDSM4(R, addr)                                                        \
    asm volatile("ldmatrix.sync.aligned.m8n8.x4.shared.b16 {%0,%1,%2,%3}, [%4];" \
                 : "=r"(R[0]), "=r"(R[1]), "=r"(R[2]), "=r"(R[3]) : "r"(addr))
#define LDSM4T(R, addr)                                                       \
    asm volatile("ldmatrix.sync.aligned.m8n8.x4.trans.shared.b16 {%0,%1,%2,%3}, [%4];" \
                 : "=r"(R[0]), "=r"(R[1]), "=r"(R[2]), "=r"(R[3]) : "r"(addr))
#define MMA16816(d, a, b0v, b1v)                                              \
    asm volatile("mma.sync.aligned.m16n8k16.row.col.f32.bf16.bf16.f32 "       \
                 "{%0,%1,%2,%3},{%4,%5,%6,%7},{%8,%9},{%0,%1,%2,%3};"         \
                 : "+f"(d[0]), "+f"(d[1]), "+f"(d[2]), "+f"(d[3])             \
                 : "r"(a[0]), "r"(a[1]), "r"(a[2]), "r"(a[3]),                \
                   "r"(b0v), "r"(b1v))
#define CP16(smaddr, gptr)                                                    \
    asm volatile("cp.async.cg.shared.global [%0], [%1], 16;" :: "r"(smaddr), "l"(gptr))
#define CP_COMMIT asm volatile("cp.async.commit_group;")

__device__ __forceinline__ void split2(float x, float y,
                                       unsigned& hi, unsigned& lo) {
    __nv_bfloat16 hx = __float2bfloat16_rn(x);
    __nv_bfloat16 hy = __float2bfloat16_rn(y);
    float rx = x - __bfloat162float(hx);
    float ry = y - __bfloat162float(hy);
    __nv_bfloat16 lx = __float2bfloat16_rn(rx);
    __nv_bfloat16 ly = __float2bfloat16_rn(ry);
    __nv_bfloat162 h2 = __nv_bfloat162(hx, hy);
    __nv_bfloat162 l2 = __nv_bfloat162(lx, ly);
    hi = *(unsigned*)&h2;
    lo = *(unsigned*)&l2;
}

// ========================= conversion / packing kernels ======================
__global__ void convert_split(const float* __restrict__ src,
                              __nv_bfloat16* __restrict__ hi,
                              __nv_bfloat16* __restrict__ lo, int n4) {
    int i = blockIdx.x * blockDim.x + threadIdx.x;
    if (i >= n4) return;
    float4 v = ((const float4*)src)[i];
    uint2 h, l;
    split2(v.x, v.y, h.x, l.x);
    split2(v.z, v.w, h.y, l.y);
    ((uint2*)hi)[i] = h;
    ((uint2*)lo)[i] = l;
}

__global__ void convert_pack(const float* __restrict__ src,
                             __nv_bfloat16* __restrict__ hi,
                             __nv_bfloat16* __restrict__ lo,
                             int srcN, int dstOff, int n4) {
    int i = blockIdx.x * blockDim.x + threadIdx.x;
    if (i >= n4) return;
    int rw = srcN >> 2;
    int r = i / rw, c = (i % rw) * 4;
    float4 v = *(const float4*)&src[(size_t)r * srcN + c];
    uint2 h, l;
    split2(v.x, v.y, h.x, l.x);
    split2(v.z, v.w, h.y, l.y);
    size_t d = (size_t)r * NQKV + dstOff + c;
    *(uint2*)&hi[d] = h;
    *(uint2*)&lo[d] = l;
}

__global__ void pack_bias(const float* __restrict__ bq, const float* __restrict__ bk,
                          const float* __restrict__ bv, float* __restrict__ dst) {
    int i = blockIdx.x * blockDim.x + threadIdx.x;
    if (i >= NQKV) return;
    dst[i] = (i < 2048) ? bq[i] : (i < 2560) ? bk[i - 2048] : bv[i - 2560];
}

// ======================== GEMM mainloop shared pieces ========================
#define LDA 40
#define LDB 136
#define ST_EL 18944   // per-stage smem elements: 2*128*40 + 2*32*136

struct GemmAcc { float a[4][4][4]; };

// 3-stage cp.async pipeline, ONE __syncthreads per 32-K iteration.
__device__ __forceinline__ void gemm_mainloop(
    const __nv_bfloat16* __restrict__ Ahg, const __nv_bfloat16* __restrict__ Alg,
    const __nv_bfloat16* __restrict__ Bhg, const __nv_bfloat16* __restrict__ Blg,
    int K, int N, int row0, int col0, unsigned smBase, GemmAcc& acc) {
    const int tid = threadIdx.x;
    const int lane = tid & 31;
    const int warp = tid >> 5;
    const int wm = (warp >> 2) * 64;
    const int wn = (warp & 3) * 32;
    const int NT = K / 32;

    auto issue = [&](int st, int k0) {
        unsigned sb = smBase + st * (ST_EL * 2);
        #pragma unroll
        for (int j = 0; j < 2; j++) {
            int c = tid + j * 256;
            int r = c >> 2, c8 = (c & 3) * 8;
            unsigned so = (unsigned)(r * LDA + c8) * 2;
            CP16(sb + so, &Ahg[(size_t)(row0 + r) * K + k0 + c8]);
            CP16(sb + 10240 + so, &Alg[(size_t)(row0 + r) * K + k0 + c8]);
        }
        #pragma unroll
        for (int j = 0; j < 2; j++) {
            int c = tid + j * 256;
            int r = c >> 4, c8 = (c & 15) * 8;
            unsigned so = (unsigned)(r * LDB + c8) * 2;
            CP16(sb + 20480 + so, &Bhg[(size_t)(k0 + r) * N + col0 + c8]);
            CP16(sb + 29184 + so, &Blg[(size_t)(k0 + r) * N + col0 + c8]);
        }
    };

    issue(0, 0);
    CP_COMMIT;
    issue(1, 32);
    CP_COMMIT;

    for (int it = 0; it < NT; it++) {
        if (it == NT - 1) {
            asm volatile("cp.async.wait_group 0;");
        } else {
            asm volatile("cp.async.wait_group 1;");
        }
        __syncthreads();
        if (it + 2 < NT) {
            issue((it + 2) % 3, (it + 2) * 32);
            CP_COMMIT;
        }

        unsigned sb = smBase + (it % 3) * (ST_EL * 2);
        const unsigned aBaseH = sb, aBaseL = sb + 10240;
        const unsigned bBaseH = sb + 20480, bBaseL = sb + 29184;

        #pragma unroll
        for (int ks = 0; ks < 2; ks++) {
            unsigned ah[4][4], al[4][4];
            #pragma unroll
            for (int im = 0; im < 4; im++) {
                unsigned off =
                    ((wm + im * 16 + (lane & 15)) * LDA + ks * 16 + (lane >> 4) * 8) * 2;
                LDSM4(ah[im], aBaseH + off);
                LDSM4(al[im], aBaseL + off);
            }
            int krow = ks * 16 + (lane & 7) + ((lane >> 3) & 1) * 8;
            #pragma unroll
            for (int pr = 0; pr < 2; pr++) {
                unsigned bh[4], bl[4];
                unsigned off = (krow * LDB + wn + pr * 16 + (lane >> 4) * 8) * 2;
                LDSM4T(bh, bBaseH + off);
                LDSM4T(bl, bBaseL + off);
                #pragma unroll
                for (int im = 0; im < 4; im++) {
                    MMA16816(acc.a[im][pr * 2 + 0], ah[im], bh[0], bh[1]);
                    MMA16816(acc.a[im][pr * 2 + 0], ah[im], bl[0], bl[1]);
                    MMA16816(acc.a[im][pr * 2 + 0], al[im], bh[0], bh[1]);
                    MMA16816(acc.a[im][pr * 2 + 1], ah[im], bh[2], bh[3]);
                    MMA16816(acc.a[im][pr * 2 + 1], ah[im], bl[2], bl[3]);
                    MMA16816(acc.a[im][pr * 2 + 1], al[im], bh[2], bh[3]);
                }
            }
        }
    }
    __syncthreads();   // mainloop smem dead; safe for epilogue reuse
}

// ============= QKV GEMM with fused bias + RoPE + hi/lo split epilogue ========
#define STF 132   // fp32 smem stride for epilogue tile

__global__ __launch_bounds__(256) void gemm_qkv_fused(
    const __nv_bfloat16* __restrict__ Ahg, const __nv_bfloat16* __restrict__ Alg,
    const __nv_bfloat16* __restrict__ Bhg, const __nv_bfloat16* __restrict__ Blg,
    const float* __restrict__ bias) {
    extern __shared__ __nv_bfloat16 smem[];
    const unsigned smBase = (unsigned)__cvta_generic_to_shared(smem);

    const int tid = threadIdx.x;
    const int lane = tid & 31;
    const int warp = tid >> 5;
    const int wm = (warp >> 2) * 64;
    const int wn = (warp & 3) * 32;
    const int row0 = blockIdx.y * 128;
    const int col0 = blockIdx.x * 128;

    GemmAcc acc = {};
    gemm_mainloop(Ahg, Alg, Bhg, Blg, D, NQKV, row0, col0, smBase, acc);

    // ---- stage fp32 tile (with bias) in smem ----
    float* st = (float*)smem;
    const int qr = lane >> 2, qc = lane & 3;
    #pragma unroll
    for (int im = 0; im < 4; im++) {
        #pragma unroll
        for (int jn = 0; jn < 4; jn++) {
            int rr = wm + im * 16 + qr;
            int cc = wn + jn * 8 + 2 * qc;
            float b0v = bias[col0 + cc], b1v = bias[col0 + cc + 1];
            st[rr * STF + cc]           = acc.a[im][jn][0] + b0v;
            st[rr * STF + cc + 1]       = acc.a[im][jn][1] + b1v;
            st[(rr + 8) * STF + cc]     = acc.a[im][jn][2] + b0v;
            st[(rr + 8) * STF + cc + 1] = acc.a[im][jn][3] + b1v;
        }
    }
    __syncthreads();

    const int tile = col0 >> 7;      // head tile: 0-15 q, 16-19 k, 20-23 v
    const int bb = row0 >> 11;
    const float scale = 0.08838834764831845f;
    const float L2E = 0.20762050593046f;   // log2(10000)/64 -> used as ln-base exp arg

    if (tile < 20) {   // q or k: rope + split
        bool isq = tile < 16;
        int hh = isq ? tile : tile - 16;
        int nh = isq ? H : G;
        __nv_bfloat16* dh = isq ? g_qsh : g_ksh;
        __nv_bfloat16* dl = isq ? g_qsl : g_ksl;
        float sc = isq ? scale : 1.0f;
        #pragma unroll 4
        for (int t = 0; t < 16; t++) {
            int idx = tid + t * 256;
            int r = idx >> 5;
            int i2 = (idx & 31) * 2;
            int s = (row0 + r) & (S - 1);
            float a0 = st[r * STF + i2],      a1 = st[r * STF + i2 + 1];
            float c0 = st[r * STF + i2 + 64], c1 = st[r * STF + i2 + 65];
            float f0 = exp2f(-(float)i2 * L2E);
            float f1 = exp2f(-(float)(i2 + 1) * L2E);
            float cs0 = cosf(s * f0), sn0 = sinf(s * f0);
            float cs1 = cosf(s * f1), sn1 = sinf(s * f1);
            float o10 = (a0 * cs0 - c0 * sn0) * sc;
            float o11 = (a1 * cs1 - c1 * sn1) * sc;
            float o20 = (c0 * cs0 + a0 * sn0) * sc;
            float o21 = (c1 * cs1 + a1 * sn1) * sc;
            unsigned h1, l1, h2, l2;
            split2(o10, o11, h1, l1);
            split2(o20, o21, h2, l2);
            size_t dst = ((size_t)(bb * nh + hh) * S + s) * HD + i2;
            *(unsigned*)&dh[dst] = h1;
            *(unsigned*)&dl[dst] = l1;
            *(unsigned*)&dh[dst + 64] = h2;
            *(unsigned*)&dl[dst + 64] = l2;
        }
    } else {           // v: split only
        int gg = tile - 20;
        #pragma unroll 4
        for (int t = 0; t < 32; t++) {
            int idx = tid + t * 256;
            int r = idx >> 6;
            int i2 = (idx & 63) * 2;
            int s = (row0 + r) & (S - 1);
            float v0 = st[r * STF + i2], v1 = st[r * STF + i2 + 1];
            unsigned h, l;
            split2(v0, v1, h, l);
            size_t dst = ((size_t)(bb * G + gg) * S + s) * HD + i2;
            *(unsigned*)&g_vsh[dst] = h;
            *(unsigned*)&g_vsl[dst] = l;
        }
    }
}

// ================ plain GEMM + bias (for output projection) ==================
__global__ __launch_bounds__(256) void gemm_bias_bf16(
    const __nv_bfloat16* __restrict__ Ahg, const __nv_bfloat16* __restrict__ Alg,
    const __nv_bfloat16* __restrict__ Bhg, const __nv_bfloat16* __restrict__ Blg,
    const float* __restrict__ bias, float* __restrict__ C,
    int M, int N, int K) {
    extern __shared__ __nv_bfloat16 smem[];
    const unsigned smBase = (unsigned)__cvta_generic_to_shared(smem);

    const int tid = threadIdx.x;
    const int lane = tid & 31;
    const int warp = tid >> 5;
    const int wm = (warp >> 2) * 64;
    const int wn = (warp & 3) * 32;
    const int row0 = blockIdx.y * 128;
    const int col0 = blockIdx.x * 128;

    GemmAcc acc = {};
    gemm_mainloop(Ahg, Alg, Bhg, Blg, K, N, row0, col0, smBase, acc);

    const int qr = lane >> 2, qc = lane & 3;
    #pragma unroll
    for (int im = 0; im < 4; im++) {
        #pragma unroll
        for (int jn = 0; jn < 4; jn++) {
            int row = row0 + wm + im * 16 + qr;
            int col = col0 + wn + jn * 8 + 2 * qc;
            float b0v = bias[col], b1v = bias[col + 1];
            float2 o0 = make_float2(acc.a[im][jn][0] + b0v, acc.a[im][jn][1] + b1v);
            float2 o1 = make_float2(acc.a[im][jn][2] + b0v, acc.a[im][jn][3] + b1v);
            *(float2*)&C[(size_t)row * N + col] = o0;
            *(float2*)&C[(size_t)(row + 8) * N + col] = o1;
        }
    }
}

// ====== Flash attention: 128-row q tiles, 8 warps, HMMA 3xBF16 split =========
#define LQ 136

__global__ __launch_bounds__(256) void flash_tc() {
    extern __shared__ __nv_bfloat16 smb[];
    __nv_bfloat16* Qh = smb;
    __nv_bfloat16* Ql = Qh + 128 * LQ;
    __nv_bfloat16* Kh = Ql + 128 * LQ;
    __nv_bfloat16* Kl = Kh + 64 * LQ;
    __nv_bfloat16* Vh = Kl + 64 * LQ;
    __nv_bfloat16* Vl = Vh + 64 * LQ;

    const int tid  = threadIdx.x;
    const int lane = tid & 31;
    const int warp = tid >> 5;              // 0..7
    const int qtile = gridDim.x - 1 - blockIdx.x;  // heavy tiles first
    const int h  = blockIdx.y;
    const int b  = blockIdx.z;
    const int g  = h / (H / G);
    const int q0 = qtile * 128;
    const int wm = warp * 16;

    const unsigned qBH = (unsigned)__cvta_generic_to_shared(Qh);
    const unsigned qBL = (unsigned)__cvta_generic_to_shared(Ql);
    const unsigned kBH = (unsigned)__cvta_generic_to_shared(Kh);
    const unsigned kBL = (unsigned)__cvta_generic_to_shared(Kl);
    const unsigned vBH = (unsigned)__cvta_generic_to_shared(Vh);
    const unsigned vBL = (unsigned)__cvta_generic_to_shared(Vl);

    // ---- load Q tile (pre-split, pre-scaled, roped) ----
    #pragma unroll
    for (int it = 0; it < 8; it++) {
        int i4 = tid + it * 256;           // 0..2047
        int r  = i4 >> 4;                  // 0..127
        int c8 = (i4 & 15) * 8;
        size_t gi = ((size_t)(b * H + h) * S + q0 + r) * HD + c8;
        *(uint4*)&Qh[r * LQ + c8] = *(const uint4*)&g_qsh[gi];
        *(uint4*)&Ql[r * LQ + c8] = *(const uint4*)&g_qsl[gi];
    }

    const int gid = lane >> 2, tig = lane & 3;
    const int row0g = q0 + wm + gid;
    const int row1g = row0g + 8;
    const int wmaxrow = q0 + wm + 15;

    float rm0 = -1e30f, rm1 = -1e30f, rl0 = 0.0f, rl1 = 0.0f;
    float oacc[16][4] = {};

    const int NKT = 2 * qtile + 2;
    for (int kt = 0; kt < NKT; kt++) {
        const int k0 = kt * 64;
        __syncthreads();
        // ---- load K,V tiles ----
        #pragma unroll
        for (int it = 0; it < 4; it++) {
            int i4 = tid + it * 256;       // 0..1023
            int r  = i4 >> 4;              // 0..63
            int c8 = (i4 & 15) * 8;
            size_t gi = ((size_t)(b * G + g) * S + k0 + r) * HD + c8;
            unsigned so = r * LQ + c8;
            *(uint4*)&Kh[so] = *(const uint4*)&g_ksh[gi];
            *(uint4*)&Kl[so] = *(const uint4*)&g_ksl[gi];
            *(uint4*)&Vh[so] = *(const uint4*)&g_vsh[gi];
            *(uint4*)&Vl[so] = *(const uint4*)&g_vsl[gi];
        }
        __syncthreads();

        if (k0 > wmaxrow) continue;        // whole warp above diagonal

        // ---- S = Q @ K^T ----
        float sacc[8][4] = {};
        #pragma unroll
        for (int ks = 0; ks < 8; ks++) {
            unsigned ah[4], al[4];
            unsigned offa = ((wm + (lane & 15)) * LQ + ks * 16 + (lane >> 4) * 8) * 2;
            LDSM4(ah, qBH + offa);
            LDSM4(al, qBL + offa);
            #pragma unroll
            for (int nb = 0; nb < 4; nb++) {
                unsigned kh[4], kl[4];
                unsigned offb = ((nb * 16 + (lane >> 4) * 8 + (lane & 7)) * LQ +
                                 ks * 16 + ((lane >> 3) & 1) * 8) * 2;
                LDSM4(kh, kBH + offb);
                LDSM4(kl, kBL + offb);
                MMA16816(sacc[2 * nb + 0], ah, kh[0], kh[1]);
                MMA16816(sacc[2 * nb + 0], ah, kl[0], kl[1]);
                MMA16816(sacc[2 * nb + 0], al, kh[0], kh[1]);
                MMA16816(sacc[2 * nb + 1], ah, kh[2], kh[3]);
                MMA16816(sacc[2 * nb + 1], ah, kl[2], kl[3]);
                MMA16816(sacc[2 * nb + 1], al, kh[2], kh[3]);
            }
        }

        if (k0 + 63 > row0g) {
            #pragma unroll
            for (int nt = 0; nt < 8; nt++) {
                int colg = k0 + nt * 8 + 2 * tig;
                if (colg > row0g)     sacc[nt][0] = -1e30f;
                if (colg + 1 > row0g) sacc[nt][1] = -1e30f;
                if (colg > row1g)     sacc[nt][2] = -1e30f;
                if (colg + 1 > row1g) sacc[nt][3] = -1e30f;
            }
        }

        // ---- online softmax ----
        float mx0 = rm0, mx1 = rm1;
        #pragma unroll
        for (int nt = 0; nt < 8; nt++) {
            mx0 = fmaxf(mx0, fmaxf(sacc[nt][0], sacc[nt][1]));
            mx1 = fmaxf(mx1, fmaxf(sacc[nt][2], sacc[nt][3]));
        }
        mx0 = fmaxf(mx0, __shfl_xor_sync(0xffffffff, mx0, 1));
        mx0 = fmaxf(mx0, __shfl_xor_sync(0xffffffff, mx0, 2));
        mx1 = fmaxf(mx1, __shfl_xor_sync(0xffffffff, mx1, 1));
        mx1 = fmaxf(mx1, __shfl_xor_sync(0xffffffff, mx1, 2));
        float sc0 = __expf(rm0 - mx0);
        float sc1 = __expf(rm1 - mx1);
        rm0 = mx0; rm1 = mx1;
        float sum0 = 0.0f, sum1 = 0.0f;
        #pragma unroll
        for (int nt = 0; nt < 8; nt++) {
            sacc[nt][0] = __expf(sacc[nt][0] - mx0);
            sacc[nt][1] = __expf(sacc[nt][1] - mx0);
            sacc[nt][2] = __expf(sacc[nt][2] - mx1);
            sacc[nt][3] = __expf(sacc[nt][3] - mx1);
            sum0 += sacc[nt][0] + sacc[nt][1];
            sum1 += sacc[nt][2] + sacc[nt][3];
        }
        sum0 += __shfl_xor_sync(0xffffffff, sum0, 1);
        sum0 += __shfl_xor_sync(0xffffffff, sum0, 2);
        sum1 += __shfl_xor_sync(0xffffffff, sum1, 1);
        sum1 += __shfl_xor_sync(0xffffffff, sum1, 2);
        rl0 = rl0 * sc0 + sum0;
        rl1 = rl1 * sc1 + sum1;
        #pragma unroll
        for (int nt = 0; nt < 16; nt++) {
            oacc[nt][0] *= sc0; oacc[nt][1] *= sc0;
            oacc[nt][2] *= sc1; oacc[nt][3] *= sc1;
        }

        // ---- O += P @ V ----
        #pragma unroll
        for (int j = 0; j < 4; j++) {
            unsigned ph[4], pl[4];
            split2(sacc[2 * j][0],     sacc[2 * j][1],     ph[0], pl[0]);
            split2(sacc[2 * j][2],     sacc[2 * j][3],     ph[1], pl[1]);
            split2(sacc[2 * j + 1][0], sacc[2 * j + 1][1], ph[2], pl[2]);
            split2(sacc[2 * j + 1][2], sacc[2 * j + 1][3], ph[3], pl[3]);
            #pragma unroll
            for (int nb = 0; nb < 8; nb++) {
                unsigned vh4[4], vl4[4];
                unsigned offv = ((j * 16 + (lane & 7) + ((lane >> 3) & 1) * 8) * LQ +
                                 nb * 16 + (lane >> 4) * 8) * 2;
                LDSM4T(vh4, vBH + offv);
                LDSM4T(vl4, vBL + offv);
                MMA16816(oacc[2 * nb + 0], ph, vh4[0], vh4[1]);
                MMA16816(oacc[2 * nb + 0], ph, vl4[0], vl4[1]);
                MMA16816(oacc[2 * nb + 0], pl, vh4[0], vh4[1]);
                MMA16816(oacc[2 * nb + 1], ph, vh4[2], vh4[3]);
                MMA16816(oacc[2 * nb + 1], ph, vl4[2], vl4[3]);
                MMA16816(oacc[2 * nb + 1], pl, vh4[2], vh4[3]);
            }
        }
    }

    // ---- finalize ----
    float li0 = 1.0f / rl0, li1 = 1.0f / rl1;
    size_t or0 = (size_t)(b * S + row0g) * (H * HD) + h * HD;
    size_t or1 = (size_t)(b * S + row1g) * (H * HD) + h * HD;
    #pragma unroll
    for (int nt = 0; nt < 16; nt++) {
        int col = nt * 8 + 2 * tig;
        unsigned hh, ll;
        split2(oacc[nt][0] * li0, oacc[nt][1] * li0, hh, ll);
        *(unsigned*)&g_ah[or0 + col] = hh;
        *(unsigned*)&g_al[or0 + col] = ll;
        split2(oacc[nt][2] * li1, oacc[nt][3] * li1, hh, ll);
        *(unsigned*)&g_ah[or1 + col] = hh;
        *(unsigned*)&g_al[or1 + col] = ll;
    }
}

// =============================== launch ======================================
extern "C" void kernel_launch(void* const* d_in, const int* in_sizes, int n_in,
                              void* d_out, int out_size) {
    const float* x  = (const float*)d_in[0];
    const float* Wq = (const float*)d_in[1];
    const float* bq = (const float*)d_in[2];
    const float* Wk = (const float*)d_in[3];
    const float* bk = (const float*)d_in[4];
    const float* Wv = (const float*)d_in[5];
    const float* bv = (const float*)d_in[6];
    const float* Wo = (const float*)d_in[7];
    const float* bo = (const float*)d_in[8];
    float* out = (float*)d_out;

    __nv_bfloat16 *xh, *xl, *wqh, *wql, *woh, *wol, *ah, *al;
    float *bqkv;
    cudaGetSymbolAddress((void**)&xh, g_xh);
    cudaGetSymbolAddress((void**)&xl, g_xl);
    cudaGetSymbolAddress((void**)&wqh, g_wqh);
    cudaGetSymbolAddress((void**)&wql, g_wql);
    cudaGetSymbolAddress((void**)&woh, g_woh);
    cudaGetSymbolAddress((void**)&wol, g_wol);
    cudaGetSymbolAddress((void**)&ah, g_ah);
    cudaGetSymbolAddress((void**)&al, g_al);
    cudaGetSymbolAddress((void**)&bqkv, g_bqkv);

    const int M = B * S;  // 8192

    // ---- pre-split conversions ----
    {
        int n4 = M * D / 4;
        convert_split<<<(n4 + 255) / 256, 256>>>(x, xh, xl, n4);
    }
    {
        int n4 = D * 2048 / 4;
        convert_pack<<<(n4 + 255) / 256, 256>>>(Wq, wqh, wql, 2048, 0, n4);
        n4 = D * 512 / 4;
        convert_pack<<<(n4 + 255) / 256, 256>>>(Wk, wqh, wql, 512, 2048, n4);
        convert_pack<<<(n4 + 255) / 256, 256>>>(Wv, wqh, wql, 512, 2560, n4);
        n4 = D * D / 4;
        convert_split<<<(n4 + 255) / 256, 256>>>(Wo, woh, wol, n4);
    }
    pack_bias<<<(NQKV + 255) / 256, 256>>>(bq, bk, bv, bqkv);

    size_t gsm = (size_t)3 * ST_EL * sizeof(__nv_bfloat16);  // 113664 B
    cudaFuncSetAttribute(gemm_qkv_fused, cudaFuncAttributeMaxDynamicSharedMemorySize, (int)gsm);
    cudaFuncSetAttribute(gemm_bias_bf16, cudaFuncAttributeMaxDynamicSharedMemorySize, (int)gsm);

    // ---- fused QKV projection + bias + RoPE + split ----
    gemm_qkv_fused<<<dim3(NQKV / 128, M / 128), 256, gsm>>>(xh, xl, wqh, wql, bqkv);

    // ---- flash attention (128-row q tiles) ----
    size_t smem = (size_t)(2 * 128 + 4 * 64) * LQ * sizeof(__nv_bfloat16);  // 139264 B
    cudaFuncSetAttribute(flash_tc, cudaFuncAttributeMaxDynamicSharedMemorySize, (int)smem);
    flash_tc<<<dim3(S / 128, H, B), 256, smem>>>();

    // ---- output projection ----
    gemm_bias_bf16<<<dim3(D / 128, M / 128), 256, gsm>>>(
        ah, al, woh, wol, bo, out, M, D, H * HD);
}

// round 9
// speedup vs baseline: 4.4512x; 1.1517x over previous
#include <cuda_runtime.h>
#include <cuda_bf16.h>
#include <cuda_fp16.h>
#include <math.h>

#define B 4
#define S 2048
#define D 2048
#define H 16
#define G 4
#define HD 128
#define NQKV 3072   // packed q(2048) | k(512) | v(512)

// ------------------------- scratch (device globals, no allocs) --------------
__device__ __nv_bfloat16 g_xh[(size_t)B * S * D];
__device__ __nv_bfloat16 g_xl[(size_t)B * S * D];
__device__ __nv_bfloat16 g_wqh[(size_t)D * NQKV];          // packed Wqkv hi [k][n]
__device__ __nv_bfloat16 g_wql[(size_t)D * NQKV];
__device__ __half        g_woh[(size_t)H * HD * D];        // Wo*32 hi (fp16)
__device__ __half        g_wol[(size_t)H * HD * D];        // Wo*32 lo (fp16)
__device__ __half        g_ah[(size_t)B * S * H * HD];     // attn out (fp16 single)
__device__ float         g_bqkv[NQKV];
// pre-split, roped operands for flash
__device__ __nv_bfloat16 g_qsh[(size_t)B * H * S * HD];    // q hi [b][h][s][hd]
__device__ __nv_bfloat16 g_qsl[(size_t)B * H * S * HD];
__device__ __nv_bfloat16 g_ksh[(size_t)B * G * S * HD];    // k hi [b][g][s][hd]
__device__ __nv_bfloat16 g_ksl[(size_t)B * G * S * HD];
__device__ __half        g_vsh[(size_t)B * G * S * HD];    // v hi (fp16)
__device__ __half        g_vsl[(size_t)B * G * S * HD];    // v lo (fp16)

// ============================ shared PTX helpers =============================
#define LDSM4(R, addr)                                                        \
    asm volatile("ldmatrix.sync.aligned.m8n8.x4.shared.b16 {%0,%1,%2,%3}, [%4];" \
                 : "=r"(R[0]), "=r"(R[1]), "=r"(R[2]), "=r"(R[3]) : "r"(addr))
#define LDSM4T(R, addr)                                                       \
    asm volatile("ldmatrix.sync.aligned.m8n8.x4.trans.shared.b16 {%0,%1,%2,%3}, [%4];" \
                 : "=r"(R[0]), "=r"(R[1]), "=r"(R[2]), "=r"(R[3]) : "r"(addr))
#define MMA16816(d, a, b0v, b1v)                                              \
    asm volatile("mma.sync.aligned.m16n8k16.row.col.f32.bf16.bf16.f32 "       \
                 "{%0,%1,%2,%3},{%4,%5,%6,%7},{%8,%9},{%0,%1,%2,%3};"         \
                 : "+f"(d[0]), "+f"(d[1]), "+f"(d[2]), "+f"(d[3])             \
                 : "r"(a[0]), "r"(a[1]), "r"(a[2]), "r"(a[3]),                \
                   "r"(b0v), "r"(b1v))
#define MMA16816H(d, a, b0v, b1v)                                             \
    asm volatile("mma.sync.aligned.m16n8k16.row.col.f32.f16.f16.f32 "         \
                 "{%0,%1,%2,%3},{%4,%5,%6,%7},{%8,%9},{%0,%1,%2,%3};"         \
                 : "+f"(d[0]), "+f"(d[1]), "+f"(d[2]), "+f"(d[3])             \
                 : "r"(a[0]), "r"(a[1]), "r"(a[2]), "r"(a[3]),                \
                   "r"(b0v), "r"(b1v))
#define CP16(smaddr, gptr)                                                    \
    asm volatile("cp.async.cg.shared.global [%0], [%1], 16;" :: "r"(smaddr), "l"(gptr))
#define CP_COMMIT asm volatile("cp.async.commit_group;")

__device__ __forceinline__ void split2(float x, float y,
                                       unsigned& hi, unsigned& lo) {
    __nv_bfloat16 hx = __float2bfloat16_rn(x);
    __nv_bfloat16 hy = __float2bfloat16_rn(y);
    float rx = x - __bfloat162float(hx);
    float ry = y - __bfloat162float(hy);
    __nv_bfloat16 lx = __float2bfloat16_rn(rx);
    __nv_bfloat16 ly = __float2bfloat16_rn(ry);
    __nv_bfloat162 h2 = __nv_bfloat162(hx, hy);
    __nv_bfloat162 l2 = __nv_bfloat162(lx, ly);
    hi = *(unsigned*)&h2;
    lo = *(unsigned*)&l2;
}

__device__ __forceinline__ void split2h(float x, float y,
                                        unsigned& hi, unsigned& lo) {
    __half hx = __float2half_rn(x);
    __half hy = __float2half_rn(y);
    float rx = x - __half2float(hx);
    float ry = y - __half2float(hy);
    __half2 h2 = __halves2half2(hx, hy);
    __half2 l2 = __halves2half2(__float2half_rn(rx), __float2half_rn(ry));
    hi = *(unsigned*)&h2;
    lo = *(unsigned*)&l2;
}

__device__ __forceinline__ unsigned packh2(float x, float y) {
    __half2 h = __floats2half2_rn(x, y);
    return *(unsigned*)&h;
}

// ========================= conversion / packing kernels ======================
__global__ void convert_split(const float* __restrict__ src,
                              __nv_bfloat16* __restrict__ hi,
                              __nv_bfloat16* __restrict__ lo, int n4) {
    int i = blockIdx.x * blockDim.x + threadIdx.x;
    if (i >= n4) return;
    float4 v = ((const float4*)src)[i];
    uint2 h, l;
    split2(v.x, v.y, h.x, l.x);
    split2(v.z, v.w, h.y, l.y);
    ((uint2*)hi)[i] = h;
    ((uint2*)lo)[i] = l;
}

// Wo * 32 -> fp16 hi/lo
__global__ void convert_split_h32(const float* __restrict__ src,
                                  __half* __restrict__ hi,
                                  __half* __restrict__ lo, int n4) {
    int i = blockIdx.x * blockDim.x + threadIdx.x;
    if (i >= n4) return;
    float4 v = ((const float4*)src)[i];
    uint2 h, l;
    split2h(v.x * 32.0f, v.y * 32.0f, h.x, l.x);
    split2h(v.z * 32.0f, v.w * 32.0f, h.y, l.y);
    ((uint2*)hi)[i] = h;
    ((uint2*)lo)[i] = l;
}

__global__ void convert_pack(const float* __restrict__ src,
                             __nv_bfloat16* __restrict__ hi,
                             __nv_bfloat16* __restrict__ lo,
                             int srcN, int dstOff, int n4) {
    int i = blockIdx.x * blockDim.x + threadIdx.x;
    if (i >= n4) return;
    int rw = srcN >> 2;
    int r = i / rw, c = (i % rw) * 4;
    float4 v = *(const float4*)&src[(size_t)r * srcN + c];
    uint2 h, l;
    split2(v.x, v.y, h.x, l.x);
    split2(v.z, v.w, h.y, l.y);
    size_t d = (size_t)r * NQKV + dstOff + c;
    *(uint2*)&hi[d] = h;
    *(uint2*)&lo[d] = l;
}

__global__ void pack_bias(const float* __restrict__ bq, const float* __restrict__ bk,
                          const float* __restrict__ bv, float* __restrict__ dst) {
    int i = blockIdx.x * blockDim.x + threadIdx.x;
    if (i >= NQKV) return;
    dst[i] = (i < 2048) ? bq[i] : (i < 2560) ? bk[i - 2048] : bv[i - 2560];
}

// ======================== bf16 3-term GEMM mainloop ==========================
#define LDA 40
#define LDB 136
#define ST_EL 18944   // per-stage smem elements: 2*128*40 + 2*32*136

struct GemmAcc { float a[4][4][4]; };

// 3-stage cp.async pipeline, ONE __syncthreads per 32-K iteration.
__device__ __forceinline__ void gemm_mainloop(
    const __nv_bfloat16* __restrict__ Ahg, const __nv_bfloat16* __restrict__ Alg,
    const __nv_bfloat16* __restrict__ Bhg, const __nv_bfloat16* __restrict__ Blg,
    int K, int N, int row0, int col0, unsigned smBase, GemmAcc& acc) {
    const int tid = threadIdx.x;
    const int lane = tid & 31;
    const int warp = tid >> 5;
    const int wm = (warp >> 2) * 64;
    const int wn = (warp & 3) * 32;
    const int NT = K / 32;

    auto issue = [&](int st, int k0) {
        unsigned sb = smBase + st * (ST_EL * 2);
        #pragma unroll
        for (int j = 0; j < 2; j++) {
            int c = tid + j * 256;
            int r = c >> 2, c8 = (c & 3) * 8;
            unsigned so = (unsigned)(r * LDA + c8) * 2;
            CP16(sb + so, &Ahg[(size_t)(row0 + r) * K + k0 + c8]);
            CP16(sb + 10240 + so, &Alg[(size_t)(row0 + r) * K + k0 + c8]);
        }
        #pragma unroll
        for (int j = 0; j < 2; j++) {
            int c = tid + j * 256;
            int r = c >> 4, c8 = (c & 15) * 8;
            unsigned so = (unsigned)(r * LDB + c8) * 2;
            CP16(sb + 20480 + so, &Bhg[(size_t)(k0 + r) * N + col0 + c8]);
            CP16(sb + 29184 + so, &Blg[(size_t)(k0 + r) * N + col0 + c8]);
        }
    };

    issue(0, 0);
    CP_COMMIT;
    issue(1, 32);
    CP_COMMIT;

    for (int it = 0; it < NT; it++) {
        if (it == NT - 1) {
            asm volatile("cp.async.wait_group 0;");
        } else {
            asm volatile("cp.async.wait_group 1;");
        }
        __syncthreads();
        if (it + 2 < NT) {
            issue((it + 2) % 3, (it + 2) * 32);
            CP_COMMIT;
        }

        unsigned sb = smBase + (it % 3) * (ST_EL * 2);
        const unsigned aBaseH = sb, aBaseL = sb + 10240;
        const unsigned bBaseH = sb + 20480, bBaseL = sb + 29184;

        #pragma unroll
        for (int ks = 0; ks < 2; ks++) {
            unsigned ah[4][4], al[4][4];
            #pragma unroll
            for (int im = 0; im < 4; im++) {
                unsigned off =
                    ((wm + im * 16 + (lane & 15)) * LDA + ks * 16 + (lane >> 4) * 8) * 2;
                LDSM4(ah[im], aBaseH + off);
                LDSM4(al[im], aBaseL + off);
            }
            int krow = ks * 16 + (lane & 7) + ((lane >> 3) & 1) * 8;
            #pragma unroll
            for (int pr = 0; pr < 2; pr++) {
                unsigned bh[4], bl[4];
                unsigned off = (krow * LDB + wn + pr * 16 + (lane >> 4) * 8) * 2;
                LDSM4T(bh, bBaseH + off);
                LDSM4T(bl, bBaseL + off);
                #pragma unroll
                for (int im = 0; im < 4; im++) {
                    MMA16816(acc.a[im][pr * 2 + 0], ah[im], bh[0], bh[1]);
                    MMA16816(acc.a[im][pr * 2 + 0], ah[im], bl[0], bl[1]);
                    MMA16816(acc.a[im][pr * 2 + 0], al[im], bh[0], bh[1]);
                    MMA16816(acc.a[im][pr * 2 + 1], ah[im], bh[2], bh[3]);
                    MMA16816(acc.a[im][pr * 2 + 1], ah[im], bl[2], bl[3]);
                    MMA16816(acc.a[im][pr * 2 + 1], al[im], bh[2], bh[3]);
                }
            }
        }
    }
    __syncthreads();   // mainloop smem dead; safe for epilogue reuse
}

// ============= QKV GEMM with fused bias + RoPE + hi/lo split epilogue ========
#define STF 132   // fp32 smem stride for epilogue tile

__global__ __launch_bounds__(256) void gemm_qkv_fused(
    const __nv_bfloat16* __restrict__ Ahg, const __nv_bfloat16* __restrict__ Alg,
    const __nv_bfloat16* __restrict__ Bhg, const __nv_bfloat16* __restrict__ Blg,
    const float* __restrict__ bias) {
    extern __shared__ __nv_bfloat16 smem[];
    const unsigned smBase = (unsigned)__cvta_generic_to_shared(smem);

    const int tid = threadIdx.x;
    const int lane = tid & 31;
    const int warp = tid >> 5;
    const int wm = (warp >> 2) * 64;
    const int wn = (warp & 3) * 32;
    const int row0 = blockIdx.y * 128;
    const int col0 = blockIdx.x * 128;

    GemmAcc acc = {};
    gemm_mainloop(Ahg, Alg, Bhg, Blg, D, NQKV, row0, col0, smBase, acc);

    // ---- stage fp32 tile (with bias) in smem ----
    float* st = (float*)smem;
    const int qr = lane >> 2, qc = lane & 3;
    #pragma unroll
    for (int im = 0; im < 4; im++) {
        #pragma unroll
        for (int jn = 0; jn < 4; jn++) {
            int rr = wm + im * 16 + qr;
            int cc = wn + jn * 8 + 2 * qc;
            float b0v = bias[col0 + cc], b1v = bias[col0 + cc + 1];
            st[rr * STF + cc]           = acc.a[im][jn][0] + b0v;
            st[rr * STF + cc + 1]       = acc.a[im][jn][1] + b1v;
            st[(rr + 8) * STF + cc]     = acc.a[im][jn][2] + b0v;
            st[(rr + 8) * STF + cc + 1] = acc.a[im][jn][3] + b1v;
        }
    }
    __syncthreads();

    const int tile = col0 >> 7;      // head tile: 0-15 q, 16-19 k, 20-23 v
    const int bb = row0 >> 11;
    const float scale = 0.08838834764831845f;
    const float L2E = 0.20762050593046f;

    if (tile < 20) {   // q or k: rope + split (bf16)
        bool isq = tile < 16;
        int hh = isq ? tile : tile - 16;
        int nh = isq ? H : G;
        __nv_bfloat16* dh = isq ? g_qsh : g_ksh;
        __nv_bfloat16* dl = isq ? g_qsl : g_ksl;
        float sc = isq ? scale : 1.0f;
        #pragma unroll 4
        for (int t = 0; t < 16; t++) {
            int idx = tid + t * 256;
            int r = idx >> 5;
            int i2 = (idx & 31) * 2;
            int s = (row0 + r) & (S - 1);
            float a0 = st[r * STF + i2],      a1 = st[r * STF + i2 + 1];
            float c0 = st[r * STF + i2 + 64], c1 = st[r * STF + i2 + 65];
            float f0 = exp2f(-(float)i2 * L2E);
            float f1 = exp2f(-(float)(i2 + 1) * L2E);
            float cs0 = cosf(s * f0), sn0 = sinf(s * f0);
            float cs1 = cosf(s * f1), sn1 = sinf(s * f1);
            float o10 = (a0 * cs0 - c0 * sn0) * sc;
            float o11 = (a1 * cs1 - c1 * sn1) * sc;
            float o20 = (c0 * cs0 + a0 * sn0) * sc;
            float o21 = (c1 * cs1 + a1 * sn1) * sc;
            unsigned h1, l1, h2, l2;
            split2(o10, o11, h1, l1);
            split2(o20, o21, h2, l2);
            size_t dst = ((size_t)(bb * nh + hh) * S + s) * HD + i2;
            *(unsigned*)&dh[dst] = h1;
            *(unsigned*)&dl[dst] = l1;
            *(unsigned*)&dh[dst + 64] = h2;
            *(unsigned*)&dl[dst + 64] = l2;
        }
    } else {           // v: split to fp16 hi/lo
        int gg = tile - 20;
        #pragma unroll 4
        for (int t = 0; t < 32; t++) {
            int idx = tid + t * 256;
            int r = idx >> 6;
            int i2 = (idx & 63) * 2;
            int s = (row0 + r) & (S - 1);
            float v0 = st[r * STF + i2], v1 = st[r * STF + i2 + 1];
            unsigned h, l;
            split2h(v0, v1, h, l);
            size_t dst = ((size_t)(bb * G + gg) * S + s) * HD + i2;
            *(unsigned*)&g_vsh[dst] = h;
            *(unsigned*)&g_vsl[dst] = l;
        }
    }
}

// ========= output projection: A fp16 single, B fp16 hi/lo (2-term) ==========
#define STH_EL 13824   // per-stage elements: 128*40 + 2*32*136

__global__ __launch_bounds__(256) void gemm_out_h(
    const __half* __restrict__ Ag,
    const __half* __restrict__ Bhg, const __half* __restrict__ Blg,
    const float* __restrict__ bias, float* __restrict__ C,
    int M, int N, int K) {
    extern __shared__ __nv_bfloat16 smemb[];
    __half* smem = (__half*)smemb;
    const unsigned smBase = (unsigned)__cvta_generic_to_shared(smem);

    const int tid = threadIdx.x;
    const int lane = tid & 31;
    const int warp = tid >> 5;
    const int wm = (warp >> 2) * 64;
    const int wn = (warp & 3) * 32;
    const int row0 = blockIdx.y * 128;
    const int col0 = blockIdx.x * 128;
    const int NT = K / 32;

    float acc[4][4][4] = {};

    auto issue = [&](int st, int k0) {
        unsigned sb = smBase + st * (STH_EL * 2);
        #pragma unroll
        for (int j = 0; j < 2; j++) {
            int c = tid + j * 256;
            int r = c >> 2, c8 = (c & 3) * 8;
            unsigned so = (unsigned)(r * LDA + c8) * 2;
            CP16(sb + so, &Ag[(size_t)(row0 + r) * K + k0 + c8]);
        }
        #pragma unroll
        for (int j = 0; j < 2; j++) {
            int c = tid + j * 256;
            int r = c >> 4, c8 = (c & 15) * 8;
            unsigned so = (unsigned)(r * LDB + c8) * 2;
            CP16(sb + 10240 + so, &Bhg[(size_t)(k0 + r) * N + col0 + c8]);
            CP16(sb + 18944 + so, &Blg[(size_t)(k0 + r) * N + col0 + c8]);
        }
    };

    issue(0, 0);
    CP_COMMIT;
    issue(1, 32);
    CP_COMMIT;

    for (int it = 0; it < NT; it++) {
        if (it == NT - 1) {
            asm volatile("cp.async.wait_group 0;");
        } else {
            asm volatile("cp.async.wait_group 1;");
        }
        __syncthreads();
        if (it + 2 < NT) {
            issue((it + 2) % 3, (it + 2) * 32);
            CP_COMMIT;
        }

        unsigned sb = smBase + (it % 3) * (STH_EL * 2);
        const unsigned aBase = sb;
        const unsigned bBaseH = sb + 10240, bBaseL = sb + 18944;

        #pragma unroll
        for (int ks = 0; ks < 2; ks++) {
            unsigned ah[4][4];
            #pragma unroll
            for (int im = 0; im < 4; im++) {
                unsigned off =
                    ((wm + im * 16 + (lane & 15)) * LDA + ks * 16 + (lane >> 4) * 8) * 2;
                LDSM4(ah[im], aBase + off);
            }
            int krow = ks * 16 + (lane & 7) + ((lane >> 3) & 1) * 8;
            #pragma unroll
            for (int pr = 0; pr < 2; pr++) {
                unsigned bh[4], bl[4];
                unsigned off = (krow * LDB + wn + pr * 16 + (lane >> 4) * 8) * 2;
                LDSM4T(bh, bBaseH + off);
                LDSM4T(bl, bBaseL + off);
                #pragma unroll
                for (int im = 0; im < 4; im++) {
                    MMA16816H(acc[im][pr * 2 + 0], ah[im], bh[0], bh[1]);
                    MMA16816H(acc[im][pr * 2 + 0], ah[im], bl[0], bl[1]);
                    MMA16816H(acc[im][pr * 2 + 1], ah[im], bh[2], bh[3]);
                    MMA16816H(acc[im][pr * 2 + 1], ah[im], bl[2], bl[3]);
                }
            }
        }
    }

    const float inv32 = 1.0f / 32.0f;
    const int qr = lane >> 2, qc = lane & 3;
    #pragma unroll
    for (int im = 0; im < 4; im++) {
        #pragma unroll
        for (int jn = 0; jn < 4; jn++) {
            int row = row0 + wm + im * 16 + qr;
            int col = col0 + wn + jn * 8 + 2 * qc;
            float b0v = bias[col], b1v = bias[col + 1];
            float2 o0 = make_float2(acc[im][jn][0] * inv32 + b0v,
                                    acc[im][jn][1] * inv32 + b1v);
            float2 o1 = make_float2(acc[im][jn][2] * inv32 + b0v,
                                    acc[im][jn][3] * inv32 + b1v);
            *(float2*)&C[(size_t)row * N + col] = o0;
            *(float2*)&C[(size_t)(row + 8) * N + col] = o1;
        }
    }
}

// ====== Flash attention: 128-row q tiles, QK bf16 3-term, PV fp16 2-term =====
#define LQ 136

__global__ __launch_bounds__(256) void flash_tc() {
    extern __shared__ __nv_bfloat16 smb[];
    __nv_bfloat16* Qh = smb;
    __nv_bfloat16* Ql = Qh + 128 * LQ;
    __nv_bfloat16* Kh = Ql + 128 * LQ;
    __nv_bfloat16* Kl = Kh + 64 * LQ;
    __half*        Vh = (__half*)(Kl + 64 * LQ);
    __half*        Vl = Vh + 64 * LQ;

    const int tid  = threadIdx.x;
    const int lane = tid & 31;
    const int warp = tid >> 5;              // 0..7
    const int qtile = gridDim.x - 1 - blockIdx.x;  // heavy tiles first
    const int h  = blockIdx.y;
    const int b  = blockIdx.z;
    const int g  = h / (H / G);
    const int q0 = qtile * 128;
    const int wm = warp * 16;

    const unsigned qBH = (unsigned)__cvta_generic_to_shared(Qh);
    const unsigned qBL = (unsigned)__cvta_generic_to_shared(Ql);
    const unsigned kBH = (unsigned)__cvta_generic_to_shared(Kh);
    const unsigned kBL = (unsigned)__cvta_generic_to_shared(Kl);
    const unsigned vBH = (unsigned)__cvta_generic_to_shared(Vh);
    const unsigned vBL = (unsigned)__cvta_generic_to_shared(Vl);

    // ---- load Q tile (pre-split, pre-scaled, roped) ----
    #pragma unroll
    for (int it = 0; it < 8; it++) {
        int i4 = tid + it * 256;           // 0..2047
        int r  = i4 >> 4;                  // 0..127
        int c8 = (i4 & 15) * 8;
        size_t gi = ((size_t)(b * H + h) * S + q0 + r) * HD + c8;
        *(uint4*)&Qh[r * LQ + c8] = *(const uint4*)&g_qsh[gi];
        *(uint4*)&Ql[r * LQ + c8] = *(const uint4*)&g_qsl[gi];
    }

    const int gid = lane >> 2, tig = lane & 3;
    const int row0g = q0 + wm + gid;
    const int row1g = row0g + 8;
    const int wmaxrow = q0 + wm + 15;

    float rm0 = -1e30f, rm1 = -1e30f, rl0 = 0.0f, rl1 = 0.0f;
    float oacc[16][4] = {};

    const int NKT = 2 * qtile + 2;
    for (int kt = 0; kt < NKT; kt++) {
        const int k0 = kt * 64;
        __syncthreads();
        // ---- load K,V tiles ----
        #pragma unroll
        for (int it = 0; it < 4; it++) {
            int i4 = tid + it * 256;       // 0..1023
            int r  = i4 >> 4;              // 0..63
            int c8 = (i4 & 15) * 8;
            size_t gi = ((size_t)(b * G + g) * S + k0 + r) * HD + c8;
            unsigned so = r * LQ + c8;
            *(uint4*)&Kh[so] = *(const uint4*)&g_ksh[gi];
            *(uint4*)&Kl[so] = *(const uint4*)&g_ksl[gi];
            *(uint4*)&Vh[so] = *(const uint4*)&g_vsh[gi];
            *(uint4*)&Vl[so] = *(const uint4*)&g_vsl[gi];
        }
        __syncthreads();

        if (k0 > wmaxrow) continue;        // whole warp above diagonal

        // ---- S = Q @ K^T (bf16 3-term) ----
        float sacc[8][4] = {};
        #pragma unroll
        for (int ks = 0; ks < 8; ks++) {
            unsigned ah[4], al[4];
            unsigned offa = ((wm + (lane & 15)) * LQ + ks * 16 + (lane >> 4) * 8) * 2;
            LDSM4(ah, qBH + offa);
            LDSM4(al, qBL + offa);
            #pragma unroll
            for (int nb = 0; nb < 4; nb++) {
                unsigned kh[4], kl[4];
                unsigned offb = ((nb * 16 + (lane >> 4) * 8 + (lane & 7)) * LQ +
                                 ks * 16 + ((lane >> 3) & 1) * 8) * 2;
                LDSM4(kh, kBH + offb);
                LDSM4(kl, kBL + offb);
                MMA16816(sacc[2 * nb + 0], ah, kh[0], kh[1]);
                MMA16816(sacc[2 * nb + 0], ah, kl[0], kl[1]);
                MMA16816(sacc[2 * nb + 0], al, kh[0], kh[1]);
                MMA16816(sacc[2 * nb + 1], ah, kh[2], kh[3]);
                MMA16816(sacc[2 * nb + 1], ah, kl[2], kl[3]);
                MMA16816(sacc[2 * nb + 1], al, kh[2], kh[3]);
            }
        }

        if (k0 + 63 > row0g) {
            #pragma unroll
            for (int nt = 0; nt < 8; nt++) {
                int colg = k0 + nt * 8 + 2 * tig;
                if (colg > row0g)     sacc[nt][0] = -1e30f;
                if (colg + 1 > row0g) sacc[nt][1] = -1e30f;
                if (colg > row1g)     sacc[nt][2] = -1e30f;
                if (colg + 1 > row1g) sacc[nt][3] = -1e30f;
            }
        }

        // ---- online softmax ----
        float mx0 = rm0, mx1 = rm1;
        #pragma unroll
        for (int nt = 0; nt < 8; nt++) {
            mx0 = fmaxf(mx0, fmaxf(sacc[nt][0], sacc[nt][1]));
            mx1 = fmaxf(mx1, fmaxf(sacc[nt][2], sacc[nt][3]));
        }
        mx0 = fmaxf(mx0, __shfl_xor_sync(0xffffffff, mx0, 1));
        mx0 = fmaxf(mx0, __shfl_xor_sync(0xffffffff, mx0, 2));
        mx1 = fmaxf(mx1, __shfl_xor_sync(0xffffffff, mx1, 1));
        mx1 = fmaxf(mx1, __shfl_xor_sync(0xffffffff, mx1, 2));
        float sc0 = __expf(rm0 - mx0);
        float sc1 = __expf(rm1 - mx1);
        rm0 = mx0; rm1 = mx1;
        float sum0 = 0.0f, sum1 = 0.0f;
        #pragma unroll
        for (int nt = 0; nt < 8; nt++) {
            sacc[nt][0] = __expf(sacc[nt][0] - mx0);
            sacc[nt][1] = __expf(sacc[nt][1] - mx0);
            sacc[nt][2] = __expf(sacc[nt][2] - mx1);
            sacc[nt][3] = __expf(sacc[nt][3] - mx1);
            sum0 += sacc[nt][0] + sacc[nt][1];
            sum1 += sacc[nt][2] + sacc[nt][3];
        }
        sum0 += __shfl_xor_sync(0xffffffff, sum0, 1);
        sum0 += __shfl_xor_sync(0xffffffff, sum0, 2);
        sum1 += __shfl_xor_sync(0xffffffff, sum1, 1);
        sum1 += __shfl_xor_sync(0xffffffff, sum1, 2);
        rl0 = rl0 * sc0 + sum0;
        rl1 = rl1 * sc1 + sum1;
        #pragma unroll
        for (int nt = 0; nt < 16; nt++) {
            oacc[nt][0] *= sc0; oacc[nt][1] *= sc0;
            oacc[nt][2] *= sc1; oacc[nt][3] *= sc1;
        }

        // ---- O += P @ V (fp16, 2-term: P single, V hi/lo) ----
        #pragma unroll
        for (int j = 0; j < 4; j++) {
            unsigned ph[4];
            ph[0] = packh2(sacc[2 * j][0],     sacc[2 * j][1]);
            ph[1] = packh2(sacc[2 * j][2],     sacc[2 * j][3]);
            ph[2] = packh2(sacc[2 * j + 1][0], sacc[2 * j + 1][1]);
            ph[3] = packh2(sacc[2 * j + 1][2], sacc[2 * j + 1][3]);
            #pragma unroll
            for (int nb = 0; nb < 8; nb++) {
                unsigned vh4[4], vl4[4];
                unsigned offv = ((j * 16 + (lane & 7) + ((lane >> 3) & 1) * 8) * LQ +
                                 nb * 16 + (lane >> 4) * 8) * 2;
                LDSM4T(vh4, vBH + offv);
                LDSM4T(vl4, vBL + offv);
                MMA16816H(oacc[2 * nb + 0], ph, vh4[0], vh4[1]);
                MMA16816H(oacc[2 * nb + 0], ph, vl4[0], vl4[1]);
                MMA16816H(oacc[2 * nb + 1], ph, vh4[2], vh4[3]);
                MMA16816H(oacc[2 * nb + 1], ph, vl4[2], vl4[3]);
            }
        }
    }

    // ---- finalize: divide by l, store fp16 single ----
    float li0 = 1.0f / rl0, li1 = 1.0f / rl1;
    size_t or0 = (size_t)(b * S + row0g) * (H * HD) + h * HD;
    size_t or1 = (size_t)(b * S + row1g) * (H * HD) + h * HD;
    #pragma unroll
    for (int nt = 0; nt < 16; nt++) {
        int col = nt * 8 + 2 * tig;
        *(unsigned*)&g_ah[or0 + col] = packh2(oacc[nt][0] * li0, oacc[nt][1] * li0);
        *(unsigned*)&g_ah[or1 + col] = packh2(oacc[nt][2] * li1, oacc[nt][3] * li1);
    }
}

// =============================== launch ======================================
extern "C" void kernel_launch(void* const* d_in, const int* in_sizes, int n_in,
                              void* d_out, int out_size) {
    const float* x  = (const float*)d_in[0];
    const float* Wq = (const float*)d_in[1];
    const float* bq = (const float*)d_in[2];
    const float* Wk = (const float*)d_in[3];
    const float* bk = (const float*)d_in[4];
    const float* Wv = (const float*)d_in[5];
    const float* bv = (const float*)d_in[6];
    const float* Wo = (const float*)d_in[7];
    const float* bo = (const float*)d_in[8];
    float* out = (float*)d_out;

    __nv_bfloat16 *xh, *xl, *wqh, *wql;
    __half *woh, *wol, *ah;
    float *bqkv;
    cudaGetSymbolAddress((void**)&xh, g_xh);
    cudaGetSymbolAddress((void**)&xl, g_xl);
    cudaGetSymbolAddress((void**)&wqh, g_wqh);
    cudaGetSymbolAddress((void**)&wql, g_wql);
    cudaGetSymbolAddress((void**)&woh, g_woh);
    cudaGetSymbolAddress((void**)&wol, g_wol);
    cudaGetSymbolAddress((void**)&ah, g_ah);
    cudaGetSymbolAddress((void**)&bqkv, g_bqkv);

    const int M = B * S;  // 8192

    // ---- pre-split conversions ----
    {
        int n4 = M * D / 4;
        convert_split<<<(n4 + 255) / 256, 256>>>(x, xh, xl, n4);
    }
    {
        int n4 = D * 2048 / 4;
        convert_pack<<<(n4 + 255) / 256, 256>>>(Wq, wqh, wql, 2048, 0, n4);
        n4 = D * 512 / 4;
        convert_pack<<<(n4 + 255) / 256, 256>>>(Wk, wqh, wql, 512, 2048, n4);
        convert_pack<<<(n4 + 255) / 256, 256>>>(Wv, wqh, wql, 512, 2560, n4);
        n4 = D * D / 4;
        convert_split_h32<<<(n4 + 255) / 256, 256>>>(Wo, woh, wol, n4);
    }
    pack_bias<<<(NQKV + 255) / 256, 256>>>(bq, bk, bv, bqkv);

    size_t gsm = (size_t)3 * ST_EL * sizeof(__nv_bfloat16);  // 113664 B
    cudaFuncSetAttribute(gemm_qkv_fused, cudaFuncAttributeMaxDynamicSharedMemorySize, (int)gsm);
    size_t gsmh = (size_t)3 * STH_EL * sizeof(__half);       // 82944 B
    cudaFuncSetAttribute(gemm_out_h, cudaFuncAttributeMaxDynamicSharedMemorySize, (int)gsmh);

    // ---- fused QKV projection + bias + RoPE + split ----
    gemm_qkv_fused<<<dim3(NQKV / 128, M / 128), 256, gsm>>>(xh, xl, wqh, wql, bqkv);

    // ---- flash attention (128-row q tiles) ----
    size_t smem = (size_t)(2 * 128 + 4 * 64) * LQ * sizeof(__nv_bfloat16);  // 139264 B
    cudaFuncSetAttribute(flash_tc, cudaFuncAttributeMaxDynamicSharedMemorySize, (int)smem);
    flash_tc<<<dim3(S / 128, H, B), 256, smem>>>();

    // ---- output projection (fp16 2-term) ----
    gemm_out_h<<<dim3(D / 128, M / 128), 256, gsmh>>>(
        ah, woh, wol, bo, out, M, D, H * HD);
}

// round 10
// speedup vs baseline: 5.1167x; 1.1495x over previous
#include <cuda_runtime.h>
#include <cuda_bf16.h>
#include <cuda_fp16.h>
#include <math.h>

#define B 4
#define S 2048
#define D 2048
#define H 16
#define G 4
#define HD 128
#define NQKV 3072   // packed q(2048) | k(512) | v(512)

// ------------------------- scratch (device globals, no allocs) --------------
__device__ __nv_bfloat16 g_xh[(size_t)B * S * D];
__device__ __nv_bfloat16 g_xl[(size_t)B * S * D];
__device__ __nv_bfloat16 g_wqh[(size_t)D * NQKV];          // packed Wqkv hi [k][n]
__device__ __nv_bfloat16 g_wql[(size_t)D * NQKV];
__device__ __half        g_woh[(size_t)H * HD * D];        // Wo*32 (fp16 single)
__device__ __half        g_ah[(size_t)B * S * H * HD];     // attn out (fp16 single)
__device__ float         g_bqkv[NQKV];
// pre-split, roped operands for flash
__device__ __nv_bfloat16 g_qsh[(size_t)B * H * S * HD];    // q hi [b][h][s][hd]
__device__ __nv_bfloat16 g_qsl[(size_t)B * H * S * HD];
__device__ __nv_bfloat16 g_ksh[(size_t)B * G * S * HD];    // k hi [b][g][s][hd]
__device__ __nv_bfloat16 g_ksl[(size_t)B * G * S * HD];
__device__ __half        g_vsh[(size_t)B * G * S * HD];    // v (fp16 single)

// ============================ shared PTX helpers =============================
#define LDSM4(R, addr)                                                        \
    asm volatile("ldmatrix.sync.aligned.m8n8.x4.shared.b16 {%0,%1,%2,%3}, [%4];" \
                 : "=r"(R[0]), "=r"(R[1]), "=r"(R[2]), "=r"(R[3]) : "r"(addr))
#define LDSM4T(R, addr)                                                       \
    asm volatile("ldmatrix.sync.aligned.m8n8.x4.trans.shared.b16 {%0,%1,%2,%3}, [%4];" \
                 : "=r"(R[0]), "=r"(R[1]), "=r"(R[2]), "=r"(R[3]) : "r"(addr))
#define MMA16816(d, a, b0v, b1v)                                              \
    asm volatile("mma.sync.aligned.m16n8k16.row.col.f32.bf16.bf16.f32 "       \
                 "{%0,%1,%2,%3},{%4,%5,%6,%7},{%8,%9},{%0,%1,%2,%3};"         \
                 : "+f"(d[0]), "+f"(d[1]), "+f"(d[2]), "+f"(d[3])             \
                 : "r"(a[0]), "r"(a[1]), "r"(a[2]), "r"(a[3]),                \
                   "r"(b0v), "r"(b1v))
#define MMA16816H(d, a, b0v, b1v)                                             \
    asm volatile("mma.sync.aligned.m16n8k16.row.col.f32.f16.f16.f32 "         \
                 "{%0,%1,%2,%3},{%4,%5,%6,%7},{%8,%9},{%0,%1,%2,%3};"         \
                 : "+f"(d[0]), "+f"(d[1]), "+f"(d[2]), "+f"(d[3])             \
                 : "r"(a[0]), "r"(a[1]), "r"(a[2]), "r"(a[3]),                \
                   "r"(b0v), "r"(b1v))
#define CP16(smaddr, gptr)                                                    \
    asm volatile("cp.async.cg.shared.global [%0], [%1], 16;" :: "r"(smaddr), "l"(gptr))
#define CP_COMMIT asm volatile("cp.async.commit_group;")

__device__ __forceinline__ void split2(float x, float y,
                                       unsigned& hi, unsigned& lo) {
    __nv_bfloat16 hx = __float2bfloat16_rn(x);
    __nv_bfloat16 hy = __float2bfloat16_rn(y);
    float rx = x - __bfloat162float(hx);
    float ry = y - __bfloat162float(hy);
    __nv_bfloat16 lx = __float2bfloat16_rn(rx);
    __nv_bfloat16 ly = __float2bfloat16_rn(ry);
    __nv_bfloat162 h2 = __nv_bfloat162(hx, hy);
    __nv_bfloat162 l2 = __nv_bfloat162(lx, ly);
    hi = *(unsigned*)&h2;
    lo = *(unsigned*)&l2;
}

__device__ __forceinline__ unsigned packh2(float x, float y) {
    __half2 h = __floats2half2_rn(x, y);
    return *(unsigned*)&h;
}

// ========================= conversion / packing kernels ======================
__global__ void convert_split(const float* __restrict__ src,
                              __nv_bfloat16* __restrict__ hi,
                              __nv_bfloat16* __restrict__ lo, int n4) {
    int i = blockIdx.x * blockDim.x + threadIdx.x;
    if (i >= n4) return;
    float4 v = ((const float4*)src)[i];
    uint2 h, l;
    split2(v.x, v.y, h.x, l.x);
    split2(v.z, v.w, h.y, l.y);
    ((uint2*)hi)[i] = h;
    ((uint2*)lo)[i] = l;
}

// Wo * 32 -> fp16 single
__global__ void convert_h32(const float* __restrict__ src,
                            __half* __restrict__ dst, int n4) {
    int i = blockIdx.x * blockDim.x + threadIdx.x;
    if (i >= n4) return;
    float4 v = ((const float4*)src)[i];
    uint2 h;
    h.x = packh2(v.x * 32.0f, v.y * 32.0f);
    h.y = packh2(v.z * 32.0f, v.w * 32.0f);
    ((uint2*)dst)[i] = h;
}

__global__ void convert_pack(const float* __restrict__ src,
                             __nv_bfloat16* __restrict__ hi,
                             __nv_bfloat16* __restrict__ lo,
                             int srcN, int dstOff, int n4) {
    int i = blockIdx.x * blockDim.x + threadIdx.x;
    if (i >= n4) return;
    int rw = srcN >> 2;
    int r = i / rw, c = (i % rw) * 4;
    float4 v = *(const float4*)&src[(size_t)r * srcN + c];
    uint2 h, l;
    split2(v.x, v.y, h.x, l.x);
    split2(v.z, v.w, h.y, l.y);
    size_t d = (size_t)r * NQKV + dstOff + c;
    *(uint2*)&hi[d] = h;
    *(uint2*)&lo[d] = l;
}

__global__ void pack_bias(const float* __restrict__ bq, const float* __restrict__ bk,
                          const float* __restrict__ bv, float* __restrict__ dst) {
    int i = blockIdx.x * blockDim.x + threadIdx.x;
    if (i >= NQKV) return;
    dst[i] = (i < 2048) ? bq[i] : (i < 2560) ? bk[i - 2048] : bv[i - 2560];
}

// ======================== bf16 3-term GEMM mainloop ==========================
#define LDA 40
#define LDB 136
#define ST_EL 18944   // per-stage smem elements: 2*128*40 + 2*32*136

struct GemmAcc { float a[4][4][4]; };

// 3-stage cp.async pipeline, ONE __syncthreads per 32-K iteration.
__device__ __forceinline__ void gemm_mainloop(
    const __nv_bfloat16* __restrict__ Ahg, const __nv_bfloat16* __restrict__ Alg,
    const __nv_bfloat16* __restrict__ Bhg, const __nv_bfloat16* __restrict__ Blg,
    int K, int N, int row0, int col0, unsigned smBase, GemmAcc& acc) {
    const int tid = threadIdx.x;
    const int lane = tid & 31;
    const int warp = tid >> 5;
    const int wm = (warp >> 2) * 64;
    const int wn = (warp & 3) * 32;
    const int NT = K / 32;

    auto issue = [&](int st, int k0) {
        unsigned sb = smBase + st * (ST_EL * 2);
        #pragma unroll
        for (int j = 0; j < 2; j++) {
            int c = tid + j * 256;
            int r = c >> 2, c8 = (c & 3) * 8;
            unsigned so = (unsigned)(r * LDA + c8) * 2;
            CP16(sb + so, &Ahg[(size_t)(row0 + r) * K + k0 + c8]);
            CP16(sb + 10240 + so, &Alg[(size_t)(row0 + r) * K + k0 + c8]);
        }
        #pragma unroll
        for (int j = 0; j < 2; j++) {
            int c = tid + j * 256;
            int r = c >> 4, c8 = (c & 15) * 8;
            unsigned so = (unsigned)(r * LDB + c8) * 2;
            CP16(sb + 20480 + so, &Bhg[(size_t)(k0 + r) * N + col0 + c8]);
            CP16(sb + 29184 + so, &Blg[(size_t)(k0 + r) * N + col0 + c8]);
        }
    };

    issue(0, 0);
    CP_COMMIT;
    issue(1, 32);
    CP_COMMIT;

    for (int it = 0; it < NT; it++) {
        if (it == NT - 1) {
            asm volatile("cp.async.wait_group 0;");
        } else {
            asm volatile("cp.async.wait_group 1;");
        }
        __syncthreads();
        if (it + 2 < NT) {
            issue((it + 2) % 3, (it + 2) * 32);
            CP_COMMIT;
        }

        unsigned sb = smBase + (it % 3) * (ST_EL * 2);
        const unsigned aBaseH = sb, aBaseL = sb + 10240;
        const unsigned bBaseH = sb + 20480, bBaseL = sb + 29184;

        #pragma unroll
        for (int ks = 0; ks < 2; ks++) {
            unsigned ah[4][4], al[4][4];
            #pragma unroll
            for (int im = 0; im < 4; im++) {
                unsigned off =
                    ((wm + im * 16 + (lane & 15)) * LDA + ks * 16 + (lane >> 4) * 8) * 2;
                LDSM4(ah[im], aBaseH + off);
                LDSM4(al[im], aBaseL + off);
            }
            int krow = ks * 16 + (lane & 7) + ((lane >> 3) & 1) * 8;
            #pragma unroll
            for (int pr = 0; pr < 2; pr++) {
                unsigned bh[4], bl[4];
                unsigned off = (krow * LDB + wn + pr * 16 + (lane >> 4) * 8) * 2;
                LDSM4T(bh, bBaseH + off);
                LDSM4T(bl, bBaseL + off);
                #pragma unroll
                for (int im = 0; im < 4; im++) {
                    MMA16816(acc.a[im][pr * 2 + 0], ah[im], bh[0], bh[1]);
                    MMA16816(acc.a[im][pr * 2 + 0], ah[im], bl[0], bl[1]);
                    MMA16816(acc.a[im][pr * 2 + 0], al[im], bh[0], bh[1]);
                    MMA16816(acc.a[im][pr * 2 + 1], ah[im], bh[2], bh[3]);
                    MMA16816(acc.a[im][pr * 2 + 1], ah[im], bl[2], bl[3]);
                    MMA16816(acc.a[im][pr * 2 + 1], al[im], bh[2], bh[3]);
                }
            }
        }
    }
    __syncthreads();   // mainloop smem dead; safe for epilogue reuse
}

// ============= QKV GEMM with fused bias + RoPE + hi/lo split epilogue ========
#define STF 132   // fp32 smem stride for epilogue tile

__global__ __launch_bounds__(256) void gemm_qkv_fused(
    const __nv_bfloat16* __restrict__ Ahg, const __nv_bfloat16* __restrict__ Alg,
    const __nv_bfloat16* __restrict__ Bhg, const __nv_bfloat16* __restrict__ Blg,
    const float* __restrict__ bias) {
    extern __shared__ __nv_bfloat16 smem[];
    const unsigned smBase = (unsigned)__cvta_generic_to_shared(smem);

    const int tid = threadIdx.x;
    const int lane = tid & 31;
    const int warp = tid >> 5;
    const int wm = (warp >> 2) * 64;
    const int wn = (warp & 3) * 32;
    const int row0 = blockIdx.y * 128;
    const int col0 = blockIdx.x * 128;

    GemmAcc acc = {};
    gemm_mainloop(Ahg, Alg, Bhg, Blg, D, NQKV, row0, col0, smBase, acc);

    // ---- stage fp32 tile (with bias) in smem ----
    float* st = (float*)smem;
    const int qr = lane >> 2, qc = lane & 3;
    #pragma unroll
    for (int im = 0; im < 4; im++) {
        #pragma unroll
        for (int jn = 0; jn < 4; jn++) {
            int rr = wm + im * 16 + qr;
            int cc = wn + jn * 8 + 2 * qc;
            float b0v = bias[col0 + cc], b1v = bias[col0 + cc + 1];
            st[rr * STF + cc]           = acc.a[im][jn][0] + b0v;
            st[rr * STF + cc + 1]       = acc.a[im][jn][1] + b1v;
            st[(rr + 8) * STF + cc]     = acc.a[im][jn][2] + b0v;
            st[(rr + 8) * STF + cc + 1] = acc.a[im][jn][3] + b1v;
        }
    }
    __syncthreads();

    const int tile = col0 >> 7;      // head tile: 0-15 q, 16-19 k, 20-23 v
    const int bb = row0 >> 11;
    const float scale = 0.08838834764831845f;
    const float L2E = 0.20762050593046f;

    if (tile < 20) {   // q or k: rope + split (bf16)
        bool isq = tile < 16;
        int hh = isq ? tile : tile - 16;
        int nh = isq ? H : G;
        __nv_bfloat16* dh = isq ? g_qsh : g_ksh;
        __nv_bfloat16* dl = isq ? g_qsl : g_ksl;
        float sc = isq ? scale : 1.0f;
        #pragma unroll 4
        for (int t = 0; t < 16; t++) {
            int idx = tid + t * 256;
            int r = idx >> 5;
            int i2 = (idx & 31) * 2;
            int s = (row0 + r) & (S - 1);
            float a0 = st[r * STF + i2],      a1 = st[r * STF + i2 + 1];
            float c0 = st[r * STF + i2 + 64], c1 = st[r * STF + i2 + 65];
            float f0 = exp2f(-(float)i2 * L2E);
            float f1 = exp2f(-(float)(i2 + 1) * L2E);
            float cs0 = cosf(s * f0), sn0 = sinf(s * f0);
            float cs1 = cosf(s * f1), sn1 = sinf(s * f1);
            float o10 = (a0 * cs0 - c0 * sn0) * sc;
            float o11 = (a1 * cs1 - c1 * sn1) * sc;
            float o20 = (c0 * cs0 + a0 * sn0) * sc;
            float o21 = (c1 * cs1 + a1 * sn1) * sc;
            unsigned h1, l1, h2, l2;
            split2(o10, o11, h1, l1);
            split2(o20, o21, h2, l2);
            size_t dst = ((size_t)(bb * nh + hh) * S + s) * HD + i2;
            *(unsigned*)&dh[dst] = h1;
            *(unsigned*)&dl[dst] = l1;
            *(unsigned*)&dh[dst + 64] = h2;
            *(unsigned*)&dl[dst + 64] = l2;
        }
    } else {           // v: single fp16
        int gg = tile - 20;
        #pragma unroll 4
        for (int t = 0; t < 32; t++) {
            int idx = tid + t * 256;
            int r = idx >> 6;
            int i2 = (idx & 63) * 2;
            int s = (row0 + r) & (S - 1);
            float v0 = st[r * STF + i2], v1 = st[r * STF + i2 + 1];
            size_t dst = ((size_t)(bb * G + gg) * S + s) * HD + i2;
            *(unsigned*)&g_vsh[dst] = packh2(v0, v1);
        }
    }
}

// ============ output projection: A fp16 single x W fp16 single ===============
#define STH_EL 9472   // per-stage elements: 128*40 + 32*136

__global__ __launch_bounds__(256) void gemm_out_h(
    const __half* __restrict__ Ag, const __half* __restrict__ Bg,
    const float* __restrict__ bias, float* __restrict__ C,
    int M, int N, int K) {
    extern __shared__ __nv_bfloat16 smemb[];
    __half* smem = (__half*)smemb;
    const unsigned smBase = (unsigned)__cvta_generic_to_shared(smem);

    const int tid = threadIdx.x;
    const int lane = tid & 31;
    const int warp = tid >> 5;
    const int wm = (warp >> 2) * 64;
    const int wn = (warp & 3) * 32;
    const int row0 = blockIdx.y * 128;
    const int col0 = blockIdx.x * 128;
    const int NT = K / 32;

    float acc[4][4][4] = {};

    auto issue = [&](int st, int k0) {
        unsigned sb = smBase + st * (STH_EL * 2);
        #pragma unroll
        for (int j = 0; j < 2; j++) {
            int c = tid + j * 256;
            int r = c >> 2, c8 = (c & 3) * 8;
            unsigned so = (unsigned)(r * LDA + c8) * 2;
            CP16(sb + so, &Ag[(size_t)(row0 + r) * K + k0 + c8]);
        }
        #pragma unroll
        for (int j = 0; j < 2; j++) {
            int c = tid + j * 256;
            int r = c >> 4, c8 = (c & 15) * 8;
            unsigned so = (unsigned)(r * LDB + c8) * 2;
            CP16(sb + 10240 + so, &Bg[(size_t)(k0 + r) * N + col0 + c8]);
        }
    };

    issue(0, 0);
    CP_COMMIT;
    issue(1, 32);
    CP_COMMIT;

    for (int it = 0; it < NT; it++) {
        if (it == NT - 1) {
            asm volatile("cp.async.wait_group 0;");
        } else {
            asm volatile("cp.async.wait_group 1;");
        }
        __syncthreads();
        if (it + 2 < NT) {
            issue((it + 2) % 3, (it + 2) * 32);
            CP_COMMIT;
        }

        unsigned sb = smBase + (it % 3) * (STH_EL * 2);
        const unsigned aBase = sb;
        const unsigned bBase = sb + 10240;

        #pragma unroll
        for (int ks = 0; ks < 2; ks++) {
            unsigned ah[4][4];
            #pragma unroll
            for (int im = 0; im < 4; im++) {
                unsigned off =
                    ((wm + im * 16 + (lane & 15)) * LDA + ks * 16 + (lane >> 4) * 8) * 2;
                LDSM4(ah[im], aBase + off);
            }
            int krow = ks * 16 + (lane & 7) + ((lane >> 3) & 1) * 8;
            #pragma unroll
            for (int pr = 0; pr < 2; pr++) {
                unsigned bh[4];
                unsigned off = (krow * LDB + wn + pr * 16 + (lane >> 4) * 8) * 2;
                LDSM4T(bh, bBase + off);
                #pragma unroll
                for (int im = 0; im < 4; im++) {
                    MMA16816H(acc[im][pr * 2 + 0], ah[im], bh[0], bh[1]);
                    MMA16816H(acc[im][pr * 2 + 1], ah[im], bh[2], bh[3]);
                }
            }
        }
    }

    const float inv32 = 1.0f / 32.0f;
    const int qr = lane >> 2, qc = lane & 3;
    #pragma unroll
    for (int im = 0; im < 4; im++) {
        #pragma unroll
        for (int jn = 0; jn < 4; jn++) {
            int row = row0 + wm + im * 16 + qr;
            int col = col0 + wn + jn * 8 + 2 * qc;
            float b0v = bias[col], b1v = bias[col + 1];
            float2 o0 = make_float2(acc[im][jn][0] * inv32 + b0v,
                                    acc[im][jn][1] * inv32 + b1v);
            float2 o1 = make_float2(acc[im][jn][2] * inv32 + b0v,
                                    acc[im][jn][3] * inv32 + b1v);
            *(float2*)&C[(size_t)row * N + col] = o0;
            *(float2*)&C[(size_t)(row + 8) * N + col] = o1;
        }
    }
}

// ====== Flash attention: 128-row q tiles, QK bf16 3-term, PV fp16 1-term =====
#define LQ 136

__global__ __launch_bounds__(256) void flash_tc() {
    extern __shared__ __nv_bfloat16 smb[];
    __nv_bfloat16* Qh = smb;
    __nv_bfloat16* Ql = Qh + 128 * LQ;
    __nv_bfloat16* Kh = Ql + 128 * LQ;
    __nv_bfloat16* Kl = Kh + 64 * LQ;
    __half*        Vh = (__half*)(Kl + 64 * LQ);

    const int tid  = threadIdx.x;
    const int lane = tid & 31;
    const int warp = tid >> 5;              // 0..7
    const int qtile = gridDim.x - 1 - blockIdx.x;  // heavy tiles first
    const int h  = blockIdx.y;
    const int b  = blockIdx.z;
    const int g  = h / (H / G);
    const int q0 = qtile * 128;
    const int wm = warp * 16;

    const unsigned qBH = (unsigned)__cvta_generic_to_shared(Qh);
    const unsigned qBL = (unsigned)__cvta_generic_to_shared(Ql);
    const unsigned kBH = (unsigned)__cvta_generic_to_shared(Kh);
    const unsigned kBL = (unsigned)__cvta_generic_to_shared(Kl);
    const unsigned vBH = (unsigned)__cvta_generic_to_shared(Vh);

    // ---- load Q tile (pre-split, pre-scaled, roped) ----
    #pragma unroll
    for (int it = 0; it < 8; it++) {
        int i4 = tid + it * 256;           // 0..2047
        int r  = i4 >> 4;                  // 0..127
        int c8 = (i4 & 15) * 8;
        size_t gi = ((size_t)(b * H + h) * S + q0 + r) * HD + c8;
        *(uint4*)&Qh[r * LQ + c8] = *(const uint4*)&g_qsh[gi];
        *(uint4*)&Ql[r * LQ + c8] = *(const uint4*)&g_qsl[gi];
    }

    const int gid = lane >> 2, tig = lane & 3;
    const int row0g = q0 + wm + gid;
    const int row1g = row0g + 8;
    const int wmaxrow = q0 + wm + 15;

    float rm0 = -1e30f, rm1 = -1e30f, rl0 = 0.0f, rl1 = 0.0f;
    float oacc[16][4] = {};

    const int NKT = 2 * qtile + 2;
    for (int kt = 0; kt < NKT; kt++) {
        const int k0 = kt * 64;
        __syncthreads();
        // ---- load K,V tiles ----
        #pragma unroll
        for (int it = 0; it < 4; it++) {
            int i4 = tid + it * 256;       // 0..1023
            int r  = i4 >> 4;              // 0..63
            int c8 = (i4 & 15) * 8;
            size_t gi = ((size_t)(b * G + g) * S + k0 + r) * HD + c8;
            unsigned so = r * LQ + c8;
            *(uint4*)&Kh[so] = *(const uint4*)&g_ksh[gi];
            *(uint4*)&Kl[so] = *(const uint4*)&g_ksl[gi];
            *(uint4*)&Vh[so] = *(const uint4*)&g_vsh[gi];
        }
        __syncthreads();

        if (k0 > wmaxrow) continue;        // whole warp above diagonal

        // ---- S = Q @ K^T (bf16 3-term) ----
        float sacc[8][4] = {};
        #pragma unroll
        for (int ks = 0; ks < 8; ks++) {
            unsigned ah[4], al[4];
            unsigned offa = ((wm + (lane & 15)) * LQ + ks * 16 + (lane >> 4) * 8) * 2;
            LDSM4(ah, qBH + offa);
            LDSM4(al, qBL + offa);
            #pragma unroll
            for (int nb = 0; nb < 4; nb++) {
                unsigned kh[4], kl[4];
                unsigned offb = ((nb * 16 + (lane >> 4) * 8 + (lane & 7)) * LQ +
                                 ks * 16 + ((lane >> 3) & 1) * 8) * 2;
                LDSM4(kh, kBH + offb);
                LDSM4(kl, kBL + offb);
                MMA16816(sacc[2 * nb + 0], ah, kh[0], kh[1]);
                MMA16816(sacc[2 * nb + 0], ah, kl[0], kl[1]);
                MMA16816(sacc[2 * nb + 0], al, kh[0], kh[1]);
                MMA16816(sacc[2 * nb + 1], ah, kh[2], kh[3]);
                MMA16816(sacc[2 * nb + 1], ah, kl[2], kl[3]);
                MMA16816(sacc[2 * nb + 1], al, kh[2], kh[3]);
            }
        }

        if (k0 + 63 > row0g) {
            #pragma unroll
            for (int nt = 0; nt < 8; nt++) {
                int colg = k0 + nt * 8 + 2 * tig;
                if (colg > row0g)     sacc[nt][0] = -1e30f;
                if (colg + 1 > row0g) sacc[nt][1] = -1e30f;
                if (colg > row1g)     sacc[nt][2] = -1e30f;
                if (colg + 1 > row1g) sacc[nt][3] = -1e30f;
            }
        }

        // ---- online softmax ----
        float mx0 = rm0, mx1 = rm1;
        #pragma unroll
        for (int nt = 0; nt < 8; nt++) {
            mx0 = fmaxf(mx0, fmaxf(sacc[nt][0], sacc[nt][1]));
            mx1 = fmaxf(mx1, fmaxf(sacc[nt][2], sacc[nt][3]));
        }
        mx0 = fmaxf(mx0, __shfl_xor_sync(0xffffffff, mx0, 1));
        mx0 = fmaxf(mx0, __shfl_xor_sync(0xffffffff, mx0, 2));
        mx1 = fmaxf(mx1, __shfl_xor_sync(0xffffffff, mx1, 1));
        mx1 = fmaxf(mx1, __shfl_xor_sync(0xffffffff, mx1, 2));
        float sc0 = __expf(rm0 - mx0);
        float sc1 = __expf(rm1 - mx1);
        rm0 = mx0; rm1 = mx1;
        float sum0 = 0.0f, sum1 = 0.0f;
        #pragma unroll
        for (int nt = 0; nt < 8; nt++) {
            sacc[nt][0] = __expf(sacc[nt][0] - mx0);
            sacc[nt][1] = __expf(sacc[nt][1] - mx0);
            sacc[nt][2] = __expf(sacc[nt][2] - mx1);
            sacc[nt][3] = __expf(sacc[nt][3] - mx1);
            sum0 += sacc[nt][0] + sacc[nt][1];
            sum1 += sacc[nt][2] + sacc[nt][3];
        }
        sum0 += __shfl_xor_sync(0xffffffff, sum0, 1);
        sum0 += __shfl_xor_sync(0xffffffff, sum0, 2);
        sum1 += __shfl_xor_sync(0xffffffff, sum1, 1);
        sum1 += __shfl_xor_sync(0xffffffff, sum1, 2);
        rl0 = rl0 * sc0 + sum0;
        rl1 = rl1 * sc1 + sum1;
        #pragma unroll
        for (int nt = 0; nt < 16; nt++) {
            oacc[nt][0] *= sc0; oacc[nt][1] *= sc0;
            oacc[nt][2] *= sc1; oacc[nt][3] *= sc1;
        }

        // ---- O += P @ V (fp16 single-term) ----
        #pragma unroll
        for (int j = 0; j < 4; j++) {
            unsigned ph[4];
            ph[0] = packh2(sacc[2 * j][0],     sacc[2 * j][1]);
            ph[1] = packh2(sacc[2 * j][2],     sacc[2 * j][3]);
            ph[2] = packh2(sacc[2 * j + 1][0], sacc[2 * j + 1][1]);
            ph[3] = packh2(sacc[2 * j + 1][2], sacc[2 * j + 1][3]);
            #pragma unroll
            for (int nb = 0; nb < 8; nb++) {
                unsigned vh4[4];
                unsigned offv = ((j * 16 + (lane & 7) + ((lane >> 3) & 1) * 8) * LQ +
                                 nb * 16 + (lane >> 4) * 8) * 2;
                LDSM4T(vh4, vBH + offv);
                MMA16816H(oacc[2 * nb + 0], ph, vh4[0], vh4[1]);
                MMA16816H(oacc[2 * nb + 1], ph, vh4[2], vh4[3]);
            }
        }
    }

    // ---- finalize: divide by l, store fp16 single ----
    float li0 = 1.0f / rl0, li1 = 1.0f / rl1;
    size_t or0 = (size_t)(b * S + row0g) * (H * HD) + h * HD;
    size_t or1 = (size_t)(b * S + row1g) * (H * HD) + h * HD;
    #pragma unroll
    for (int nt = 0; nt < 16; nt++) {
        int col = nt * 8 + 2 * tig;
        *(unsigned*)&g_ah[or0 + col] = packh2(oacc[nt][0] * li0, oacc[nt][1] * li0);
        *(unsigned*)&g_ah[or1 + col] = packh2(oacc[nt][2] * li1, oacc[nt][3] * li1);
    }
}

// =============================== launch ======================================
extern "C" void kernel_launch(void* const* d_in, const int* in_sizes, int n_in,
                              void* d_out, int out_size) {
    const float* x  = (const float*)d_in[0];
    const float* Wq = (const float*)d_in[1];
    const float* bq = (const float*)d_in[2];
    const float* Wk = (const float*)d_in[3];
    const float* bk = (const float*)d_in[4];
    const float* Wv = (const float*)d_in[5];
    const float* bv = (const float*)d_in[6];
    const float* Wo = (const float*)d_in[7];
    const float* bo = (const float*)d_in[8];
    float* out = (float*)d_out;

    __nv_bfloat16 *xh, *xl, *wqh, *wql;
    __half *woh, *ah;
    float *bqkv;
    cudaGetSymbolAddress((void**)&xh, g_xh);
    cudaGetSymbolAddress((void**)&xl, g_xl);
    cudaGetSymbolAddress((void**)&wqh, g_wqh);
    cudaGetSymbolAddress((void**)&wql, g_wql);
    cudaGetSymbolAddress((void**)&woh, g_woh);
    cudaGetSymbolAddress((void**)&ah, g_ah);
    cudaGetSymbolAddress((void**)&bqkv, g_bqkv);

    const int M = B * S;  // 8192

    // ---- pre-split conversions ----
    {
        int n4 = M * D / 4;
        convert_split<<<(n4 + 255) / 256, 256>>>(x, xh, xl, n4);
    }
    {
        int n4 = D * 2048 / 4;
        convert_pack<<<(n4 + 255) / 256, 256>>>(Wq, wqh, wql, 2048, 0, n4);
        n4 = D * 512 / 4;
        convert_pack<<<(n4 + 255) / 256, 256>>>(Wk, wqh, wql, 512, 2048, n4);
        convert_pack<<<(n4 + 255) / 256, 256>>>(Wv, wqh, wql, 512, 2560, n4);
        n4 = D * D / 4;
        convert_h32<<<(n4 + 255) / 256, 256>>>(Wo, woh, n4);
    }
    pack_bias<<<(NQKV + 255) / 256, 256>>>(bq, bk, bv, bqkv);

    size_t gsm = (size_t)3 * ST_EL * sizeof(__nv_bfloat16);  // 113664 B
    cudaFuncSetAttribute(gemm_qkv_fused, cudaFuncAttributeMaxDynamicSharedMemorySize, (int)gsm);
    size_t gsmh = (size_t)3 * STH_EL * sizeof(__half);       // 56832 B
    cudaFuncSetAttribute(gemm_out_h, cudaFuncAttributeMaxDynamicSharedMemorySize, (int)gsmh);

    // ---- fused QKV projection + bias + RoPE + split ----
    gemm_qkv_fused<<<dim3(NQKV / 128, M / 128), 256, gsm>>>(xh, xl, wqh, wql, bqkv);

    // ---- flash attention (128-row q tiles) ----
    size_t smem = (size_t)(2 * 128 + 3 * 64) * LQ * sizeof(__nv_bfloat16);  // 121856 B
    cudaFuncSetAttribute(flash_tc, cudaFuncAttributeMaxDynamicSharedMemorySize, (int)smem);
    flash_tc<<<dim3(S / 128, H, B), 256, smem>>>();

    // ---- output projection (fp16 single-term) ----
    gemm_out_h<<<dim3(D / 128, M / 128), 256, gsmh>>>(
        ah, woh, bo, out, M, D, H * HD);
}

// round 11
// speedup vs baseline: 5.3932x; 1.0541x over previous
#include <cuda_runtime.h>
#include <cuda_bf16.h>
#include <cuda_fp16.h>
#include <math.h>

#define B 4
#define S 2048
#define D 2048
#define H 16
#define G 4
#define HD 128
#define NQKV 3072   // packed q(2048) | k(512) | v(512)

// ------------------------- scratch (device globals, no allocs) --------------
__device__ __nv_bfloat16 g_xh[(size_t)B * S * D];
__device__ __nv_bfloat16 g_xl[(size_t)B * S * D];
__device__ __nv_bfloat16 g_wqh[(size_t)D * NQKV];          // packed Wqkv hi [k][n]
__device__ __nv_bfloat16 g_wql[(size_t)D * NQKV];
__device__ __half        g_woh[(size_t)H * HD * D];        // Wo*32 (fp16 single)
__device__ __half        g_ah[(size_t)B * S * H * HD];     // attn out (fp16 single)
__device__ float         g_bqkv[NQKV];
__device__ float2        g_rope[(size_t)S * 64];           // (cos,sin) per (s, freq)
// pre-split, roped operands for flash
__device__ __nv_bfloat16 g_qsh[(size_t)B * H * S * HD];    // q hi [b][h][s][hd]
__device__ __nv_bfloat16 g_qsl[(size_t)B * H * S * HD];
__device__ __nv_bfloat16 g_ksh[(size_t)B * G * S * HD];    // k hi [b][g][s][hd]
__device__ __nv_bfloat16 g_ksl[(size_t)B * G * S * HD];
__device__ __half        g_vsh[(size_t)B * G * S * HD];    // v (fp16 single)

// ============================ shared PTX helpers =============================
#define LDSM4(R, addr)                                                        \
    asm volatile("ldmatrix.sync.aligned.m8n8.x4.shared.b16 {%0,%1,%2,%3}, [%4];" \
                 : "=r"(R[0]), "=r"(R[1]), "=r"(R[2]), "=r"(R[3]) : "r"(addr))
#define LDSM4T(R, addr)                                                       \
    asm volatile("ldmatrix.sync.aligned.m8n8.x4.trans.shared.b16 {%0,%1,%2,%3}, [%4];" \
                 : "=r"(R[0]), "=r"(R[1]), "=r"(R[2]), "=r"(R[3]) : "r"(addr))
#define MMA16816(d, a, b0v, b1v)                                              \
    asm volatile("mma.sync.aligned.m16n8k16.row.col.f32.bf16.bf16.f32 "       \
                 "{%0,%1,%2,%3},{%4,%5,%6,%7},{%8,%9},{%0,%1,%2,%3};"         \
                 : "+f"(d[0]), "+f"(d[1]), "+f"(d[2]), "+f"(d[3])             \
                 : "r"(a[0]), "r"(a[1]), "r"(a[2]), "r"(a[3]),                \
                   "r"(b0v), "r"(b1v))
#define MMA16816H(d, a, b0v, b1v)                                             \
    asm volatile("mma.sync.aligned.m16n8k16.row.col.f32.f16.f16.f32 "         \
                 "{%0,%1,%2,%3},{%4,%5,%6,%7},{%8,%9},{%0,%1,%2,%3};"         \
                 : "+f"(d[0]), "+f"(d[1]), "+f"(d[2]), "+f"(d[3])             \
                 : "r"(a[0]), "r"(a[1]), "r"(a[2]), "r"(a[3]),                \
                   "r"(b0v), "r"(b1v))
#define CP16(smaddr, gptr)                                                    \
    asm volatile("cp.async.cg.shared.global [%0], [%1], 16;" :: "r"(smaddr), "l"(gptr))
#define CP_COMMIT asm volatile("cp.async.commit_group;")

__device__ __forceinline__ void split2(float x, float y,
                                       unsigned& hi, unsigned& lo) {
    __nv_bfloat16 hx = __float2bfloat16_rn(x);
    __nv_bfloat16 hy = __float2bfloat16_rn(y);
    float rx = x - __bfloat162float(hx);
    float ry = y - __bfloat162float(hy);
    __nv_bfloat16 lx = __float2bfloat16_rn(rx);
    __nv_bfloat16 ly = __float2bfloat16_rn(ry);
    __nv_bfloat162 h2 = __nv_bfloat162(hx, hy);
    __nv_bfloat162 l2 = __nv_bfloat162(lx, ly);
    hi = *(unsigned*)&h2;
    lo = *(unsigned*)&l2;
}

__device__ __forceinline__ unsigned packh2(float x, float y) {
    __half2 h = __floats2half2_rn(x, y);
    return *(unsigned*)&h;
}

// ================= ONE fused conversion / packing / table kernel =============
#define CN0 4194304                 // x split quads (8192*2048/4)
#define CN1 1048576                 // Wq pack quads
#define CN2 262144                  // Wk pack quads
#define CN3 262144                  // Wv pack quads
#define CN4 1048576                 // Wo h32 quads
#define CN5 3072                    // bias elems
#define CN6 131072                  // rope table entries (2048*64)
#define CTOT (CN0 + CN1 + CN2 + CN3 + CN4 + CN5 + CN6)

__global__ void convert_all(const float* __restrict__ x,
                            const float* __restrict__ Wq,
                            const float* __restrict__ Wk,
                            const float* __restrict__ Wv,
                            const float* __restrict__ Wo,
                            const float* __restrict__ bq,
                            const float* __restrict__ bk,
                            const float* __restrict__ bv) {
    long i = (long)blockIdx.x * blockDim.x + threadIdx.x;
    if (i < CN0) {                            // x -> bf16 hi/lo
        float4 v = ((const float4*)x)[i];
        uint2 h, l;
        split2(v.x, v.y, h.x, l.x);
        split2(v.z, v.w, h.y, l.y);
        ((uint2*)g_xh)[i] = h;
        ((uint2*)g_xl)[i] = l;
    } else if (i < CN0 + CN1 + CN2 + CN3) {   // Wq/Wk/Wv -> packed bf16 hi/lo
        long j;
        int srcN, off;
        const float* src;
        if (i < CN0 + CN1)      { j = i - CN0;               srcN = 2048; off = 0;    src = Wq; }
        else if (i < CN0 + CN1 + CN2) { j = i - CN0 - CN1;   srcN = 512;  off = 2048; src = Wk; }
        else                    { j = i - CN0 - CN1 - CN2;   srcN = 512;  off = 2560; src = Wv; }
        int rw = srcN >> 2;
        int r = (int)(j / rw), c = (int)(j % rw) * 4;
        float4 v = *(const float4*)&src[(size_t)r * srcN + c];
        uint2 h, l;
        split2(v.x, v.y, h.x, l.x);
        split2(v.z, v.w, h.y, l.y);
        size_t d = (size_t)r * NQKV + off + c;
        *(uint2*)&g_wqh[d] = h;
        *(uint2*)&g_wql[d] = l;
    } else if (i < CN0 + CN1 + CN2 + CN3 + CN4) {  // Wo*32 -> fp16
        long j = i - (CN0 + CN1 + CN2 + CN3);
        float4 v = ((const float4*)Wo)[j];
        uint2 h;
        h.x = packh2(v.x * 32.0f, v.y * 32.0f);
        h.y = packh2(v.z * 32.0f, v.w * 32.0f);
        ((uint2*)g_woh)[j] = h;
    } else if (i < CN0 + CN1 + CN2 + CN3 + CN4 + CN5) {  // bias pack
        int j = (int)(i - (CN0 + CN1 + CN2 + CN3 + CN4));
        g_bqkv[j] = (j < 2048) ? bq[j] : (j < 2560) ? bk[j - 2048] : bv[j - 2560];
    } else {                                   // rope table
        int j = (int)(i - (CN0 + CN1 + CN2 + CN3 + CN4 + CN5));
        int s = j >> 6, f = j & 63;
        float inv_freq = powf(10000.0f, -(float)f / 64.0f);
        float ang = (float)s * inv_freq;
        g_rope[j] = make_float2(cosf(ang), sinf(ang));
    }
}

// ======================== bf16 3-term GEMM mainloop ==========================
#define LDA 40
#define LDB 136
#define ST_EL 18944   // per-stage smem elements: 2*128*40 + 2*32*136

struct GemmAcc { float a[4][4][4]; };

// 3-stage cp.async pipeline, ONE __syncthreads per 32-K iteration.
__device__ __forceinline__ void gemm_mainloop(
    const __nv_bfloat16* __restrict__ Ahg, const __nv_bfloat16* __restrict__ Alg,
    const __nv_bfloat16* __restrict__ Bhg, const __nv_bfloat16* __restrict__ Blg,
    int K, int N, int row0, int col0, unsigned smBase, GemmAcc& acc) {
    const int tid = threadIdx.x;
    const int lane = tid & 31;
    const int warp = tid >> 5;
    const int wm = (warp >> 2) * 64;
    const int wn = (warp & 3) * 32;
    const int NT = K / 32;

    auto issue = [&](int st, int k0) {
        unsigned sb = smBase + st * (ST_EL * 2);
        #pragma unroll
        for (int j = 0; j < 2; j++) {
            int c = tid + j * 256;
            int r = c >> 2, c8 = (c & 3) * 8;
            unsigned so = (unsigned)(r * LDA + c8) * 2;
            CP16(sb + so, &Ahg[(size_t)(row0 + r) * K + k0 + c8]);
            CP16(sb + 10240 + so, &Alg[(size_t)(row0 + r) * K + k0 + c8]);
        }
        #pragma unroll
        for (int j = 0; j < 2; j++) {
            int c = tid + j * 256;
            int r = c >> 4, c8 = (c & 15) * 8;
            unsigned so = (unsigned)(r * LDB + c8) * 2;
            CP16(sb + 20480 + so, &Bhg[(size_t)(k0 + r) * N + col0 + c8]);
            CP16(sb + 29184 + so, &Blg[(size_t)(k0 + r) * N + col0 + c8]);
        }
    };

    issue(0, 0);
    CP_COMMIT;
    issue(1, 32);
    CP_COMMIT;

    for (int it = 0; it < NT; it++) {
        if (it == NT - 1) {
            asm volatile("cp.async.wait_group 0;");
        } else {
            asm volatile("cp.async.wait_group 1;");
        }
        __syncthreads();
        if (it + 2 < NT) {
            issue((it + 2) % 3, (it + 2) * 32);
            CP_COMMIT;
        }

        unsigned sb = smBase + (it % 3) * (ST_EL * 2);
        const unsigned aBaseH = sb, aBaseL = sb + 10240;
        const unsigned bBaseH = sb + 20480, bBaseL = sb + 29184;

        #pragma unroll
        for (int ks = 0; ks < 2; ks++) {
            unsigned ah[4][4], al[4][4];
            #pragma unroll
            for (int im = 0; im < 4; im++) {
                unsigned off =
                    ((wm + im * 16 + (lane & 15)) * LDA + ks * 16 + (lane >> 4) * 8) * 2;
                LDSM4(ah[im], aBaseH + off);
                LDSM4(al[im], aBaseL + off);
            }
            int krow = ks * 16 + (lane & 7) + ((lane >> 3) & 1) * 8;
            #pragma unroll
            for (int pr = 0; pr < 2; pr++) {
                unsigned bh[4], bl[4];
                unsigned off = (krow * LDB + wn + pr * 16 + (lane >> 4) * 8) * 2;
                LDSM4T(bh, bBaseH + off);
                LDSM4T(bl, bBaseL + off);
                #pragma unroll
                for (int im = 0; im < 4; im++) {
                    MMA16816(acc.a[im][pr * 2 + 0], ah[im], bh[0], bh[1]);
                    MMA16816(acc.a[im][pr * 2 + 0], ah[im], bl[0], bl[1]);
                    MMA16816(acc.a[im][pr * 2 + 0], al[im], bh[0], bh[1]);
                    MMA16816(acc.a[im][pr * 2 + 1], ah[im], bh[2], bh[3]);
                    MMA16816(acc.a[im][pr * 2 + 1], ah[im], bl[2], bl[3]);
                    MMA16816(acc.a[im][pr * 2 + 1], al[im], bh[2], bh[3]);
                }
            }
        }
    }
    __syncthreads();   // mainloop smem dead; safe for epilogue reuse
}

// ============= QKV GEMM with fused bias + RoPE + hi/lo split epilogue ========
#define STF 132   // fp32 smem stride for epilogue tile

__global__ __launch_bounds__(256) void gemm_qkv_fused(
    const __nv_bfloat16* __restrict__ Ahg, const __nv_bfloat16* __restrict__ Alg,
    const __nv_bfloat16* __restrict__ Bhg, const __nv_bfloat16* __restrict__ Blg,
    const float* __restrict__ bias) {
    extern __shared__ __nv_bfloat16 smem[];
    const unsigned smBase = (unsigned)__cvta_generic_to_shared(smem);

    const int tid = threadIdx.x;
    const int lane = tid & 31;
    const int warp = tid >> 5;
    const int wm = (warp >> 2) * 64;
    const int wn = (warp & 3) * 32;
    const int row0 = blockIdx.y * 128;
    const int col0 = blockIdx.x * 128;

    GemmAcc acc = {};
    gemm_mainloop(Ahg, Alg, Bhg, Blg, D, NQKV, row0, col0, smBase, acc);

    // ---- stage fp32 tile (with bias) in smem ----
    float* st = (float*)smem;
    const int qr = lane >> 2, qc = lane & 3;
    #pragma unroll
    for (int im = 0; im < 4; im++) {
        #pragma unroll
        for (int jn = 0; jn < 4; jn++) {
            int rr = wm + im * 16 + qr;
            int cc = wn + jn * 8 + 2 * qc;
            float b0v = bias[col0 + cc], b1v = bias[col0 + cc + 1];
            st[rr * STF + cc]           = acc.a[im][jn][0] + b0v;
            st[rr * STF + cc + 1]       = acc.a[im][jn][1] + b1v;
            st[(rr + 8) * STF + cc]     = acc.a[im][jn][2] + b0v;
            st[(rr + 8) * STF + cc + 1] = acc.a[im][jn][3] + b1v;
        }
    }
    __syncthreads();

    const int tile = col0 >> 7;      // head tile: 0-15 q, 16-19 k, 20-23 v
    const int bb = row0 >> 11;
    const float scale = 0.08838834764831845f;

    if (tile < 20) {   // q or k: rope (table) + split (bf16)
        bool isq = tile < 16;
        int hh = isq ? tile : tile - 16;
        int nh = isq ? H : G;
        __nv_bfloat16* dh = isq ? g_qsh : g_ksh;
        __nv_bfloat16* dl = isq ? g_qsl : g_ksl;
        float sc = isq ? scale : 1.0f;
        #pragma unroll 4
        for (int t = 0; t < 16; t++) {
            int idx = tid + t * 256;
            int r = idx >> 5;
            int i2 = (idx & 31) * 2;
            int s = (row0 + r) & (S - 1);
            float a0 = st[r * STF + i2],      a1 = st[r * STF + i2 + 1];
            float c0 = st[r * STF + i2 + 64], c1 = st[r * STF + i2 + 65];
            float4 tcs = *(const float4*)&g_rope[(size_t)s * 64 + i2];
            float cs0 = tcs.x, sn0 = tcs.y, cs1 = tcs.z, sn1 = tcs.w;
            float o10 = (a0 * cs0 - c0 * sn0) * sc;
            float o11 = (a1 * cs1 - c1 * sn1) * sc;
            float o20 = (c0 * cs0 + a0 * sn0) * sc;
            float o21 = (c1 * cs1 + a1 * sn1) * sc;
            unsigned h1, l1, h2, l2;
            split2(o10, o11, h1, l1);
            split2(o20, o21, h2, l2);
            size_t dst = ((size_t)(bb * nh + hh) * S + s) * HD + i2;
            *(unsigned*)&dh[dst] = h1;
            *(unsigned*)&dl[dst] = l1;
            *(unsigned*)&dh[dst + 64] = h2;
            *(unsigned*)&dl[dst + 64] = l2;
        }
    } else {           // v: single fp16
        int gg = tile - 20;
        #pragma unroll 4
        for (int t = 0; t < 32; t++) {
            int idx = tid + t * 256;
            int r = idx >> 6;
            int i2 = (idx & 63) * 2;
            int s = (row0 + r) & (S - 1);
            float v0 = st[r * STF + i2], v1 = st[r * STF + i2 + 1];
            size_t dst = ((size_t)(bb * G + gg) * S + s) * HD + i2;
            *(unsigned*)&g_vsh[dst] = packh2(v0, v1);
        }
    }
}

// ============ output projection: A fp16 single x W fp16 single ===============
#define STH_EL 9472   // per-stage elements: 128*40 + 32*136

__global__ __launch_bounds__(256) void gemm_out_h(
    const __half* __restrict__ Ag, const __half* __restrict__ Bg,
    const float* __restrict__ bias, float* __restrict__ C,
    int M, int N, int K) {
    extern __shared__ __nv_bfloat16 smemb[];
    __half* smem = (__half*)smemb;
    const unsigned smBase = (unsigned)__cvta_generic_to_shared(smem);

    const int tid = threadIdx.x;
    const int lane = tid & 31;
    const int warp = tid >> 5;
    const int wm = (warp >> 2) * 64;
    const int wn = (warp & 3) * 32;
    const int row0 = blockIdx.y * 128;
    const int col0 = blockIdx.x * 128;
    const int NT = K / 32;

    float acc[4][4][4] = {};

    auto issue = [&](int st, int k0) {
        unsigned sb = smBase + st * (STH_EL * 2);
        #pragma unroll
        for (int j = 0; j < 2; j++) {
            int c = tid + j * 256;
            int r = c >> 2, c8 = (c & 3) * 8;
            unsigned so = (unsigned)(r * LDA + c8) * 2;
            CP16(sb + so, &Ag[(size_t)(row0 + r) * K + k0 + c8]);
        }
        #pragma unroll
        for (int j = 0; j < 2; j++) {
            int c = tid + j * 256;
            int r = c >> 4, c8 = (c & 15) * 8;
            unsigned so = (unsigned)(r * LDB + c8) * 2;
            CP16(sb + 10240 + so, &Bg[(size_t)(k0 + r) * N + col0 + c8]);
        }
    };

    issue(0, 0);
    CP_COMMIT;
    issue(1, 32);
    CP_COMMIT;

    for (int it = 0; it < NT; it++) {
        if (it == NT - 1) {
            asm volatile("cp.async.wait_group 0;");
        } else {
            asm volatile("cp.async.wait_group 1;");
        }
        __syncthreads();
        if (it + 2 < NT) {
            issue((it + 2) % 3, (it + 2) * 32);
            CP_COMMIT;
        }

        unsigned sb = smBase + (it % 3) * (STH_EL * 2);
        const unsigned aBase = sb;
        const unsigned bBase = sb + 10240;

        #pragma unroll
        for (int ks = 0; ks < 2; ks++) {
            unsigned ah[4][4];
            #pragma unroll
            for (int im = 0; im < 4; im++) {
                unsigned off =
                    ((wm + im * 16 + (lane & 15)) * LDA + ks * 16 + (lane >> 4) * 8) * 2;
                LDSM4(ah[im], aBase + off);
            }
            int krow = ks * 16 + (lane & 7) + ((lane >> 3) & 1) * 8;
            #pragma unroll
            for (int pr = 0; pr < 2; pr++) {
                unsigned bh[4];
                unsigned off = (krow * LDB + wn + pr * 16 + (lane >> 4) * 8) * 2;
                LDSM4T(bh, bBase + off);
                #pragma unroll
                for (int im = 0; im < 4; im++) {
                    MMA16816H(acc[im][pr * 2 + 0], ah[im], bh[0], bh[1]);
                    MMA16816H(acc[im][pr * 2 + 1], ah[im], bh[2], bh[3]);
                }
            }
        }
    }

    const float inv32 = 1.0f / 32.0f;
    const int qr = lane >> 2, qc = lane & 3;
    #pragma unroll
    for (int im = 0; im < 4; im++) {
        #pragma unroll
        for (int jn = 0; jn < 4; jn++) {
            int row = row0 + wm + im * 16 + qr;
            int col = col0 + wn + jn * 8 + 2 * qc;
            float b0v = bias[col], b1v = bias[col + 1];
            float2 o0 = make_float2(acc[im][jn][0] * inv32 + b0v,
                                    acc[im][jn][1] * inv32 + b1v);
            float2 o1 = make_float2(acc[im][jn][2] * inv32 + b0v,
                                    acc[im][jn][3] * inv32 + b1v);
            *(float2*)&C[(size_t)row * N + col] = o0;
            *(float2*)&C[(size_t)(row + 8) * N + col] = o1;
        }
    }
}

// ====== Flash attention: 128-row q tiles, QK bf16 3-term, PV fp16 1-term =====
#define LQ 136

__global__ __launch_bounds__(256) void flash_tc() {
    extern __shared__ __nv_bfloat16 smb[];
    __nv_bfloat16* Qh = smb;
    __nv_bfloat16* Ql = Qh + 128 * LQ;
    __nv_bfloat16* Kh = Ql + 128 * LQ;
    __nv_bfloat16* Kl = Kh + 64 * LQ;
    __half*        Vh = (__half*)(Kl + 64 * LQ);

    const int tid  = threadIdx.x;
    const int lane = tid & 31;
    const int warp = tid >> 5;              // 0..7
    const int qtile = gridDim.z - 1 - blockIdx.z;  // z slowest: heavy tiles first
    const int h  = blockIdx.x;
    const int b  = blockIdx.y;
    const int g  = h / (H / G);
    const int q0 = qtile * 128;
    const int wm = warp * 16;

    const unsigned qBH = (unsigned)__cvta_generic_to_shared(Qh);
    const unsigned qBL = (unsigned)__cvta_generic_to_shared(Ql);
    const unsigned kBH = (unsigned)__cvta_generic_to_shared(Kh);
    const unsigned kBL = (unsigned)__cvta_generic_to_shared(Kl);
    const unsigned vBH = (unsigned)__cvta_generic_to_shared(Vh);

    // ---- load Q tile (pre-split, pre-scaled, roped) ----
    #pragma unroll
    for (int it = 0; it < 8; it++) {
        int i4 = tid + it * 256;           // 0..2047
        int r  = i4 >> 4;                  // 0..127
        int c8 = (i4 & 15) * 8;
        size_t gi = ((size_t)(b * H + h) * S + q0 + r) * HD + c8;
        *(uint4*)&Qh[r * LQ + c8] = *(const uint4*)&g_qsh[gi];
        *(uint4*)&Ql[r * LQ + c8] = *(const uint4*)&g_qsl[gi];
    }

    const int gid = lane >> 2, tig = lane & 3;
    const int row0g = q0 + wm + gid;
    const int row1g = row0g + 8;
    const int wmaxrow = q0 + wm + 15;

    float rm0 = -1e30f, rm1 = -1e30f, rl0 = 0.0f, rl1 = 0.0f;
    float oacc[16][4] = {};

    const int NKT = 2 * qtile + 2;
    for (int kt = 0; kt < NKT; kt++) {
        const int k0 = kt * 64;
        __syncthreads();
        // ---- load K,V tiles ----
        #pragma unroll
        for (int it = 0; it < 4; it++) {
            int i4 = tid + it * 256;       // 0..1023
            int r  = i4 >> 4;              // 0..63
            int c8 = (i4 & 15) * 8;
            size_t gi = ((size_t)(b * G + g) * S + k0 + r) * HD + c8;
            unsigned so = r * LQ + c8;
            *(uint4*)&Kh[so] = *(const uint4*)&g_ksh[gi];
            *(uint4*)&Kl[so] = *(const uint4*)&g_ksl[gi];
            *(uint4*)&Vh[so] = *(const uint4*)&g_vsh[gi];
        }
        __syncthreads();

        if (k0 > wmaxrow) continue;        // whole warp above diagonal

        // ---- S = Q @ K^T (bf16 3-term) ----
        float sacc[8][4] = {};
        #pragma unroll
        for (int ks = 0; ks < 8; ks++) {
            unsigned ah[4], al[4];
            unsigned offa = ((wm + (lane & 15)) * LQ + ks * 16 + (lane >> 4) * 8) * 2;
            LDSM4(ah, qBH + offa);
            LDSM4(al, qBL + offa);
            #pragma unroll
            for (int nb = 0; nb < 4; nb++) {
                unsigned kh[4], kl[4];
                unsigned offb = ((nb * 16 + (lane >> 4) * 8 + (lane & 7)) * LQ +
                                 ks * 16 + ((lane >> 3) & 1) * 8) * 2;
                LDSM4(kh, kBH + offb);
                LDSM4(kl, kBL + offb);
                MMA16816(sacc[2 * nb + 0], ah, kh[0], kh[1]);
                MMA16816(sacc[2 * nb + 0], ah, kl[0], kl[1]);
                MMA16816(sacc[2 * nb + 0], al, kh[0], kh[1]);
                MMA16816(sacc[2 * nb + 1], ah, kh[2], kh[3]);
                MMA16816(sacc[2 * nb + 1], ah, kl[2], kl[3]);
                MMA16816(sacc[2 * nb + 1], al, kh[2], kh[3]);
            }
        }

        if (k0 + 63 > row0g) {
            #pragma unroll
            for (int nt = 0; nt < 8; nt++) {
                int colg = k0 + nt * 8 + 2 * tig;
                if (colg > row0g)     sacc[nt][0] = -1e30f;
                if (colg + 1 > row0g) sacc[nt][1] = -1e30f;
                if (colg > row1g)     sacc[nt][2] = -1e30f;
                if (colg + 1 > row1g) sacc[nt][3] = -1e30f;
            }
        }

        // ---- online softmax ----
        float mx0 = rm0, mx1 = rm1;
        #pragma unroll
        for (int nt = 0; nt < 8; nt++) {
            mx0 = fmaxf(mx0, fmaxf(sacc[nt][0], sacc[nt][1]));
            mx1 = fmaxf(mx1, fmaxf(sacc[nt][2], sacc[nt][3]));
        }
        mx0 = fmaxf(mx0, __shfl_xor_sync(0xffffffff, mx0, 1));
        mx0 = fmaxf(mx0, __shfl_xor_sync(0xffffffff, mx0, 2));
        mx1 = fmaxf(mx1, __shfl_xor_sync(0xffffffff, mx1, 1));
        mx1 = fmaxf(mx1, __shfl_xor_sync(0xffffffff, mx1, 2));
        float sc0 = __expf(rm0 - mx0);
        float sc1 = __expf(rm1 - mx1);
        rm0 = mx0; rm1 = mx1;
        float sum0 = 0.0f, sum1 = 0.0f;
        #pragma unroll
        for (int nt = 0; nt < 8; nt++) {
            sacc[nt][0] = __expf(sacc[nt][0] - mx0);
            sacc[nt][1] = __expf(sacc[nt][1] - mx0);
            sacc[nt][2] = __expf(sacc[nt][2] - mx1);
            sacc[nt][3] = __expf(sacc[nt][3] - mx1);
            sum0 += sacc[nt][0] + sacc[nt][1];
            sum1 += sacc[nt][2] + sacc[nt][3];
        }
        sum0 += __shfl_xor_sync(0xffffffff, sum0, 1);
        sum0 += __shfl_xor_sync(0xffffffff, sum0, 2);
        sum1 += __shfl_xor_sync(0xffffffff, sum1, 1);
        sum1 += __shfl_xor_sync(0xffffffff, sum1, 2);
        rl0 = rl0 * sc0 + sum0;
        rl1 = rl1 * sc1 + sum1;
        #pragma unroll
        for (int nt = 0; nt < 16; nt++) {
            oacc[nt][0] *= sc0; oacc[nt][1] *= sc0;
            oacc[nt][2] *= sc1; oacc[nt][3] *= sc1;
        }

        // ---- O += P @ V (fp16 single-term) ----
        #pragma unroll
        for (int j = 0; j < 4; j++) {
            unsigned ph[4];
            ph[0] = packh2(sacc[2 * j][0],     sacc[2 * j][1]);
            ph[1] = packh2(sacc[2 * j][2],     sacc[2 * j][3]);
            ph[2] = packh2(sacc[2 * j + 1][0], sacc[2 * j + 1][1]);
            ph[3] = packh2(sacc[2 * j + 1][2], sacc[2 * j + 1][3]);
            #pragma unroll
            for (int nb = 0; nb < 8; nb++) {
                unsigned vh4[4];
                unsigned offv = ((j * 16 + (lane & 7) + ((lane >> 3) & 1) * 8) * LQ +
                                 nb * 16 + (lane >> 4) * 8) * 2;
                LDSM4T(vh4, vBH + offv);
                MMA16816H(oacc[2 * nb + 0], ph, vh4[0], vh4[1]);
                MMA16816H(oacc[2 * nb + 1], ph, vh4[2], vh4[3]);
            }
        }
    }

    // ---- finalize: divide by l, store fp16 single ----
    float li0 = 1.0f / rl0, li1 = 1.0f / rl1;
    size_t or0 = (size_t)(b * S + row0g) * (H * HD) + h * HD;
    size_t or1 = (size_t)(b * S + row1g) * (H * HD) + h * HD;
    #pragma unroll
    for (int nt = 0; nt < 16; nt++) {
        int col = nt * 8 + 2 * tig;
        *(unsigned*)&g_ah[or0 + col] = packh2(oacc[nt][0] * li0, oacc[nt][1] * li0);
        *(unsigned*)&g_ah[or1 + col] = packh2(oacc[nt][2] * li1, oacc[nt][3] * li1);
    }
}

// =============================== launch ======================================
extern "C" void kernel_launch(void* const* d_in, const int* in_sizes, int n_in,
                              void* d_out, int out_size) {
    const float* x  = (const float*)d_in[0];
    const float* Wq = (const float*)d_in[1];
    const float* bq = (const float*)d_in[2];
    const float* Wk = (const float*)d_in[3];
    const float* bk = (const float*)d_in[4];
    const float* Wv = (const float*)d_in[5];
    const float* bv = (const float*)d_in[6];
    const float* Wo = (const float*)d_in[7];
    const float* bo = (const float*)d_in[8];
    float* out = (float*)d_out;

    __nv_bfloat16 *xh, *xl, *wqh, *wql;
    __half *woh, *ah;
    float *bqkv;
    cudaGetSymbolAddress((void**)&xh, g_xh);
    cudaGetSymbolAddress((void**)&xl, g_xl);
    cudaGetSymbolAddress((void**)&wqh, g_wqh);
    cudaGetSymbolAddress((void**)&wql, g_wql);
    cudaGetSymbolAddress((void**)&woh, g_woh);
    cudaGetSymbolAddress((void**)&ah, g_ah);
    cudaGetSymbolAddress((void**)&bqkv, g_bqkv);

    const int M = B * S;  // 8192

    // ---- one fused conversion / packing / rope-table launch ----
    convert_all<<<(CTOT + 255) / 256, 256>>>(x, Wq, Wk, Wv, Wo, bq, bk, bv);

    size_t gsm = (size_t)3 * ST_EL * sizeof(__nv_bfloat16);  // 113664 B
    cudaFuncSetAttribute(gemm_qkv_fused, cudaFuncAttributeMaxDynamicSharedMemorySize, (int)gsm);
    size_t gsmh = (size_t)3 * STH_EL * sizeof(__half);       // 56832 B
    cudaFuncSetAttribute(gemm_out_h, cudaFuncAttributeMaxDynamicSharedMemorySize, (int)gsmh);

    // ---- fused QKV projection + bias + RoPE + split ----
    gemm_qkv_fused<<<dim3(NQKV / 128, M / 128), 256, gsm>>>(xh, xl, wqh, wql, bqkv);

    // ---- flash attention (128-row q tiles, heavy-first via z) ----
    size_t smem = (size_t)(2 * 128 + 3 * 64) * LQ * sizeof(__nv_bfloat16);  // 121856 B
    cudaFuncSetAttribute(flash_tc, cudaFuncAttributeMaxDynamicSharedMemorySize, (int)smem);
    flash_tc<<<dim3(H, B, S / 128), 256, smem>>>();

    // ---- output projection (fp16 single-term) ----
    gemm_out_h<<<dim3(D / 128, M / 128), 256, gsmh>>>(
        ah, woh, bo, out, M, D, H * HD);
}